// round 1
// baseline (speedup 1.0000x reference)
#include <cuda_runtime.h>

#define S_LEN   2048
#define D_MODEL 4096
#define NQ      32
#define NKV     8
#define HD      128
#define WINDOW  1024

// ---- scratch (device globals; no allocations allowed) ----
__device__ float g_q[S_LEN * NQ * HD];     // 32 MB
__device__ float g_k[S_LEN * NKV * HD];    // 8 MB
__device__ float g_v[S_LEN * NKV * HD];    // 8 MB
__device__ float g_att[S_LEN * NQ * HD];   // 32 MB

// ============================================================================
// SGEMM: C[M,N] = A[M,K] @ B[K,N], row-major. M%128==0, N%128==0, K%16==0.
// 128x128 block tile, 16-deep K slab, 256 threads, 8x8 per-thread micro-tile.
// ============================================================================
__global__ __launch_bounds__(256) void sgemm_kernel(
    const float* __restrict__ A, const float* __restrict__ B,
    float* __restrict__ C, int M, int N, int K)
{
    __shared__ float As[128 * 17];   // [row][kk], stride 17 (conflict-free)
    __shared__ float Bs[16 * 128];   // [kk][col]

    const int tid = threadIdx.x;
    const int tx = tid & 15;         // 0..15 -> column groups
    const int ty = tid >> 4;         // 0..15 -> row groups
    const int m0 = blockIdx.y * 128;
    const int n0 = blockIdx.x * 128;

    float acc[8][8];
#pragma unroll
    for (int i = 0; i < 8; i++)
#pragma unroll
        for (int j = 0; j < 8; j++) acc[i][j] = 0.f;

    for (int kt = 0; kt < K; kt += 16) {
        // load A tile: 128 rows x 16 cols
#pragma unroll
        for (int i = 0; i < 8; i++) {
            int idx = tid + i * 256;
            int row = idx >> 4, kk = idx & 15;
            As[row * 17 + kk] = A[(m0 + row) * K + kt + kk];
        }
        // load B tile: 16 rows x 128 cols
#pragma unroll
        for (int i = 0; i < 8; i++) {
            int idx = tid + i * 256;
            int kk = idx >> 7, col = idx & 127;
            Bs[kk * 128 + col] = B[(kt + kk) * N + n0 + col];
        }
        __syncthreads();

#pragma unroll
        for (int kk = 0; kk < 16; kk++) {
            float a[8], b[8];
#pragma unroll
            for (int i = 0; i < 4; i++) {
                a[i]     = As[(ty * 4 + i) * 17 + kk];
                a[4 + i] = As[(64 + ty * 4 + i) * 17 + kk];
            }
            float4 b0 = *(const float4*)&Bs[kk * 128 + tx * 4];
            float4 b1 = *(const float4*)&Bs[kk * 128 + 64 + tx * 4];
            b[0] = b0.x; b[1] = b0.y; b[2] = b0.z; b[3] = b0.w;
            b[4] = b1.x; b[5] = b1.y; b[6] = b1.z; b[7] = b1.w;
#pragma unroll
            for (int i = 0; i < 8; i++)
#pragma unroll
                for (int j = 0; j < 8; j++)
                    acc[i][j] = fmaf(a[i], b[j], acc[i][j]);
        }
        __syncthreads();
    }

#pragma unroll
    for (int i = 0; i < 4; i++) {
        int row0 = m0 + ty * 4 + i;
        int row1 = row0 + 64;
        float4 v;
        v.x = acc[i][0]; v.y = acc[i][1]; v.z = acc[i][2]; v.w = acc[i][3];
        *(float4*)&C[row0 * N + n0 + tx * 4] = v;
        v.x = acc[i][4]; v.y = acc[i][5]; v.z = acc[i][6]; v.w = acc[i][7];
        *(float4*)&C[row0 * N + n0 + 64 + tx * 4] = v;
        v.x = acc[4+i][0]; v.y = acc[4+i][1]; v.z = acc[4+i][2]; v.w = acc[4+i][3];
        *(float4*)&C[row1 * N + n0 + tx * 4] = v;
        v.x = acc[4+i][4]; v.y = acc[4+i][5]; v.z = acc[4+i][6]; v.w = acc[4+i][7];
        *(float4*)&C[row1 * N + n0 + 64 + tx * 4] = v;
    }
}

// ============================================================================
// RoPE (interleaved even/odd pairs), in-place on [S][nh][128] buffer.
// ============================================================================
__global__ void rope_kernel(float* __restrict__ buf,
                            const float* __restrict__ cosb,
                            const float* __restrict__ sinb, int nh)
{
    int idx = blockIdx.x * blockDim.x + threadIdx.x;
    int total = S_LEN * nh * 64;
    if (idx >= total) return;
    int i = idx & 63;          // pair index within head
    int t = idx >> 6;          // s * nh + h
    int s = t / nh;
    float2 v = *(float2*)&buf[t * 128 + i * 2];
    float c = cosb[s * 64 + i];
    float sn = sinb[s * 64 + i];
    float2 r;
    r.x = v.x * c - v.y * sn;
    r.y = v.x * sn + v.y * c;
    *(float2*)&buf[t * 128 + i * 2] = r;
}

// ============================================================================
// Flash attention, fp32, causal + sliding window (analytic mask).
// BQ=BK=32, 256 threads. grid = (S/32, NQ).
// S-compute mapping: thread -> 2x2 S block. O mapping: 8 threads per q row,
// 16 output dims each.
// ============================================================================
#define BQ  32
#define BK  32
#define KST 132   // KV smem row stride (floats), %4==0, de-conflicted
#define SST 33    // S smem row stride

__global__ __launch_bounds__(256) void attn_kernel()
{
    __shared__ float Qs[BQ * 128];      // 16 KB
    __shared__ float KVs[BK * KST];     // 16.5 KB (K, then reused for V)
    __shared__ float Ss[BQ * SST];      // 4.2 KB

    const int tid = threadIdx.x;
    const int qt = blockIdx.x;
    const int h = blockIdx.y;
    const int kvh = h >> 2;             // N_REP = 4
    const int q0 = qt * BQ;

    // load Q tile (rows q0..q0+31, head h)
#pragma unroll
    for (int i = 0; i < 4; i++) {
        int v = tid + i * 256;          // over 1024 float4s
        int row = v >> 5, c4 = v & 31;
        *(float4*)&Qs[row * 128 + c4 * 4] =
            *(const float4*)&g_q[(q0 + row) * (NQ * HD) + h * HD + c4 * 4];
    }

    const int tx = tid & 15, ty = tid >> 4;   // S block: rows ty*2+i, cols tx*2+j
    const int r = tid >> 3, q8 = tid & 7;     // O: row r, dims d0..d0+15
    const int d0 = q8 * 16;

    float O[16];
#pragma unroll
    for (int d = 0; d < 16; d++) O[d] = 0.f;
    float m_i = -1e30f, l_i = 0.f;

    const int kt_lo = (q0 >= (WINDOW - 1)) ? ((q0 - (WINDOW - 1)) >> 5) : 0;
    const int kt_hi = q0 >> 5;
    const float scale = 0.08838834764831845f;  // 1/sqrt(128)

    __syncthreads();   // Qs ready

    for (int kt = kt_lo; kt <= kt_hi; kt++) {
        const int k0 = kt * BK;
        // load K tile
#pragma unroll
        for (int i = 0; i < 16; i++) {
            int idx = tid + i * 256;
            int row = idx >> 7, col = idx & 127;
            KVs[row * KST + col] = g_k[(k0 + row) * (NKV * HD) + kvh * HD + col];
        }
        __syncthreads();

        // S = Q K^T
        float sacc00 = 0.f, sacc01 = 0.f, sacc10 = 0.f, sacc11 = 0.f;
#pragma unroll 8
        for (int d = 0; d < 128; d += 4) {
            float4 a0 = *(const float4*)&Qs[(ty * 2) * 128 + d];
            float4 a1 = *(const float4*)&Qs[(ty * 2 + 1) * 128 + d];
            float4 b0 = *(const float4*)&KVs[(tx * 2) * KST + d];
            float4 b1 = *(const float4*)&KVs[(tx * 2 + 1) * KST + d];
            sacc00 += a0.x*b0.x + a0.y*b0.y + a0.z*b0.z + a0.w*b0.w;
            sacc01 += a0.x*b1.x + a0.y*b1.y + a0.z*b1.z + a0.w*b1.w;
            sacc10 += a1.x*b0.x + a1.y*b0.y + a1.z*b0.z + a1.w*b0.w;
            sacc11 += a1.x*b1.x + a1.y*b1.y + a1.z*b1.z + a1.w*b1.w;
        }
        {
            float sv[2][2] = {{sacc00, sacc01}, {sacc10, sacc11}};
#pragma unroll
            for (int i = 0; i < 2; i++)
#pragma unroll
                for (int j = 0; j < 2; j++) {
                    int qg = q0 + ty * 2 + i;
                    int kg = k0 + tx * 2 + j;
                    int diff = qg - kg;
                    bool valid = (diff >= 0) && (diff < WINDOW);
                    Ss[(ty * 2 + i) * SST + tx * 2 + j] =
                        valid ? sv[i][j] * scale : -1e30f;
                }
        }
        __syncthreads();   // S complete, K consumed

        // load V tile (overwrites K buffer)
#pragma unroll
        for (int i = 0; i < 16; i++) {
            int idx = tid + i * 256;
            int row = idx >> 7, col = idx & 127;
            KVs[row * KST + col] = g_v[(k0 + row) * (NKV * HD) + kvh * HD + col];
        }

        // online softmax for own row (8 threads/row, 4 cols each)
        float lm = -1e30f;
#pragma unroll
        for (int c = 0; c < 4; c++)
            lm = fmaxf(lm, Ss[r * SST + q8 * 4 + c]);
        lm = fmaxf(lm, __shfl_xor_sync(0xffffffffu, lm, 1));
        lm = fmaxf(lm, __shfl_xor_sync(0xffffffffu, lm, 2));
        lm = fmaxf(lm, __shfl_xor_sync(0xffffffffu, lm, 4));
        float m_new = fmaxf(m_i, lm);
        float alpha = __expf(m_i - m_new);
        float psum = 0.f;
#pragma unroll
        for (int c = 0; c < 4; c++) {
            float s = Ss[r * SST + q8 * 4 + c];
            float p = (s > -1e29f) ? __expf(s - m_new) : 0.f;
            Ss[r * SST + q8 * 4 + c] = p;
            psum += p;
        }
        psum += __shfl_xor_sync(0xffffffffu, psum, 1);
        psum += __shfl_xor_sync(0xffffffffu, psum, 2);
        psum += __shfl_xor_sync(0xffffffffu, psum, 4);
        l_i = l_i * alpha + psum;
        m_i = m_new;
#pragma unroll
        for (int d = 0; d < 16; d++) O[d] *= alpha;
        __syncthreads();   // P complete + V loaded

        // O += P @ V
#pragma unroll 8
        for (int c = 0; c < 32; c++) {
            float p = Ss[r * SST + c];
#pragma unroll
            for (int d4 = 0; d4 < 4; d4++) {
                float4 v = *(const float4*)&KVs[c * KST + d0 + d4 * 4];
                O[d4 * 4 + 0] = fmaf(p, v.x, O[d4 * 4 + 0]);
                O[d4 * 4 + 1] = fmaf(p, v.y, O[d4 * 4 + 1]);
                O[d4 * 4 + 2] = fmaf(p, v.z, O[d4 * 4 + 2]);
                O[d4 * 4 + 3] = fmaf(p, v.w, O[d4 * 4 + 3]);
            }
        }
        __syncthreads();   // before next K overwrite
    }

    float inv = 1.f / l_i;
#pragma unroll
    for (int d4 = 0; d4 < 4; d4++) {
        float4 o;
        o.x = O[d4 * 4 + 0] * inv;
        o.y = O[d4 * 4 + 1] * inv;
        o.z = O[d4 * 4 + 2] * inv;
        o.w = O[d4 * 4 + 3] * inv;
        *(float4*)&g_att[(q0 + r) * (NQ * HD) + h * HD + d0 + d4 * 4] = o;
    }
}

// ============================================================================
extern "C" void kernel_launch(void* const* d_in, const int* in_sizes, int n_in,
                              void* d_out, int out_size)
{
    const float* x   = (const float*)d_in[0];
    const float* fc  = (const float*)d_in[1];
    const float* fs  = (const float*)d_in[2];
    // d_in[3]: mask — unused (causal + sliding window computed analytically)
    const float* w_q = (const float*)d_in[4];
    const float* w_k = (const float*)d_in[5];
    const float* w_v = (const float*)d_in[6];
    const float* w_o = (const float*)d_in[7];
    float* out = (float*)d_out;

    float *gq, *gk, *gv, *ga;
    cudaGetSymbolAddress((void**)&gq, g_q);
    cudaGetSymbolAddress((void**)&gk, g_k);
    cudaGetSymbolAddress((void**)&gv, g_v);
    cudaGetSymbolAddress((void**)&ga, g_att);

    dim3 thr(256);
    // QKV projections
    sgemm_kernel<<<dim3(D_MODEL / 128, S_LEN / 128), thr>>>(x, w_q, gq, S_LEN, NQ * HD, D_MODEL);
    sgemm_kernel<<<dim3((NKV * HD) / 128, S_LEN / 128), thr>>>(x, w_k, gk, S_LEN, NKV * HD, D_MODEL);
    sgemm_kernel<<<dim3((NKV * HD) / 128, S_LEN / 128), thr>>>(x, w_v, gv, S_LEN, NKV * HD, D_MODEL);
    // RoPE
    rope_kernel<<<(S_LEN * NQ * 64 + 255) / 256, 256>>>(gq, fc, fs, NQ);
    rope_kernel<<<(S_LEN * NKV * 64 + 255) / 256, 256>>>(gk, fc, fs, NKV);
    // Attention
    attn_kernel<<<dim3(S_LEN / BQ, NQ), 256>>>();
    // Output projection
    sgemm_kernel<<<dim3(D_MODEL / 128, S_LEN / 128), thr>>>(ga, w_o, out, S_LEN, NQ * HD, D_MODEL);
}

// round 3
// speedup vs baseline: 1.1062x; 1.1062x over previous
#include <cuda_runtime.h>
#include <cuda_bf16.h>

#define S_LEN   2048
#define D_MODEL 4096
#define NQ      32
#define NKV     8
#define HD      128
#define WINDOW  1024

// ---- scratch (device globals; no allocations allowed) ----
__device__ float g_q[S_LEN * NQ * HD];     // 32 MB
__device__ float g_k[S_LEN * NKV * HD];    // 8 MB
__device__ float g_v[S_LEN * NKV * HD];    // 8 MB
__device__ float g_att[S_LEN * NQ * HD];   // 32 MB

// ============================================================================
// GEMM via tensor cores: C[M,N] = A[M,K] @ B[K,N], fp32 in/out.
// Inputs split into bf16 hi+lo; D += Ah*Bh + Ah*Bl + Al*Bh  (error ~2^-16).
// 128x128 block tile, K-slab 32, 256 threads = 8 warps (4m x 2n), warp tile
// 32x64 via mma.sync.m16n8k16. Smem stride 40 bf16 -> conflict-free frags.
// ============================================================================
#define AST 40

#define MMA_BF16(acc, a, b0v, b1v)                                            \
    asm volatile(                                                             \
        "mma.sync.aligned.m16n8k16.row.col.f32.bf16.bf16.f32 "                \
        "{%0,%1,%2,%3},{%4,%5,%6,%7},{%8,%9},{%0,%1,%2,%3};"                  \
        : "+f"(acc[0]), "+f"(acc[1]), "+f"(acc[2]), "+f"(acc[3])              \
        : "r"(a[0]), "r"(a[1]), "r"(a[2]), "r"(a[3]), "r"(b0v), "r"(b1v))

__global__ __launch_bounds__(256) void gemm_tc_kernel(
    const float* __restrict__ A, const float* __restrict__ B,
    float* __restrict__ C, int M, int N, int K)
{
    __shared__ __align__(16) __nv_bfloat16 Ah[128 * AST];
    __shared__ __align__(16) __nv_bfloat16 Al[128 * AST];
    __shared__ __align__(16) __nv_bfloat16 Bh[128 * AST];
    __shared__ __align__(16) __nv_bfloat16 Bl[128 * AST];

    const int tid = threadIdx.x;
    const int lane = tid & 31, w = tid >> 5;
    const int g = lane >> 2, tg = lane & 3;
    const int wm = (w & 3) * 32;        // warp row offset in tile
    const int wn = (w >> 2) * 64;       // warp col offset in tile
    const int m0 = blockIdx.y * 128, n0 = blockIdx.x * 128;

    float acc[2][8][4];
#pragma unroll
    for (int mt = 0; mt < 2; mt++)
#pragma unroll
        for (int nt = 0; nt < 8; nt++)
#pragma unroll
            for (int i = 0; i < 4; i++) acc[mt][nt][i] = 0.f;

    for (int kt = 0; kt < K; kt += 32) {
        // ---- load + convert A tile: 128 rows x 32 k ----
#pragma unroll
        for (int i = 0; i < 4; i++) {
            int idx = tid + i * 256;
            int row = idx >> 3, c4 = (idx & 7) * 4;
            float4 v = *(const float4*)&A[(m0 + row) * K + kt + c4];
            float vv[4] = {v.x, v.y, v.z, v.w};
#pragma unroll
            for (int j = 0; j < 4; j++) {
                __nv_bfloat16 h = __float2bfloat16_rn(vv[j]);
                Ah[row * AST + c4 + j] = h;
                Al[row * AST + c4 + j] =
                    __float2bfloat16_rn(vv[j] - __bfloat162float(h));
            }
        }
        // ---- load + convert B tile: 32 k x 128 cols, stored [n][k] ----
#pragma unroll
        for (int i = 0; i < 4; i++) {
            int idx = tid + i * 256;
            int kk = idx >> 5, n4 = (idx & 31) * 4;
            float4 v = *(const float4*)&B[(kt + kk) * N + n0 + n4];
            float vv[4] = {v.x, v.y, v.z, v.w};
#pragma unroll
            for (int j = 0; j < 4; j++) {
                __nv_bfloat16 h = __float2bfloat16_rn(vv[j]);
                Bh[(n4 + j) * AST + kk] = h;
                Bl[(n4 + j) * AST + kk] =
                    __float2bfloat16_rn(vv[j] - __bfloat162float(h));
            }
        }
        __syncthreads();

#pragma unroll
        for (int ks = 0; ks < 32; ks += 16) {
            unsigned ah[2][4], al[2][4];
#pragma unroll
            for (int mt = 0; mt < 2; mt++) {
                int base = (wm + mt * 16 + g) * AST + ks + 2 * tg;
                ah[mt][0] = *(const unsigned*)&Ah[base];
                ah[mt][1] = *(const unsigned*)&Ah[base + 8 * AST];
                ah[mt][2] = *(const unsigned*)&Ah[base + 8];
                ah[mt][3] = *(const unsigned*)&Ah[base + 8 * AST + 8];
                al[mt][0] = *(const unsigned*)&Al[base];
                al[mt][1] = *(const unsigned*)&Al[base + 8 * AST];
                al[mt][2] = *(const unsigned*)&Al[base + 8];
                al[mt][3] = *(const unsigned*)&Al[base + 8 * AST + 8];
            }
#pragma unroll
            for (int nt = 0; nt < 8; nt++) {
                int bbase = (wn + nt * 8 + g) * AST + ks + 2 * tg;
                unsigned bh0 = *(const unsigned*)&Bh[bbase];
                unsigned bh1 = *(const unsigned*)&Bh[bbase + 8];
                unsigned bl0 = *(const unsigned*)&Bl[bbase];
                unsigned bl1 = *(const unsigned*)&Bl[bbase + 8];
#pragma unroll
                for (int mt = 0; mt < 2; mt++) {
                    MMA_BF16(acc[mt][nt], ah[mt], bh0, bh1);
                    MMA_BF16(acc[mt][nt], al[mt], bh0, bh1);
                    MMA_BF16(acc[mt][nt], ah[mt], bl0, bl1);
                }
            }
        }
        __syncthreads();
    }

    // ---- epilogue ----
#pragma unroll
    for (int mt = 0; mt < 2; mt++) {
#pragma unroll
        for (int nt = 0; nt < 8; nt++) {
            int row = m0 + wm + mt * 16 + g;
            int col = n0 + wn + nt * 8 + tg * 2;
            float2 v0 = {acc[mt][nt][0], acc[mt][nt][1]};
            float2 v1 = {acc[mt][nt][2], acc[mt][nt][3]};
            *(float2*)&C[row * N + col] = v0;
            *(float2*)&C[(row + 8) * N + col] = v1;
        }
    }
}

// ============================================================================
// RoPE (interleaved even/odd pairs), in-place on [S][nh][128] buffer.
// ============================================================================
__global__ void rope_kernel(float* __restrict__ buf,
                            const float* __restrict__ cosb,
                            const float* __restrict__ sinb, int nh)
{
    int idx = blockIdx.x * blockDim.x + threadIdx.x;
    int total = S_LEN * nh * 64;
    if (idx >= total) return;
    int i = idx & 63;
    int t = idx >> 6;
    int s = t / nh;
    float2 v = *(float2*)&buf[t * 128 + i * 2];
    float c = cosb[s * 64 + i];
    float sn = sinb[s * 64 + i];
    float2 r;
    r.x = v.x * c - v.y * sn;
    r.y = v.x * sn + v.y * c;
    *(float2*)&buf[t * 128 + i * 2] = r;
}

// ============================================================================
// Flash attention, fp32, causal + sliding window (analytic mask).
// BQ=BK=32, 256 threads. grid = (S/32, NQ).
// ============================================================================
#define BQ  32
#define BK  32
#define KST 132
#define SST 33

__global__ __launch_bounds__(256) void attn_kernel()
{
    __shared__ float Qs[BQ * 128];
    __shared__ float KVs[BK * KST];
    __shared__ float Ss[BQ * SST];

    const int tid = threadIdx.x;
    const int qt = blockIdx.x;
    const int h = blockIdx.y;
    const int kvh = h >> 2;
    const int q0 = qt * BQ;

#pragma unroll
    for (int i = 0; i < 4; i++) {
        int v = tid + i * 256;
        int row = v >> 5, c4 = v & 31;
        *(float4*)&Qs[row * 128 + c4 * 4] =
            *(const float4*)&g_q[(q0 + row) * (NQ * HD) + h * HD + c4 * 4];
    }

    const int tx = tid & 15, ty = tid >> 4;
    const int r = tid >> 3, q8 = tid & 7;
    const int d0 = q8 * 16;

    float O[16];
#pragma unroll
    for (int d = 0; d < 16; d++) O[d] = 0.f;
    float m_i = -1e30f, l_i = 0.f;

    const int kt_lo = (q0 >= (WINDOW - 1)) ? ((q0 - (WINDOW - 1)) >> 5) : 0;
    const int kt_hi = q0 >> 5;
    const float scale = 0.08838834764831845f;

    __syncthreads();

    for (int kt = kt_lo; kt <= kt_hi; kt++) {
        const int k0 = kt * BK;
#pragma unroll
        for (int i = 0; i < 16; i++) {
            int idx = tid + i * 256;
            int row = idx >> 7, col = idx & 127;
            KVs[row * KST + col] = g_k[(k0 + row) * (NKV * HD) + kvh * HD + col];
        }
        __syncthreads();

        float sacc00 = 0.f, sacc01 = 0.f, sacc10 = 0.f, sacc11 = 0.f;
#pragma unroll 8
        for (int d = 0; d < 128; d += 4) {
            float4 a0 = *(const float4*)&Qs[(ty * 2) * 128 + d];
            float4 a1 = *(const float4*)&Qs[(ty * 2 + 1) * 128 + d];
            float4 b0 = *(const float4*)&KVs[(tx * 2) * KST + d];
            float4 b1 = *(const float4*)&KVs[(tx * 2 + 1) * KST + d];
            sacc00 += a0.x*b0.x + a0.y*b0.y + a0.z*b0.z + a0.w*b0.w;
            sacc01 += a0.x*b1.x + a0.y*b1.y + a0.z*b1.z + a0.w*b1.w;
            sacc10 += a1.x*b0.x + a1.y*b0.y + a1.z*b0.z + a1.w*b0.w;
            sacc11 += a1.x*b1.x + a1.y*b1.y + a1.z*b1.z + a1.w*b1.w;
        }
        {
            float sv[2][2] = {{sacc00, sacc01}, {sacc10, sacc11}};
#pragma unroll
            for (int i = 0; i < 2; i++)
#pragma unroll
                for (int j = 0; j < 2; j++) {
                    int qg = q0 + ty * 2 + i;
                    int kg = k0 + tx * 2 + j;
                    int diff = qg - kg;
                    bool valid = (diff >= 0) && (diff < WINDOW);
                    Ss[(ty * 2 + i) * SST + tx * 2 + j] =
                        valid ? sv[i][j] * scale : -1e30f;
                }
        }
        __syncthreads();

#pragma unroll
        for (int i = 0; i < 16; i++) {
            int idx = tid + i * 256;
            int row = idx >> 7, col = idx & 127;
            KVs[row * KST + col] = g_v[(k0 + row) * (NKV * HD) + kvh * HD + col];
        }

        float lm = -1e30f;
#pragma unroll
        for (int c = 0; c < 4; c++)
            lm = fmaxf(lm, Ss[r * SST + q8 * 4 + c]);
        lm = fmaxf(lm, __shfl_xor_sync(0xffffffffu, lm, 1));
        lm = fmaxf(lm, __shfl_xor_sync(0xffffffffu, lm, 2));
        lm = fmaxf(lm, __shfl_xor_sync(0xffffffffu, lm, 4));
        float m_new = fmaxf(m_i, lm);
        float alpha = __expf(m_i - m_new);
        float psum = 0.f;
#pragma unroll
        for (int c = 0; c < 4; c++) {
            float s = Ss[r * SST + q8 * 4 + c];
            float p = (s > -1e29f) ? __expf(s - m_new) : 0.f;
            Ss[r * SST + q8 * 4 + c] = p;
            psum += p;
        }
        psum += __shfl_xor_sync(0xffffffffu, psum, 1);
        psum += __shfl_xor_sync(0xffffffffu, psum, 2);
        psum += __shfl_xor_sync(0xffffffffu, psum, 4);
        l_i = l_i * alpha + psum;
        m_i = m_new;
#pragma unroll
        for (int d = 0; d < 16; d++) O[d] *= alpha;
        __syncthreads();

#pragma unroll 8
        for (int c = 0; c < 32; c++) {
            float p = Ss[r * SST + c];
#pragma unroll
            for (int d4 = 0; d4 < 4; d4++) {
                float4 v = *(const float4*)&KVs[c * KST + d0 + d4 * 4];
                O[d4 * 4 + 0] = fmaf(p, v.x, O[d4 * 4 + 0]);
                O[d4 * 4 + 1] = fmaf(p, v.y, O[d4 * 4 + 1]);
                O[d4 * 4 + 2] = fmaf(p, v.z, O[d4 * 4 + 2]);
                O[d4 * 4 + 3] = fmaf(p, v.w, O[d4 * 4 + 3]);
            }
        }
        __syncthreads();
    }

    float inv = 1.f / l_i;
#pragma unroll
    for (int d4 = 0; d4 < 4; d4++) {
        float4 o;
        o.x = O[d4 * 4 + 0] * inv;
        o.y = O[d4 * 4 + 1] * inv;
        o.z = O[d4 * 4 + 2] * inv;
        o.w = O[d4 * 4 + 3] * inv;
        *(float4*)&g_att[(q0 + r) * (NQ * HD) + h * HD + d0 + d4 * 4] = o;
    }
}

// ============================================================================
extern "C" void kernel_launch(void* const* d_in, const int* in_sizes, int n_in,
                              void* d_out, int out_size)
{
    const float* x   = (const float*)d_in[0];
    const float* fc  = (const float*)d_in[1];
    const float* fs  = (const float*)d_in[2];
    // d_in[3]: mask — unused (causal + sliding window computed analytically)
    const float* w_q = (const float*)d_in[4];
    const float* w_k = (const float*)d_in[5];
    const float* w_v = (const float*)d_in[6];
    const float* w_o = (const float*)d_in[7];
    float* out = (float*)d_out;

    float *gq, *gk, *gv, *ga;
    cudaGetSymbolAddress((void**)&gq, g_q);
    cudaGetSymbolAddress((void**)&gk, g_k);
    cudaGetSymbolAddress((void**)&gv, g_v);
    cudaGetSymbolAddress((void**)&ga, g_att);

    dim3 thr(256);
    gemm_tc_kernel<<<dim3(D_MODEL / 128, S_LEN / 128), thr>>>(x, w_q, gq, S_LEN, NQ * HD, D_MODEL);
    gemm_tc_kernel<<<dim3((NKV * HD) / 128, S_LEN / 128), thr>>>(x, w_k, gk, S_LEN, NKV * HD, D_MODEL);
    gemm_tc_kernel<<<dim3((NKV * HD) / 128, S_LEN / 128), thr>>>(x, w_v, gv, S_LEN, NKV * HD, D_MODEL);
    rope_kernel<<<(S_LEN * NQ * 64 + 255) / 256, 256>>>(gq, fc, fs, NQ);
    rope_kernel<<<(S_LEN * NKV * 64 + 255) / 256, 256>>>(gk, fc, fs, NKV);
    attn_kernel<<<dim3(S_LEN / BQ, NQ), 256>>>();
    gemm_tc_kernel<<<dim3(D_MODEL / 128, S_LEN / 128), thr>>>(ga, w_o, out, S_LEN, NQ * HD, D_MODEL);
}

// round 5
// speedup vs baseline: 1.5498x; 1.4010x over previous
#include <cuda_runtime.h>
#include <cuda_bf16.h>
#include <cstdint>

#define S_LEN   2048
#define D_MODEL 4096
#define NQ      32
#define NKV     8
#define HD      128
#define WINDOW  1024
#define NQD     (NQ*HD)    // 4096
#define NKVD    (NKV*HD)   // 1024

// ---- fp32 scratch ----
__device__ float g_q[S_LEN * NQD];
__device__ float g_k[S_LEN * NKVD];
__device__ float g_v[S_LEN * NKVD];
__device__ float g_att[S_LEN * NQD];
// ---- bf16 hi/lo operands (pre-converted / pre-transposed) ----
__device__ __nv_bfloat16 g_xh[S_LEN * D_MODEL],  g_xl[S_LEN * D_MODEL];
__device__ __nv_bfloat16 g_ath[S_LEN * NQD],     g_atl[S_LEN * NQD];
__device__ __nv_bfloat16 g_wqh[NQD * D_MODEL],   g_wql[NQD * D_MODEL];    // [N][K]
__device__ __nv_bfloat16 g_wkh[NKVD * D_MODEL],  g_wkl[NKVD * D_MODEL];
__device__ __nv_bfloat16 g_wvh[NKVD * D_MODEL],  g_wvl[NKVD * D_MODEL];
__device__ __nv_bfloat16 g_woh[D_MODEL * NQD],   g_wol[D_MODEL * NQD];

// ============================================================================
// helpers
// ============================================================================
__device__ __forceinline__ unsigned smem_u32(const void* p) {
    unsigned a;
    asm("{ .reg .u64 t; cvta.to.shared.u64 t, %1; cvt.u32.u64 %0, t; }" : "=r"(a) : "l"(p));
    return a;
}
__device__ __forceinline__ void cp_async16(unsigned s, const void* g) {
    asm volatile("cp.async.cg.shared.global [%0], [%1], 16;" :: "r"(s), "l"(g) : "memory");
}
__device__ __forceinline__ void split2(float v, __nv_bfloat16& h, __nv_bfloat16& l) {
    h = __float2bfloat16_rn(v);
    l = __float2bfloat16_rn(v - __bfloat162float(h));
}

#define MMA_BF16(acc, a, b0v, b1v)                                            \
    asm volatile(                                                             \
        "mma.sync.aligned.m16n8k16.row.col.f32.bf16.bf16.f32 "                \
        "{%0,%1,%2,%3},{%4,%5,%6,%7},{%8,%9},{%0,%1,%2,%3};"                  \
        : "+f"(acc[0]), "+f"(acc[1]), "+f"(acc[2]), "+f"(acc[3])              \
        : "r"(a[0]), "r"(a[1]), "r"(a[2]), "r"(a[3]), "r"(b0v), "r"(b1v))

// ============================================================================
// one-time converts: fp32 -> bf16 hi/lo (same layout)
// ============================================================================
__global__ void cvt_hl(const float* __restrict__ in, __nv_bfloat16* __restrict__ ho,
                       __nv_bfloat16* __restrict__ lo, int n) {
    int i = (blockIdx.x * blockDim.x + threadIdx.x) * 4;
    if (i >= n) return;
    float4 v = *(const float4*)&in[i];
    __align__(8) __nv_bfloat16 h[4], l[4];
    split2(v.x, h[0], l[0]);
    split2(v.y, h[1], l[1]);
    split2(v.z, h[2], l[2]);
    split2(v.w, h[3], l[3]);
    *(uint2*)&ho[i] = *(uint2*)h;
    *(uint2*)&lo[i] = *(uint2*)l;
}

// weights: w[K][N] fp32 -> th/tl[N][K] bf16 hi/lo (transpose + split)
__global__ void transpose_hl(const float* __restrict__ w, __nv_bfloat16* __restrict__ th,
                             __nv_bfloat16* __restrict__ tl, int K, int N) {
    __shared__ float t[32][33];
    int n0 = blockIdx.x * 32, k0 = blockIdx.y * 32;
    int tx = threadIdx.x, ty = threadIdx.y;   // 32 x 8
#pragma unroll
    for (int i = 0; i < 32; i += 8)
        t[ty + i][tx] = w[(k0 + ty + i) * N + n0 + tx];
    __syncthreads();
#pragma unroll
    for (int i = 0; i < 32; i += 8) {
        float v = t[tx][ty + i];              // = w[k0+tx][n0+ty+i]
        __nv_bfloat16 h, l;
        split2(v, h, l);
        th[(n0 + ty + i) * K + k0 + tx] = h;
        tl[(n0 + ty + i) * K + k0 + tx] = l;
    }
}

// ============================================================================
// mma.sync GEMM: C[M,N] = A[M,K] @ Bt[N,K]^T, pre-split bf16 hi/lo, fp32 out.
// 128x128 tile, K-slab 32, 256 thr = 8 warps (2m x 4n), warp tile 64x32.
// cp.async double-buffered. Smem rows 80B (stride 40 bf16) -> conflict-free.
// ============================================================================
#define ABYTES 10240                 // one operand array: 128 rows * 80 B
#define STAGEB (4 * ABYTES)          // Ah, Al, Bh, Bl
#define GSMEM  (2 * STAGEB)          // 81920 B

__global__ __launch_bounds__(256, 1) void gemm_mma(
    const __nv_bfloat16* __restrict__ Ah, const __nv_bfloat16* __restrict__ Al,
    const __nv_bfloat16* __restrict__ Bh, const __nv_bfloat16* __restrict__ Bl,
    float* __restrict__ C, int M, int N, int K)
{
    extern __shared__ char smem[];
    const int tid = threadIdx.x, lane = tid & 31, w = tid >> 5;
    const int g = lane >> 2, tg = lane & 3;
    const int wm = (w & 1) * 64, wn = (w >> 1) * 32;
    const int m0 = blockIdx.y * 128, n0 = blockIdx.x * 128;
    const unsigned sbase = smem_u32(smem);

    // slab loader: 128 rows x 32 k per array, 16B chunks, 2 per thread
    auto load_slab = [&](int st, int kt) {
        unsigned s0 = sbase + st * STAGEB;
#pragma unroll
        for (int i = 0; i < 2; i++) {
            int idx = tid + i * 256;
            int row = idx >> 2, c = idx & 3;
            unsigned so = (unsigned)(row * 80 + c * 16);
            long ea = (long)(m0 + row) * K + kt + c * 8;
            long eb = (long)(n0 + row) * K + kt + c * 8;
            cp_async16(s0 + so, Ah + ea);
            cp_async16(s0 + ABYTES + so, Al + ea);
            cp_async16(s0 + 2 * ABYTES + so, Bh + eb);
            cp_async16(s0 + 3 * ABYTES + so, Bl + eb);
        }
        asm volatile("cp.async.commit_group;" ::: "memory");
    };

    float acc[4][4][4];
#pragma unroll
    for (int mt = 0; mt < 4; mt++)
#pragma unroll
        for (int nt = 0; nt < 4; nt++)
#pragma unroll
            for (int i = 0; i < 4; i++) acc[mt][nt][i] = 0.f;

    const int T = K >> 5;
    load_slab(0, 0);
    load_slab(1, 32);

    for (int it = 0; it < T; it++) {
        asm volatile("cp.async.wait_group 1;" ::: "memory");
        __syncthreads();
        const char* sb = smem + (it & 1) * STAGEB;
        const char* pAh = sb;
        const char* pAl = sb + ABYTES;
        const char* pBh = sb + 2 * ABYTES;
        const char* pBl = sb + 3 * ABYTES;

#pragma unroll
        for (int ks = 0; ks < 32; ks += 16) {
            unsigned ah[4][4], al[4][4];
            const int ko = (ks + 2 * tg) * 2;
#pragma unroll
            for (int mt = 0; mt < 4; mt++) {
                int o = (wm + mt * 16 + g) * 80 + ko;
                ah[mt][0] = *(const unsigned*)(pAh + o);
                ah[mt][1] = *(const unsigned*)(pAh + o + 8 * 80);
                ah[mt][2] = *(const unsigned*)(pAh + o + 16);
                ah[mt][3] = *(const unsigned*)(pAh + o + 8 * 80 + 16);
                al[mt][0] = *(const unsigned*)(pAl + o);
                al[mt][1] = *(const unsigned*)(pAl + o + 8 * 80);
                al[mt][2] = *(const unsigned*)(pAl + o + 16);
                al[mt][3] = *(const unsigned*)(pAl + o + 8 * 80 + 16);
            }
#pragma unroll
            for (int nt = 0; nt < 4; nt++) {
                int bo = (wn + nt * 8 + g) * 80 + ko;
                unsigned bh0 = *(const unsigned*)(pBh + bo);
                unsigned bh1 = *(const unsigned*)(pBh + bo + 16);
                unsigned bl0 = *(const unsigned*)(pBl + bo);
                unsigned bl1 = *(const unsigned*)(pBl + bo + 16);
#pragma unroll
                for (int mt = 0; mt < 4; mt++) {
                    MMA_BF16(acc[mt][nt], ah[mt], bh0, bh1);
                    MMA_BF16(acc[mt][nt], al[mt], bh0, bh1);
                    MMA_BF16(acc[mt][nt], ah[mt], bl0, bl1);
                }
            }
        }
        __syncthreads();
        if (it + 2 < T) load_slab(it & 1, (it + 2) * 32);
    }

    // epilogue: direct float2 stores
#pragma unroll
    for (int mt = 0; mt < 4; mt++)
#pragma unroll
        for (int nt = 0; nt < 4; nt++) {
            int row = m0 + wm + mt * 16 + g;
            int col = n0 + wn + nt * 8 + tg * 2;
            float2 v0 = {acc[mt][nt][0], acc[mt][nt][1]};
            float2 v1 = {acc[mt][nt][2], acc[mt][nt][3]};
            *(float2*)&C[(long)row * N + col] = v0;
            *(float2*)&C[(long)(row + 8) * N + col] = v1;
        }
}

// ============================================================================
// RoPE
// ============================================================================
__global__ void rope_kernel(float* __restrict__ buf, const float* __restrict__ cosb,
                            const float* __restrict__ sinb, int nh)
{
    int idx = blockIdx.x * blockDim.x + threadIdx.x;
    int total = S_LEN * nh * 64;
    if (idx >= total) return;
    int i = idx & 63;
    int t = idx >> 6;
    int s = t / nh;
    float2 v = *(float2*)&buf[t * 128 + i * 2];
    float c = cosb[s * 64 + i];
    float sn = sinb[s * 64 + i];
    float2 r;
    r.x = v.x * c - v.y * sn;
    r.y = v.x * sn + v.y * c;
    *(float2*)&buf[t * 128 + i * 2] = r;
}

// ============================================================================
// Flash attention fp32 (unchanged)
// ============================================================================
#define BQ  32
#define BK  32
#define KST 132
#define SST 33

__global__ __launch_bounds__(256) void attn_kernel()
{
    __shared__ float Qs[BQ * 128];
    __shared__ float KVs[BK * KST];
    __shared__ float Ss[BQ * SST];

    const int tid = threadIdx.x;
    const int qt = blockIdx.x;
    const int h = blockIdx.y;
    const int kvh = h >> 2;
    const int q0 = qt * BQ;

#pragma unroll
    for (int i = 0; i < 4; i++) {
        int v = tid + i * 256;
        int row = v >> 5, c4 = v & 31;
        *(float4*)&Qs[row * 128 + c4 * 4] =
            *(const float4*)&g_q[(q0 + row) * NQD + h * HD + c4 * 4];
    }

    const int tx = tid & 15, ty = tid >> 4;
    const int r = tid >> 3, q8 = tid & 7;
    const int d0 = q8 * 16;

    float O[16];
#pragma unroll
    for (int d = 0; d < 16; d++) O[d] = 0.f;
    float m_i = -1e30f, l_i = 0.f;

    const int kt_lo = (q0 >= (WINDOW - 1)) ? ((q0 - (WINDOW - 1)) >> 5) : 0;
    const int kt_hi = q0 >> 5;
    const float scale = 0.08838834764831845f;

    __syncthreads();

    for (int kt = kt_lo; kt <= kt_hi; kt++) {
        const int k0 = kt * BK;
#pragma unroll
        for (int i = 0; i < 16; i++) {
            int idx = tid + i * 256;
            int row = idx >> 7, col = idx & 127;
            KVs[row * KST + col] = g_k[(k0 + row) * NKVD + kvh * HD + col];
        }
        __syncthreads();

        float sacc00 = 0.f, sacc01 = 0.f, sacc10 = 0.f, sacc11 = 0.f;
#pragma unroll 8
        for (int d = 0; d < 128; d += 4) {
            float4 a0 = *(const float4*)&Qs[(ty * 2) * 128 + d];
            float4 a1 = *(const float4*)&Qs[(ty * 2 + 1) * 128 + d];
            float4 b0 = *(const float4*)&KVs[(tx * 2) * KST + d];
            float4 b1 = *(const float4*)&KVs[(tx * 2 + 1) * KST + d];
            sacc00 += a0.x*b0.x + a0.y*b0.y + a0.z*b0.z + a0.w*b0.w;
            sacc01 += a0.x*b1.x + a0.y*b1.y + a0.z*b1.z + a0.w*b1.w;
            sacc10 += a1.x*b0.x + a1.y*b0.y + a1.z*b0.z + a1.w*b0.w;
            sacc11 += a1.x*b1.x + a1.y*b1.y + a1.z*b1.z + a1.w*b1.w;
        }
        {
            float sv[2][2] = {{sacc00, sacc01}, {sacc10, sacc11}};
#pragma unroll
            for (int i = 0; i < 2; i++)
#pragma unroll
                for (int j = 0; j < 2; j++) {
                    int qg = q0 + ty * 2 + i;
                    int kg = k0 + tx * 2 + j;
                    int diff = qg - kg;
                    bool valid = (diff >= 0) && (diff < WINDOW);
                    Ss[(ty * 2 + i) * SST + tx * 2 + j] =
                        valid ? sv[i][j] * scale : -1e30f;
                }
        }
        __syncthreads();

#pragma unroll
        for (int i = 0; i < 16; i++) {
            int idx = tid + i * 256;
            int row = idx >> 7, col = idx & 127;
            KVs[row * KST + col] = g_v[(k0 + row) * NKVD + kvh * HD + col];
        }

        float lm = -1e30f;
#pragma unroll
        for (int c = 0; c < 4; c++)
            lm = fmaxf(lm, Ss[r * SST + q8 * 4 + c]);
        lm = fmaxf(lm, __shfl_xor_sync(0xffffffffu, lm, 1));
        lm = fmaxf(lm, __shfl_xor_sync(0xffffffffu, lm, 2));
        lm = fmaxf(lm, __shfl_xor_sync(0xffffffffu, lm, 4));
        float m_new = fmaxf(m_i, lm);
        float alpha = __expf(m_i - m_new);
        float psum = 0.f;
#pragma unroll
        for (int c = 0; c < 4; c++) {
            float s = Ss[r * SST + q8 * 4 + c];
            float p = (s > -1e29f) ? __expf(s - m_new) : 0.f;
            Ss[r * SST + q8 * 4 + c] = p;
            psum += p;
        }
        psum += __shfl_xor_sync(0xffffffffu, psum, 1);
        psum += __shfl_xor_sync(0xffffffffu, psum, 2);
        psum += __shfl_xor_sync(0xffffffffu, psum, 4);
        l_i = l_i * alpha + psum;
        m_i = m_new;
#pragma unroll
        for (int d = 0; d < 16; d++) O[d] *= alpha;
        __syncthreads();

#pragma unroll 8
        for (int c = 0; c < 32; c++) {
            float p = Ss[r * SST + c];
#pragma unroll
            for (int d4 = 0; d4 < 4; d4++) {
                float4 v = *(const float4*)&KVs[c * KST + d0 + d4 * 4];
                O[d4 * 4 + 0] = fmaf(p, v.x, O[d4 * 4 + 0]);
                O[d4 * 4 + 1] = fmaf(p, v.y, O[d4 * 4 + 1]);
                O[d4 * 4 + 2] = fmaf(p, v.z, O[d4 * 4 + 2]);
                O[d4 * 4 + 3] = fmaf(p, v.w, O[d4 * 4 + 3]);
            }
        }
        __syncthreads();
    }

    float inv = 1.f / l_i;
#pragma unroll
    for (int d4 = 0; d4 < 4; d4++) {
        float4 o;
        o.x = O[d4 * 4 + 0] * inv;
        o.y = O[d4 * 4 + 1] * inv;
        o.z = O[d4 * 4 + 2] * inv;
        o.w = O[d4 * 4 + 3] * inv;
        *(float4*)&g_att[(q0 + r) * NQD + h * HD + d0 + d4 * 4] = o;
    }
}

// ============================================================================
extern "C" void kernel_launch(void* const* d_in, const int* in_sizes, int n_in,
                              void* d_out, int out_size)
{
    const float* x   = (const float*)d_in[0];
    const float* fc  = (const float*)d_in[1];
    const float* fs  = (const float*)d_in[2];
    // d_in[3]: mask — unused (causal + sliding window computed analytically)
    const float* w_q = (const float*)d_in[4];
    const float* w_k = (const float*)d_in[5];
    const float* w_v = (const float*)d_in[6];
    const float* w_o = (const float*)d_in[7];
    float* out = (float*)d_out;

    float *gq, *gk, *gv, *ga;
    cudaGetSymbolAddress((void**)&gq, g_q);
    cudaGetSymbolAddress((void**)&gk, g_k);
    cudaGetSymbolAddress((void**)&gv, g_v);
    cudaGetSymbolAddress((void**)&ga, g_att);
    __nv_bfloat16 *xh, *xl, *ath, *atl, *wqh, *wql, *wkh, *wkl, *wvh, *wvl, *woh, *wol;
    cudaGetSymbolAddress((void**)&xh, g_xh);   cudaGetSymbolAddress((void**)&xl, g_xl);
    cudaGetSymbolAddress((void**)&ath, g_ath); cudaGetSymbolAddress((void**)&atl, g_atl);
    cudaGetSymbolAddress((void**)&wqh, g_wqh); cudaGetSymbolAddress((void**)&wql, g_wql);
    cudaGetSymbolAddress((void**)&wkh, g_wkh); cudaGetSymbolAddress((void**)&wkl, g_wkl);
    cudaGetSymbolAddress((void**)&wvh, g_wvh); cudaGetSymbolAddress((void**)&wvl, g_wvl);
    cudaGetSymbolAddress((void**)&woh, g_woh); cudaGetSymbolAddress((void**)&wol, g_wol);

    cudaFuncSetAttribute(gemm_mma, cudaFuncAttributeMaxDynamicSharedMemorySize, GSMEM);

    // one-time operand prep
    cvt_hl<<<(S_LEN * D_MODEL / 4 + 255) / 256, 256>>>(x, xh, xl, S_LEN * D_MODEL);
    transpose_hl<<<dim3(NQD / 32, D_MODEL / 32), dim3(32, 8)>>>(w_q, wqh, wql, D_MODEL, NQD);
    transpose_hl<<<dim3(NKVD / 32, D_MODEL / 32), dim3(32, 8)>>>(w_k, wkh, wkl, D_MODEL, NKVD);
    transpose_hl<<<dim3(NKVD / 32, D_MODEL / 32), dim3(32, 8)>>>(w_v, wvh, wvl, D_MODEL, NKVD);
    transpose_hl<<<dim3(D_MODEL / 32, NQD / 32), dim3(32, 8)>>>(w_o, woh, wol, NQD, D_MODEL);

    // QKV projections
    gemm_mma<<<dim3(NQD / 128, S_LEN / 128), 256, GSMEM>>>(xh, xl, wqh, wql, gq, S_LEN, NQD, D_MODEL);
    gemm_mma<<<dim3(NKVD / 128, S_LEN / 128), 256, GSMEM>>>(xh, xl, wkh, wkl, gk, S_LEN, NKVD, D_MODEL);
    gemm_mma<<<dim3(NKVD / 128, S_LEN / 128), 256, GSMEM>>>(xh, xl, wvh, wvl, gv, S_LEN, NKVD, D_MODEL);

    rope_kernel<<<(S_LEN * NQ * 64 + 255) / 256, 256>>>(gq, fc, fs, NQ);
    rope_kernel<<<(S_LEN * NKV * 64 + 255) / 256, 256>>>(gk, fc, fs, NKV);

    attn_kernel<<<dim3(S_LEN / BQ, NQ), 256>>>();

    // output projection
    cvt_hl<<<(S_LEN * NQD / 4 + 255) / 256, 256>>>(ga, ath, atl, S_LEN * NQD);
    gemm_mma<<<dim3(D_MODEL / 128, S_LEN / 128), 256, GSMEM>>>(ath, atl, woh, wol, out, S_LEN, D_MODEL, NQD);
}

// round 6
// speedup vs baseline: 4.2895x; 2.7678x over previous
#include <cuda_runtime.h>
#include <cuda_bf16.h>
#include <cstdint>

#define S_LEN   2048
#define D_MODEL 4096
#define NQ      32
#define NKV     8
#define HD      128
#define WINDOW  1024
#define NQD     (NQ*HD)    // 4096
#define NKVD    (NKV*HD)   // 1024

// ---- fp32 scratch ----
__device__ float g_q[S_LEN * NQD];
__device__ float g_k[S_LEN * NKVD];
__device__ float g_v[S_LEN * NKVD];
// ---- bf16 hi/lo operands ----
__device__ __nv_bfloat16 g_xh[S_LEN * D_MODEL],  g_xl[S_LEN * D_MODEL];
__device__ __nv_bfloat16 g_ath[S_LEN * NQD],     g_atl[S_LEN * NQD];   // attn out
__device__ __nv_bfloat16 g_qh[S_LEN * NQD],      g_ql[S_LEN * NQD];
__device__ __nv_bfloat16 g_kh[S_LEN * NKVD],     g_kl[S_LEN * NKVD];
__device__ __nv_bfloat16 g_vth[NKVD * S_LEN],    g_vtl[NKVD * S_LEN];  // [kvh][hd][seq]
__device__ __nv_bfloat16 g_wqh[NQD * D_MODEL],   g_wql[NQD * D_MODEL]; // [N][K]
__device__ __nv_bfloat16 g_wkh[NKVD * D_MODEL],  g_wkl[NKVD * D_MODEL];
__device__ __nv_bfloat16 g_wvh[NKVD * D_MODEL],  g_wvl[NKVD * D_MODEL];
__device__ __nv_bfloat16 g_woh[D_MODEL * NQD],   g_wol[D_MODEL * NQD];

// ============================================================================
// helpers
// ============================================================================
__device__ __forceinline__ unsigned smem_u32(const void* p) {
    unsigned a;
    asm("{ .reg .u64 t; cvta.to.shared.u64 t, %1; cvt.u32.u64 %0, t; }" : "=r"(a) : "l"(p));
    return a;
}
__device__ __forceinline__ void cp_async16(unsigned s, const void* g) {
    asm volatile("cp.async.cg.shared.global [%0], [%1], 16;" :: "r"(s), "l"(g) : "memory");
}
__device__ __forceinline__ void split2(float v, __nv_bfloat16& h, __nv_bfloat16& l) {
    h = __float2bfloat16_rn(v);
    l = __float2bfloat16_rn(v - __bfloat162float(h));
}

#define MMA_BF16(acc, a, b0v, b1v)                                            \
    asm volatile(                                                             \
        "mma.sync.aligned.m16n8k16.row.col.f32.bf16.bf16.f32 "                \
        "{%0,%1,%2,%3},{%4,%5,%6,%7},{%8,%9},{%0,%1,%2,%3};"                  \
        : "+f"(acc[0]), "+f"(acc[1]), "+f"(acc[2]), "+f"(acc[3])              \
        : "r"(a[0]), "r"(a[1]), "r"(a[2]), "r"(a[3]), "r"(b0v), "r"(b1v))

#define LDSM4(r, addr)                                                        \
    asm volatile("ldmatrix.sync.aligned.m8n8.x4.shared.b16 {%0,%1,%2,%3}, [%4];" \
        : "=r"((r)[0]), "=r"((r)[1]), "=r"((r)[2]), "=r"((r)[3]) : "r"(addr))

// ============================================================================
// one-time converts
// ============================================================================
__global__ void cvt_hl(const float* __restrict__ in, __nv_bfloat16* __restrict__ ho,
                       __nv_bfloat16* __restrict__ lo, int n) {
    int i = (blockIdx.x * blockDim.x + threadIdx.x) * 4;
    if (i >= n) return;
    float4 v = *(const float4*)&in[i];
    __align__(8) __nv_bfloat16 h[4], l[4];
    split2(v.x, h[0], l[0]);
    split2(v.y, h[1], l[1]);
    split2(v.z, h[2], l[2]);
    split2(v.w, h[3], l[3]);
    *(uint2*)&ho[i] = *(uint2*)h;
    *(uint2*)&lo[i] = *(uint2*)l;
}

// weights: w[K][N] fp32 -> th/tl[N][K] bf16 (transpose + split)
__global__ void transpose_hl(const float* __restrict__ w, __nv_bfloat16* __restrict__ th,
                             __nv_bfloat16* __restrict__ tl, int K, int N) {
    __shared__ float t[32][33];
    int n0 = blockIdx.x * 32, k0 = blockIdx.y * 32;
    int tx = threadIdx.x, ty = threadIdx.y;   // 32 x 8
#pragma unroll
    for (int i = 0; i < 32; i += 8)
        t[ty + i][tx] = w[(k0 + ty + i) * N + n0 + tx];
    __syncthreads();
#pragma unroll
    for (int i = 0; i < 32; i += 8) {
        float v = t[tx][ty + i];
        __nv_bfloat16 h, l;
        split2(v, h, l);
        th[(n0 + ty + i) * K + k0 + tx] = h;
        tl[(n0 + ty + i) * K + k0 + tx] = l;
    }
}

// V: g_v [seq][kvh*128] fp32 -> vth/vtl [kvh][hd][seq] bf16
__global__ void vtrans_hl(const float* __restrict__ v, __nv_bfloat16* __restrict__ th,
                          __nv_bfloat16* __restrict__ tl) {
    __shared__ float t[32][33];
    int s0 = blockIdx.x * 32, h0 = blockIdx.y * 32, kvh = blockIdx.z;
    int tx = threadIdx.x, ty = threadIdx.y;
#pragma unroll
    for (int i = 0; i < 32; i += 8)
        t[ty + i][tx] = v[(s0 + ty + i) * NKVD + kvh * HD + h0 + tx];
    __syncthreads();
#pragma unroll
    for (int i = 0; i < 32; i += 8) {
        float val = t[tx][ty + i];
        __nv_bfloat16 h, l;
        split2(val, h, l);
        long o = (long)(kvh * HD + h0 + ty + i) * S_LEN + s0 + tx;
        th[o] = h;
        tl[o] = l;
    }
}

// ============================================================================
// mma.sync GEMM (pass-major ILP + ldmatrix): C = A[M,K] @ Bt[N,K]^T
// 128x128 tile, K-slab 32, 256 thr = 8 warps (2m x 4n), warp 64x32.
// ============================================================================
#define ABYTES 10240
#define STAGEB (4 * ABYTES)
#define GSMEM  (2 * STAGEB)

__global__ __launch_bounds__(256, 1) void gemm_mma(
    const __nv_bfloat16* __restrict__ Ah, const __nv_bfloat16* __restrict__ Al,
    const __nv_bfloat16* __restrict__ Bh, const __nv_bfloat16* __restrict__ Bl,
    float* __restrict__ C, int M, int N, int K)
{
    extern __shared__ char smem[];
    const int tid = threadIdx.x, lane = tid & 31, w = tid >> 5;
    const int g = lane >> 2, tg = lane & 3;
    const int t8 = lane >> 3, r8 = lane & 7;
    const int wm = (w & 1) * 64, wn = (w >> 1) * 32;
    const int m0 = blockIdx.y * 128, n0 = blockIdx.x * 128;
    const unsigned sbase = smem_u32(smem);

    auto load_slab = [&](int st, int kt) {
        unsigned s0 = sbase + st * STAGEB;
#pragma unroll
        for (int i = 0; i < 2; i++) {
            int idx = tid + i * 256;
            int row = idx >> 2, c = idx & 3;
            unsigned so = (unsigned)(row * 80 + c * 16);
            long ea = (long)(m0 + row) * K + kt + c * 8;
            long eb = (long)(n0 + row) * K + kt + c * 8;
            cp_async16(s0 + so, Ah + ea);
            cp_async16(s0 + ABYTES + so, Al + ea);
            cp_async16(s0 + 2 * ABYTES + so, Bh + eb);
            cp_async16(s0 + 3 * ABYTES + so, Bl + eb);
        }
        asm volatile("cp.async.commit_group;" ::: "memory");
    };

    float acc[4][4][4];
#pragma unroll
    for (int mt = 0; mt < 4; mt++)
#pragma unroll
        for (int nt = 0; nt < 4; nt++)
#pragma unroll
            for (int i = 0; i < 4; i++) acc[mt][nt][i] = 0.f;

    // ldmatrix per-lane base offsets (bytes)
    const unsigned aoff = (unsigned)((wm + (t8 & 1) * 8 + r8) * 80 + (t8 >> 1) * 16);
    const unsigned boff = (unsigned)((wn + (t8 >> 1) * 8 + r8) * 80 + (t8 & 1) * 16);

    const int T = K >> 5;
    load_slab(0, 0);
    load_slab(1, 32);

    for (int it = 0; it < T; it++) {
        asm volatile("cp.async.wait_group 1;" ::: "memory");
        __syncthreads();
        unsigned sb = sbase + (it & 1) * STAGEB;
        unsigned sAh = sb, sAl = sb + ABYTES, sBh = sb + 2 * ABYTES, sBl = sb + 3 * ABYTES;

#pragma unroll
        for (int ks = 0; ks < 2; ks++) {       // k16 halves; byte offset ks*32
            unsigned a_h[4][4], a_l[4][4], b_h[2][4], b_l[2][4];
#pragma unroll
            for (int mt = 0; mt < 4; mt++) {
                LDSM4(a_h[mt], sAh + aoff + mt * 1280 + ks * 32);
                LDSM4(a_l[mt], sAl + aoff + mt * 1280 + ks * 32);
            }
#pragma unroll
            for (int ntp = 0; ntp < 2; ntp++) {
                LDSM4(b_h[ntp], sBh + boff + ntp * 1280 + ks * 32);
                LDSM4(b_l[ntp], sBl + boff + ntp * 1280 + ks * 32);
            }
            // pass-major: 16 independent accumulators between reuses
#pragma unroll
            for (int mt = 0; mt < 4; mt++)
#pragma unroll
                for (int nt = 0; nt < 4; nt++)
                    MMA_BF16(acc[mt][nt], a_h[mt], b_h[nt >> 1][(nt & 1) * 2], b_h[nt >> 1][(nt & 1) * 2 + 1]);
#pragma unroll
            for (int mt = 0; mt < 4; mt++)
#pragma unroll
                for (int nt = 0; nt < 4; nt++)
                    MMA_BF16(acc[mt][nt], a_l[mt], b_h[nt >> 1][(nt & 1) * 2], b_h[nt >> 1][(nt & 1) * 2 + 1]);
#pragma unroll
            for (int mt = 0; mt < 4; mt++)
#pragma unroll
                for (int nt = 0; nt < 4; nt++)
                    MMA_BF16(acc[mt][nt], a_h[mt], b_l[nt >> 1][(nt & 1) * 2], b_l[nt >> 1][(nt & 1) * 2 + 1]);
        }
        __syncthreads();
        if (it + 2 < T) load_slab(it & 1, (it + 2) * 32);
    }

#pragma unroll
    for (int mt = 0; mt < 4; mt++)
#pragma unroll
        for (int nt = 0; nt < 4; nt++) {
            int row = m0 + wm + mt * 16 + g;
            int col = n0 + wn + nt * 8 + tg * 2;
            float2 v0 = {acc[mt][nt][0], acc[mt][nt][1]};
            float2 v1 = {acc[mt][nt][2], acc[mt][nt][3]};
            *(float2*)&C[(long)row * N + col] = v0;
            *(float2*)&C[(long)(row + 8) * N + col] = v1;
        }
}

// ============================================================================
// RoPE
// ============================================================================
__global__ void rope_kernel(float* __restrict__ buf, const float* __restrict__ cosb,
                            const float* __restrict__ sinb, int nh)
{
    int idx = blockIdx.x * blockDim.x + threadIdx.x;
    int total = S_LEN * nh * 64;
    if (idx >= total) return;
    int i = idx & 63;
    int t = idx >> 6;
    int s = t / nh;
    float2 v = *(float2*)&buf[t * 128 + i * 2];
    float c = cosb[s * 64 + i];
    float sn = sinb[s * 64 + i];
    float2 r;
    r.x = v.x * c - v.y * sn;
    r.y = v.x * sn + v.y * c;
    *(float2*)&buf[t * 128 + i * 2] = r;
}

// ============================================================================
// mma.sync flash attention: BQ=BK=64, 128 thr (4 warps, warp = 16 q-rows).
// Q/K hi/lo in smem [row][136]; Vt hi/lo in smem [hd][72]. 3-pass bf16.
// Writes output directly as bf16 hi/lo (g_ath/g_atl).
// ============================================================================
#define AQ_STB 272                // Q/K smem row stride bytes (136 bf16)
#define AV_STB 144                // Vt smem row stride bytes (72 bf16)
#define SQ_OFF 0
#define SQL_OFF (64 * AQ_STB)     // 17408
#define SK_OFF  (2 * 64 * AQ_STB) // 34816
#define SKL_OFF (3 * 64 * AQ_STB) // 52224
#define SV_OFF  (4 * 64 * AQ_STB) // 69632
#define SVL_OFF (SV_OFF + 128 * AV_STB) // 88064
#define ASMEM   (SVL_OFF + 128 * AV_STB) // 106496

__global__ __launch_bounds__(128) void attn_mma()
{
    extern __shared__ char smem[];
    const unsigned sb = smem_u32(smem);
    const int tid = threadIdx.x, lane = tid & 31, w = tid >> 5;
    const int g = lane >> 2, tg = lane & 3;
    const int t8 = lane >> 3, r8 = lane & 7;
    const int q0 = blockIdx.x * 64, h = blockIdx.y, kvh = h >> 2;

    // ---- load Q tile (64 x 128) hi/lo ----
#pragma unroll
    for (int i = 0; i < 8; i++) {
        int idx = tid + i * 128;
        int row = idx >> 4, c = idx & 15;
        long gq = (long)(q0 + row) * NQD + h * HD + c * 8;
        unsigned so = (unsigned)(row * AQ_STB + c * 16);
        *(uint4*)(smem + SQ_OFF + so) = *(const uint4*)&g_qh[gq];
        *(uint4*)(smem + SQL_OFF + so) = *(const uint4*)&g_ql[gq];
    }

    const unsigned aoffQ = (unsigned)((w * 16 + (t8 & 1) * 8 + r8) * AQ_STB + (t8 >> 1) * 16);
    const unsigned boffK = (unsigned)(((t8 >> 1) * 8 + r8) * AQ_STB + (t8 & 1) * 16);
    const unsigned boffV = (unsigned)(((t8 >> 1) * 8 + r8) * AV_STB + (t8 & 1) * 16);

    float oacc[16][4];
#pragma unroll
    for (int nt = 0; nt < 16; nt++)
#pragma unroll
        for (int i = 0; i < 4; i++) oacc[nt][i] = 0.f;
    float m_lo = -1e30f, m_hi = -1e30f, l_lo = 0.f, l_hi = 0.f;

    const int qg_lo = q0 + w * 16 + g;
    const int qg_hi = qg_lo + 8;
    int lo = q0 - (WINDOW - 1);
    const int kt_lo = lo > 0 ? (lo >> 6) : 0;
    const int kt_hi = blockIdx.x;
    const float scale = 0.08838834764831845f;

    __syncthreads();

    for (int kt = kt_lo; kt <= kt_hi; kt++) {
        const int k0 = kt * 64;
        // ---- load K (64x128) and Vt (128x64) hi/lo ----
#pragma unroll
        for (int i = 0; i < 8; i++) {
            int idx = tid + i * 128;
            int row = idx >> 4, c = idx & 15;
            long gk = (long)(k0 + row) * NKVD + kvh * HD + c * 8;
            unsigned so = (unsigned)(row * AQ_STB + c * 16);
            *(uint4*)(smem + SK_OFF + so) = *(const uint4*)&g_kh[gk];
            *(uint4*)(smem + SKL_OFF + so) = *(const uint4*)&g_kl[gk];
            int vrow = idx >> 3, vc = idx & 7;
            long gv = (long)(kvh * HD + vrow) * S_LEN + k0 + vc * 8;
            unsigned vo = (unsigned)(vrow * AV_STB + vc * 16);
            *(uint4*)(smem + SV_OFF + vo) = *(const uint4*)&g_vth[gv];
            *(uint4*)(smem + SVL_OFF + vo) = *(const uint4*)&g_vtl[gv];
        }
        __syncthreads();

        // ---- S = Q K^T (16 x 64 per warp) ----
        float sacc[8][4];
#pragma unroll
        for (int nt = 0; nt < 8; nt++)
#pragma unroll
            for (int i = 0; i < 4; i++) sacc[nt][i] = 0.f;

#pragma unroll
        for (int ks = 0; ks < 8; ks++) {
            unsigned qa[4], qla[4], kb[4][4], kbl[4][4];
            LDSM4(qa, sb + SQ_OFF + aoffQ + ks * 32);
            LDSM4(qla, sb + SQL_OFF + aoffQ + ks * 32);
#pragma unroll
            for (int ntp = 0; ntp < 4; ntp++) {
                LDSM4(kb[ntp], sb + SK_OFF + boffK + ntp * (16 * AQ_STB) + ks * 32);
                LDSM4(kbl[ntp], sb + SKL_OFF + boffK + ntp * (16 * AQ_STB) + ks * 32);
            }
#pragma unroll
            for (int nt = 0; nt < 8; nt++)
                MMA_BF16(sacc[nt], qa, kb[nt >> 1][(nt & 1) * 2], kb[nt >> 1][(nt & 1) * 2 + 1]);
#pragma unroll
            for (int nt = 0; nt < 8; nt++)
                MMA_BF16(sacc[nt], qla, kb[nt >> 1][(nt & 1) * 2], kb[nt >> 1][(nt & 1) * 2 + 1]);
#pragma unroll
            for (int nt = 0; nt < 8; nt++)
                MMA_BF16(sacc[nt], qa, kbl[nt >> 1][(nt & 1) * 2], kbl[nt >> 1][(nt & 1) * 2 + 1]);
        }

        // ---- scale + mask ----
#pragma unroll
        for (int nt = 0; nt < 8; nt++) {
            int kg0 = k0 + nt * 8 + tg * 2, kg1 = kg0 + 1;
            int d00 = qg_lo - kg0, d01 = qg_lo - kg1;
            int d10 = qg_hi - kg0, d11 = qg_hi - kg1;
            sacc[nt][0] = (d00 >= 0 && d00 < WINDOW) ? sacc[nt][0] * scale : -1e30f;
            sacc[nt][1] = (d01 >= 0 && d01 < WINDOW) ? sacc[nt][1] * scale : -1e30f;
            sacc[nt][2] = (d10 >= 0 && d10 < WINDOW) ? sacc[nt][2] * scale : -1e30f;
            sacc[nt][3] = (d11 >= 0 && d11 < WINDOW) ? sacc[nt][3] * scale : -1e30f;
        }

        // ---- online softmax (rows qg_lo / qg_hi per thread quad) ----
        float mx0 = -1e30f, mx1 = -1e30f;
#pragma unroll
        for (int nt = 0; nt < 8; nt++) {
            mx0 = fmaxf(mx0, fmaxf(sacc[nt][0], sacc[nt][1]));
            mx1 = fmaxf(mx1, fmaxf(sacc[nt][2], sacc[nt][3]));
        }
        mx0 = fmaxf(mx0, __shfl_xor_sync(0xffffffffu, mx0, 1));
        mx0 = fmaxf(mx0, __shfl_xor_sync(0xffffffffu, mx0, 2));
        mx1 = fmaxf(mx1, __shfl_xor_sync(0xffffffffu, mx1, 1));
        mx1 = fmaxf(mx1, __shfl_xor_sync(0xffffffffu, mx1, 2));
        float mn0 = fmaxf(m_lo, mx0), mn1 = fmaxf(m_hi, mx1);
        float al0 = __expf(m_lo - mn0), al1 = __expf(m_hi - mn1);
        float ps0 = 0.f, ps1 = 0.f;
#pragma unroll
        for (int nt = 0; nt < 8; nt++) {
            float p0 = (sacc[nt][0] > -1e29f) ? __expf(sacc[nt][0] - mn0) : 0.f;
            float p1 = (sacc[nt][1] > -1e29f) ? __expf(sacc[nt][1] - mn0) : 0.f;
            float p2 = (sacc[nt][2] > -1e29f) ? __expf(sacc[nt][2] - mn1) : 0.f;
            float p3 = (sacc[nt][3] > -1e29f) ? __expf(sacc[nt][3] - mn1) : 0.f;
            sacc[nt][0] = p0; sacc[nt][1] = p1; sacc[nt][2] = p2; sacc[nt][3] = p3;
            ps0 += p0 + p1;
            ps1 += p2 + p3;
        }
        ps0 += __shfl_xor_sync(0xffffffffu, ps0, 1);
        ps0 += __shfl_xor_sync(0xffffffffu, ps0, 2);
        ps1 += __shfl_xor_sync(0xffffffffu, ps1, 1);
        ps1 += __shfl_xor_sync(0xffffffffu, ps1, 2);
        l_lo = l_lo * al0 + ps0; m_lo = mn0;
        l_hi = l_hi * al1 + ps1; m_hi = mn1;
#pragma unroll
        for (int nt = 0; nt < 16; nt++) {
            oacc[nt][0] *= al0; oacc[nt][1] *= al0;
            oacc[nt][2] *= al1; oacc[nt][3] *= al1;
        }

        // ---- O += P V : P frags from sacc (hi/lo), V B-frags via ldmatrix ----
#pragma unroll
        for (int kv = 0; kv < 4; kv++) {
            unsigned pa_h[4], pa_l[4];
            {
                float p00 = sacc[2 * kv][0], p01 = sacc[2 * kv][1];
                float p10 = sacc[2 * kv][2], p11 = sacc[2 * kv][3];
                float p20 = sacc[2 * kv + 1][0], p21 = sacc[2 * kv + 1][1];
                float p30 = sacc[2 * kv + 1][2], p31 = sacc[2 * kv + 1][3];
                __nv_bfloat162 h0, h1, h2, h3, l0v, l1v, l2v, l3v;
                __nv_bfloat16 hh, ll;
                split2(p00, hh, ll); h0.x = hh; l0v.x = ll;
                split2(p01, hh, ll); h0.y = hh; l0v.y = ll;
                split2(p10, hh, ll); h1.x = hh; l1v.x = ll;
                split2(p11, hh, ll); h1.y = hh; l1v.y = ll;
                split2(p20, hh, ll); h2.x = hh; l2v.x = ll;
                split2(p21, hh, ll); h2.y = hh; l2v.y = ll;
                split2(p30, hh, ll); h3.x = hh; l3v.x = ll;
                split2(p31, hh, ll); h3.y = hh; l3v.y = ll;
                pa_h[0] = *(unsigned*)&h0; pa_h[1] = *(unsigned*)&h1;
                pa_h[2] = *(unsigned*)&h2; pa_h[3] = *(unsigned*)&h3;
                pa_l[0] = *(unsigned*)&l0v; pa_l[1] = *(unsigned*)&l1v;
                pa_l[2] = *(unsigned*)&l2v; pa_l[3] = *(unsigned*)&l3v;
            }
#pragma unroll
            for (int half = 0; half < 2; half++) {
                unsigned vbh[4][4], vbl[4][4];
#pragma unroll
                for (int ntp = 0; ntp < 4; ntp++) {
                    LDSM4(vbh[ntp], sb + SV_OFF + boffV + (half * 4 + ntp) * (16 * AV_STB) + kv * 32);
                    LDSM4(vbl[ntp], sb + SVL_OFF + boffV + (half * 4 + ntp) * (16 * AV_STB) + kv * 32);
                }
#pragma unroll
                for (int nt = 0; nt < 8; nt++)
                    MMA_BF16(oacc[half * 8 + nt], pa_h, vbh[nt >> 1][(nt & 1) * 2], vbh[nt >> 1][(nt & 1) * 2 + 1]);
#pragma unroll
                for (int nt = 0; nt < 8; nt++)
                    MMA_BF16(oacc[half * 8 + nt], pa_l, vbh[nt >> 1][(nt & 1) * 2], vbh[nt >> 1][(nt & 1) * 2 + 1]);
#pragma unroll
                for (int nt = 0; nt < 8; nt++)
                    MMA_BF16(oacc[half * 8 + nt], pa_h, vbl[nt >> 1][(nt & 1) * 2], vbl[nt >> 1][(nt & 1) * 2 + 1]);
            }
        }
        __syncthreads();
    }

    // ---- epilogue: normalize + write bf16 hi/lo pairs ----
    float inv0 = 1.f / l_lo, inv1 = 1.f / l_hi;
#pragma unroll
    for (int nt = 0; nt < 16; nt++) {
        int col = h * HD + nt * 8 + tg * 2;
        float v0 = oacc[nt][0] * inv0, v1 = oacc[nt][1] * inv0;
        float v2 = oacc[nt][2] * inv1, v3 = oacc[nt][3] * inv1;
        __nv_bfloat162 hp, lp;
        __nv_bfloat16 hh, ll;
        split2(v0, hh, ll); hp.x = hh; lp.x = ll;
        split2(v1, hh, ll); hp.y = hh; lp.y = ll;
        *(__nv_bfloat162*)&g_ath[(long)qg_lo * NQD + col] = hp;
        *(__nv_bfloat162*)&g_atl[(long)qg_lo * NQD + col] = lp;
        split2(v2, hh, ll); hp.x = hh; lp.x = ll;
        split2(v3, hh, ll); hp.y = hh; lp.y = ll;
        *(__nv_bfloat162*)&g_ath[(long)qg_hi * NQD + col] = hp;
        *(__nv_bfloat162*)&g_atl[(long)qg_hi * NQD + col] = lp;
    }
}

// ============================================================================
extern "C" void kernel_launch(void* const* d_in, const int* in_sizes, int n_in,
                              void* d_out, int out_size)
{
    const float* x   = (const float*)d_in[0];
    const float* fc  = (const float*)d_in[1];
    const float* fs  = (const float*)d_in[2];
    // d_in[3]: mask — unused (causal + sliding window computed analytically)
    const float* w_q = (const float*)d_in[4];
    const float* w_k = (const float*)d_in[5];
    const float* w_v = (const float*)d_in[6];
    const float* w_o = (const float*)d_in[7];
    float* out = (float*)d_out;

    float *gq, *gk, *gv;
    cudaGetSymbolAddress((void**)&gq, g_q);
    cudaGetSymbolAddress((void**)&gk, g_k);
    cudaGetSymbolAddress((void**)&gv, g_v);
    __nv_bfloat16 *xh, *xl, *ath, *atl, *qh, *ql, *kh, *kl, *vth, *vtl;
    __nv_bfloat16 *wqh, *wql, *wkh, *wkl, *wvh, *wvl, *woh, *wol;
    cudaGetSymbolAddress((void**)&xh, g_xh);   cudaGetSymbolAddress((void**)&xl, g_xl);
    cudaGetSymbolAddress((void**)&ath, g_ath); cudaGetSymbolAddress((void**)&atl, g_atl);
    cudaGetSymbolAddress((void**)&qh, g_qh);   cudaGetSymbolAddress((void**)&ql, g_ql);
    cudaGetSymbolAddress((void**)&kh, g_kh);   cudaGetSymbolAddress((void**)&kl, g_kl);
    cudaGetSymbolAddress((void**)&vth, g_vth); cudaGetSymbolAddress((void**)&vtl, g_vtl);
    cudaGetSymbolAddress((void**)&wqh, g_wqh); cudaGetSymbolAddress((void**)&wql, g_wql);
    cudaGetSymbolAddress((void**)&wkh, g_wkh); cudaGetSymbolAddress((void**)&wkl, g_wkl);
    cudaGetSymbolAddress((void**)&wvh, g_wvh); cudaGetSymbolAddress((void**)&wvl, g_wvl);
    cudaGetSymbolAddress((void**)&woh, g_woh); cudaGetSymbolAddress((void**)&wol, g_wol);

    cudaFuncSetAttribute(gemm_mma, cudaFuncAttributeMaxDynamicSharedMemorySize, GSMEM);
    cudaFuncSetAttribute(attn_mma, cudaFuncAttributeMaxDynamicSharedMemorySize, ASMEM);

    // one-time operand prep
    cvt_hl<<<(S_LEN * D_MODEL / 4 + 255) / 256, 256>>>(x, xh, xl, S_LEN * D_MODEL);
    transpose_hl<<<dim3(NQD / 32, D_MODEL / 32), dim3(32, 8)>>>(w_q, wqh, wql, D_MODEL, NQD);
    transpose_hl<<<dim3(NKVD / 32, D_MODEL / 32), dim3(32, 8)>>>(w_k, wkh, wkl, D_MODEL, NKVD);
    transpose_hl<<<dim3(NKVD / 32, D_MODEL / 32), dim3(32, 8)>>>(w_v, wvh, wvl, D_MODEL, NKVD);
    transpose_hl<<<dim3(D_MODEL / 32, NQD / 32), dim3(32, 8)>>>(w_o, woh, wol, NQD, D_MODEL);

    // QKV projections
    gemm_mma<<<dim3(NQD / 128, S_LEN / 128), 256, GSMEM>>>(xh, xl, wqh, wql, gq, S_LEN, NQD, D_MODEL);
    gemm_mma<<<dim3(NKVD / 128, S_LEN / 128), 256, GSMEM>>>(xh, xl, wkh, wkl, gk, S_LEN, NKVD, D_MODEL);
    gemm_mma<<<dim3(NKVD / 128, S_LEN / 128), 256, GSMEM>>>(xh, xl, wvh, wvl, gv, S_LEN, NKVD, D_MODEL);

    // RoPE (fp32), then convert Q/K and transpose-convert V for attention
    rope_kernel<<<(S_LEN * NQ * 64 + 255) / 256, 256>>>(gq, fc, fs, NQ);
    rope_kernel<<<(S_LEN * NKV * 64 + 255) / 256, 256>>>(gk, fc, fs, NKV);
    cvt_hl<<<(S_LEN * NQD / 4 + 255) / 256, 256>>>(gq, qh, ql, S_LEN * NQD);
    cvt_hl<<<(S_LEN * NKVD / 4 + 255) / 256, 256>>>(gk, kh, kl, S_LEN * NKVD);
    vtrans_hl<<<dim3(S_LEN / 32, HD / 32, NKV), dim3(32, 8)>>>(gv, vth, vtl);

    // attention (writes g_ath/g_atl)
    attn_mma<<<dim3(S_LEN / 64, NQ), 128, ASMEM>>>();

    // output projection
    gemm_mma<<<dim3(D_MODEL / 128, S_LEN / 128), 256, GSMEM>>>(ath, atl, woh, wol, out, S_LEN, D_MODEL, NQD);
}

// round 7
// speedup vs baseline: 4.8761x; 1.1367x over previous
#include <cuda_runtime.h>
#include <cuda_bf16.h>
#include <cstdint>

#define S_LEN   2048
#define D_MODEL 4096
#define NQ      32
#define NKV     8
#define HD      128
#define WINDOW  1024
#define NQD     (NQ*HD)    // 4096
#define NKVD    (NKV*HD)   // 1024

// ---- fp32 scratch ----
__device__ float g_v[S_LEN * NKVD];
// ---- bf16 hi/lo operands ----
__device__ __nv_bfloat16 g_xh[S_LEN * D_MODEL],  g_xl[S_LEN * D_MODEL];
__device__ __nv_bfloat16 g_ath[S_LEN * NQD],     g_atl[S_LEN * NQD];   // attn out
__device__ __nv_bfloat16 g_qh[S_LEN * NQD],      g_ql[S_LEN * NQD];
__device__ __nv_bfloat16 g_kh[S_LEN * NKVD],     g_kl[S_LEN * NKVD];
__device__ __nv_bfloat16 g_vth[NKVD * S_LEN],    g_vtl[NKVD * S_LEN];  // [kvh][hd][seq]
__device__ __nv_bfloat16 g_wqh[NQD * D_MODEL],   g_wql[NQD * D_MODEL]; // [N][K]
__device__ __nv_bfloat16 g_wkh[NKVD * D_MODEL],  g_wkl[NKVD * D_MODEL];
__device__ __nv_bfloat16 g_wvh[NKVD * D_MODEL],  g_wvl[NKVD * D_MODEL];
__device__ __nv_bfloat16 g_woh[D_MODEL * NQD],   g_wol[D_MODEL * NQD];

// ============================================================================
// helpers
// ============================================================================
__device__ __forceinline__ unsigned smem_u32(const void* p) {
    unsigned a;
    asm("{ .reg .u64 t; cvta.to.shared.u64 t, %1; cvt.u32.u64 %0, t; }" : "=r"(a) : "l"(p));
    return a;
}
__device__ __forceinline__ void cp_async16(unsigned s, const void* g) {
    asm volatile("cp.async.cg.shared.global [%0], [%1], 16;" :: "r"(s), "l"(g) : "memory");
}
__device__ __forceinline__ void split2(float v, __nv_bfloat16& h, __nv_bfloat16& l) {
    h = __float2bfloat16_rn(v);
    l = __float2bfloat16_rn(v - __bfloat162float(h));
}

#define MMA_BF16(acc, a, b0v, b1v)                                            \
    asm volatile(                                                             \
        "mma.sync.aligned.m16n8k16.row.col.f32.bf16.bf16.f32 "                \
        "{%0,%1,%2,%3},{%4,%5,%6,%7},{%8,%9},{%0,%1,%2,%3};"                  \
        : "+f"(acc[0]), "+f"(acc[1]), "+f"(acc[2]), "+f"(acc[3])              \
        : "r"(a[0]), "r"(a[1]), "r"(a[2]), "r"(a[3]), "r"(b0v), "r"(b1v))

#define LDSM4(r, addr)                                                        \
    asm volatile("ldmatrix.sync.aligned.m8n8.x4.shared.b16 {%0,%1,%2,%3}, [%4];" \
        : "=r"((r)[0]), "=r"((r)[1]), "=r"((r)[2]), "=r"((r)[3]) : "r"(addr))

// ============================================================================
// one-time converts
// ============================================================================
__global__ void cvt_hl(const float* __restrict__ in, __nv_bfloat16* __restrict__ ho,
                       __nv_bfloat16* __restrict__ lo, int n) {
    int i = (blockIdx.x * blockDim.x + threadIdx.x) * 4;
    if (i >= n) return;
    float4 v = *(const float4*)&in[i];
    __align__(8) __nv_bfloat16 h[4], l[4];
    split2(v.x, h[0], l[0]);
    split2(v.y, h[1], l[1]);
    split2(v.z, h[2], l[2]);
    split2(v.w, h[3], l[3]);
    *(uint2*)&ho[i] = *(uint2*)h;
    *(uint2*)&lo[i] = *(uint2*)l;
}

// weights: w[K][N] fp32 -> th/tl[N][K] bf16 (transpose + split)
__global__ void transpose_hl(const float* __restrict__ w, __nv_bfloat16* __restrict__ th,
                             __nv_bfloat16* __restrict__ tl, int K, int N) {
    __shared__ float t[32][33];
    int n0 = blockIdx.x * 32, k0 = blockIdx.y * 32;
    int tx = threadIdx.x, ty = threadIdx.y;   // 32 x 8
#pragma unroll
    for (int i = 0; i < 32; i += 8)
        t[ty + i][tx] = w[(k0 + ty + i) * N + n0 + tx];
    __syncthreads();
#pragma unroll
    for (int i = 0; i < 32; i += 8) {
        float v = t[tx][ty + i];
        __nv_bfloat16 h, l;
        split2(v, h, l);
        th[(n0 + ty + i) * K + k0 + tx] = h;
        tl[(n0 + ty + i) * K + k0 + tx] = l;
    }
}

// V: g_v [seq][kvh*128] fp32 -> vth/vtl [kvh][hd][seq] bf16
__global__ void vtrans_hl(const float* __restrict__ v, __nv_bfloat16* __restrict__ th,
                          __nv_bfloat16* __restrict__ tl) {
    __shared__ float t[32][33];
    int s0 = blockIdx.x * 32, h0 = blockIdx.y * 32, kvh = blockIdx.z;
    int tx = threadIdx.x, ty = threadIdx.y;
#pragma unroll
    for (int i = 0; i < 32; i += 8)
        t[ty + i][tx] = v[(s0 + ty + i) * NKVD + kvh * HD + h0 + tx];
    __syncthreads();
#pragma unroll
    for (int i = 0; i < 32; i += 8) {
        float val = t[tx][ty + i];
        __nv_bfloat16 h, l;
        split2(val, h, l);
        long o = (long)(kvh * HD + h0 + ty + i) * S_LEN + s0 + tx;
        th[o] = h;
        tl[o] = l;
    }
}

// ============================================================================
// mma.sync GEMM: C = A[M,K] @ Bt[N,K]^T. 128x128 tile, K-slab 32, 256 thr,
// 2 CTAs/SM (register-dieted: hold a_h + b frags; reload a_l in its pass).
// MODE 0: fp32 C.  MODE 1: fused RoPE + hi/lo bf16 split (for Q/K proj).
// ============================================================================
#define ABYTES 10240
#define STAGEB (4 * ABYTES)
#define GSMEM  (2 * STAGEB)

template<int MODE>
__global__ __launch_bounds__(256, 2) void gemm_mma(
    const __nv_bfloat16* __restrict__ Ah, const __nv_bfloat16* __restrict__ Al,
    const __nv_bfloat16* __restrict__ Bh, const __nv_bfloat16* __restrict__ Bl,
    float* __restrict__ C, __nv_bfloat16* __restrict__ Ch, __nv_bfloat16* __restrict__ Cl,
    const float* __restrict__ cosb, const float* __restrict__ sinb,
    int M, int N, int K)
{
    extern __shared__ char smem[];
    const int tid = threadIdx.x, lane = tid & 31, w = tid >> 5;
    const int g = lane >> 2, tg = lane & 3;
    const int t8 = lane >> 3, r8 = lane & 7;
    const int wm = (w & 1) * 64, wn = (w >> 1) * 32;
    const int m0 = blockIdx.y * 128, n0 = blockIdx.x * 128;
    const unsigned sbase = smem_u32(smem);

    auto load_slab = [&](int st, int kt) {
        unsigned s0 = sbase + st * STAGEB;
#pragma unroll
        for (int i = 0; i < 2; i++) {
            int idx = tid + i * 256;
            int row = idx >> 2, c = idx & 3;
            unsigned so = (unsigned)(row * 80 + c * 16);
            long ea = (long)(m0 + row) * K + kt + c * 8;
            long eb = (long)(n0 + row) * K + kt + c * 8;
            cp_async16(s0 + so, Ah + ea);
            cp_async16(s0 + ABYTES + so, Al + ea);
            cp_async16(s0 + 2 * ABYTES + so, Bh + eb);
            cp_async16(s0 + 3 * ABYTES + so, Bl + eb);
        }
        asm volatile("cp.async.commit_group;" ::: "memory");
    };

    float acc[4][4][4];
#pragma unroll
    for (int mt = 0; mt < 4; mt++)
#pragma unroll
        for (int nt = 0; nt < 4; nt++)
#pragma unroll
            for (int i = 0; i < 4; i++) acc[mt][nt][i] = 0.f;

    const unsigned aoff = (unsigned)((wm + (t8 & 1) * 8 + r8) * 80 + (t8 >> 1) * 16);
    const unsigned boff = (unsigned)((wn + (t8 >> 1) * 8 + r8) * 80 + (t8 & 1) * 16);

    const int T = K >> 5;
    load_slab(0, 0);
    load_slab(1, 32);

    for (int it = 0; it < T; it++) {
        asm volatile("cp.async.wait_group 1;" ::: "memory");
        __syncthreads();
        unsigned sb = sbase + (it & 1) * STAGEB;
        unsigned sAh = sb, sAl = sb + ABYTES, sBh = sb + 2 * ABYTES, sBl = sb + 3 * ABYTES;

#pragma unroll
        for (int ks = 0; ks < 2; ks++) {       // k16 halves; byte offset ks*32
            unsigned b_h[2][4], b_l[2][4], a_h[4][4];
#pragma unroll
            for (int ntp = 0; ntp < 2; ntp++) {
                LDSM4(b_h[ntp], sBh + boff + ntp * 1280 + ks * 32);
                LDSM4(b_l[ntp], sBl + boff + ntp * 1280 + ks * 32);
            }
#pragma unroll
            for (int mt = 0; mt < 4; mt++)
                LDSM4(a_h[mt], sAh + aoff + mt * 1280 + ks * 32);
            // pass 1: Ah * Bh
#pragma unroll
            for (int mt = 0; mt < 4; mt++)
#pragma unroll
                for (int nt = 0; nt < 4; nt++)
                    MMA_BF16(acc[mt][nt], a_h[mt], b_h[nt >> 1][(nt & 1) * 2], b_h[nt >> 1][(nt & 1) * 2 + 1]);
            // pass 2: Ah * Bl
#pragma unroll
            for (int mt = 0; mt < 4; mt++)
#pragma unroll
                for (int nt = 0; nt < 4; nt++)
                    MMA_BF16(acc[mt][nt], a_h[mt], b_l[nt >> 1][(nt & 1) * 2], b_l[nt >> 1][(nt & 1) * 2 + 1]);
            // pass 3: Al * Bh (reload A-lo frags; acc reuse distance stays 16)
#pragma unroll
            for (int mt = 0; mt < 4; mt++) {
                unsigned a_l[4];
                LDSM4(a_l, sAl + aoff + mt * 1280 + ks * 32);
#pragma unroll
                for (int nt = 0; nt < 4; nt++)
                    MMA_BF16(acc[mt][nt], a_l, b_h[nt >> 1][(nt & 1) * 2], b_h[nt >> 1][(nt & 1) * 2 + 1]);
            }
        }
        __syncthreads();
        if (it + 2 < T) load_slab(it & 1, (it + 2) * 32);
    }

    // ---- epilogue ----
#pragma unroll
    for (int mt = 0; mt < 4; mt++)
#pragma unroll
        for (int nt = 0; nt < 4; nt++) {
            int row = m0 + wm + mt * 16 + g;
            int col = n0 + wn + nt * 8 + tg * 2;
            if (MODE == 0) {
                float2 v0 = {acc[mt][nt][0], acc[mt][nt][1]};
                float2 v1 = {acc[mt][nt][2], acc[mt][nt][3]};
                *(float2*)&C[(long)row * N + col] = v0;
                *(float2*)&C[(long)(row + 8) * N + col] = v1;
            } else {
                // fused RoPE on (col, col+1) pair + hi/lo split
                int pi = (col & 127) >> 1;
#pragma unroll
                for (int half = 0; half < 2; half++) {
                    int rr = row + half * 8;
                    float cs = cosb[rr * 64 + pi], sn = sinb[rr * 64 + pi];
                    float e = acc[mt][nt][half * 2], o = acc[mt][nt][half * 2 + 1];
                    float re = e * cs - o * sn;
                    float ro = e * sn + o * cs;
                    __nv_bfloat162 hp, lp;
                    __nv_bfloat16 hh, ll;
                    split2(re, hh, ll); hp.x = hh; lp.x = ll;
                    split2(ro, hh, ll); hp.y = hh; lp.y = ll;
                    *(__nv_bfloat162*)&Ch[(long)rr * N + col] = hp;
                    *(__nv_bfloat162*)&Cl[(long)rr * N + col] = lp;
                }
            }
        }
}

// ============================================================================
// mma.sync flash attention: BQ=BK=64, 128 thr (4 warps, warp = 16 q-rows).
// Q/K hi/lo in smem [row][136]; Vt hi/lo in smem [hd][72]. 3-pass bf16.
// ============================================================================
#define AQ_STB 272
#define AV_STB 144
#define SQ_OFF 0
#define SQL_OFF (64 * AQ_STB)
#define SK_OFF  (2 * 64 * AQ_STB)
#define SKL_OFF (3 * 64 * AQ_STB)
#define SV_OFF  (4 * 64 * AQ_STB)
#define SVL_OFF (SV_OFF + 128 * AV_STB)
#define ASMEM   (SVL_OFF + 128 * AV_STB)

__global__ __launch_bounds__(128) void attn_mma()
{
    extern __shared__ char smem[];
    const unsigned sb = smem_u32(smem);
    const int tid = threadIdx.x, lane = tid & 31, w = tid >> 5;
    const int g = lane >> 2, tg = lane & 3;
    const int t8 = lane >> 3, r8 = lane & 7;
    const int q0 = blockIdx.x * 64, h = blockIdx.y, kvh = h >> 2;

#pragma unroll
    for (int i = 0; i < 8; i++) {
        int idx = tid + i * 128;
        int row = idx >> 4, c = idx & 15;
        long gq = (long)(q0 + row) * NQD + h * HD + c * 8;
        unsigned so = (unsigned)(row * AQ_STB + c * 16);
        *(uint4*)(smem + SQ_OFF + so) = *(const uint4*)&g_qh[gq];
        *(uint4*)(smem + SQL_OFF + so) = *(const uint4*)&g_ql[gq];
    }

    const unsigned aoffQ = (unsigned)((w * 16 + (t8 & 1) * 8 + r8) * AQ_STB + (t8 >> 1) * 16);
    const unsigned boffK = (unsigned)(((t8 >> 1) * 8 + r8) * AQ_STB + (t8 & 1) * 16);
    const unsigned boffV = (unsigned)(((t8 >> 1) * 8 + r8) * AV_STB + (t8 & 1) * 16);

    float oacc[16][4];
#pragma unroll
    for (int nt = 0; nt < 16; nt++)
#pragma unroll
        for (int i = 0; i < 4; i++) oacc[nt][i] = 0.f;
    float m_lo = -1e30f, m_hi = -1e30f, l_lo = 0.f, l_hi = 0.f;

    const int qg_lo = q0 + w * 16 + g;
    const int qg_hi = qg_lo + 8;
    int lo = q0 - (WINDOW - 1);
    const int kt_lo = lo > 0 ? (lo >> 6) : 0;
    const int kt_hi = blockIdx.x;
    const float scale = 0.08838834764831845f;

    __syncthreads();

    for (int kt = kt_lo; kt <= kt_hi; kt++) {
        const int k0 = kt * 64;
#pragma unroll
        for (int i = 0; i < 8; i++) {
            int idx = tid + i * 128;
            int row = idx >> 4, c = idx & 15;
            long gk = (long)(k0 + row) * NKVD + kvh * HD + c * 8;
            unsigned so = (unsigned)(row * AQ_STB + c * 16);
            *(uint4*)(smem + SK_OFF + so) = *(const uint4*)&g_kh[gk];
            *(uint4*)(smem + SKL_OFF + so) = *(const uint4*)&g_kl[gk];
            int vrow = idx >> 3, vc = idx & 7;
            long gv = (long)(kvh * HD + vrow) * S_LEN + k0 + vc * 8;
            unsigned vo = (unsigned)(vrow * AV_STB + vc * 16);
            *(uint4*)(smem + SV_OFF + vo) = *(const uint4*)&g_vth[gv];
            *(uint4*)(smem + SVL_OFF + vo) = *(const uint4*)&g_vtl[gv];
        }
        __syncthreads();

        float sacc[8][4];
#pragma unroll
        for (int nt = 0; nt < 8; nt++)
#pragma unroll
            for (int i = 0; i < 4; i++) sacc[nt][i] = 0.f;

#pragma unroll
        for (int ks = 0; ks < 8; ks++) {
            unsigned qa[4], qla[4], kb[4][4], kbl[4][4];
            LDSM4(qa, sb + SQ_OFF + aoffQ + ks * 32);
            LDSM4(qla, sb + SQL_OFF + aoffQ + ks * 32);
#pragma unroll
            for (int ntp = 0; ntp < 4; ntp++) {
                LDSM4(kb[ntp], sb + SK_OFF + boffK + ntp * (16 * AQ_STB) + ks * 32);
                LDSM4(kbl[ntp], sb + SKL_OFF + boffK + ntp * (16 * AQ_STB) + ks * 32);
            }
#pragma unroll
            for (int nt = 0; nt < 8; nt++)
                MMA_BF16(sacc[nt], qa, kb[nt >> 1][(nt & 1) * 2], kb[nt >> 1][(nt & 1) * 2 + 1]);
#pragma unroll
            for (int nt = 0; nt < 8; nt++)
                MMA_BF16(sacc[nt], qla, kb[nt >> 1][(nt & 1) * 2], kb[nt >> 1][(nt & 1) * 2 + 1]);
#pragma unroll
            for (int nt = 0; nt < 8; nt++)
                MMA_BF16(sacc[nt], qa, kbl[nt >> 1][(nt & 1) * 2], kbl[nt >> 1][(nt & 1) * 2 + 1]);
        }

#pragma unroll
        for (int nt = 0; nt < 8; nt++) {
            int kg0 = k0 + nt * 8 + tg * 2, kg1 = kg0 + 1;
            int d00 = qg_lo - kg0, d01 = qg_lo - kg1;
            int d10 = qg_hi - kg0, d11 = qg_hi - kg1;
            sacc[nt][0] = (d00 >= 0 && d00 < WINDOW) ? sacc[nt][0] * scale : -1e30f;
            sacc[nt][1] = (d01 >= 0 && d01 < WINDOW) ? sacc[nt][1] * scale : -1e30f;
            sacc[nt][2] = (d10 >= 0 && d10 < WINDOW) ? sacc[nt][2] * scale : -1e30f;
            sacc[nt][3] = (d11 >= 0 && d11 < WINDOW) ? sacc[nt][3] * scale : -1e30f;
        }

        float mx0 = -1e30f, mx1 = -1e30f;
#pragma unroll
        for (int nt = 0; nt < 8; nt++) {
            mx0 = fmaxf(mx0, fmaxf(sacc[nt][0], sacc[nt][1]));
            mx1 = fmaxf(mx1, fmaxf(sacc[nt][2], sacc[nt][3]));
        }
        mx0 = fmaxf(mx0, __shfl_xor_sync(0xffffffffu, mx0, 1));
        mx0 = fmaxf(mx0, __shfl_xor_sync(0xffffffffu, mx0, 2));
        mx1 = fmaxf(mx1, __shfl_xor_sync(0xffffffffu, mx1, 1));
        mx1 = fmaxf(mx1, __shfl_xor_sync(0xffffffffu, mx1, 2));
        float mn0 = fmaxf(m_lo, mx0), mn1 = fmaxf(m_hi, mx1);
        float al0 = __expf(m_lo - mn0), al1 = __expf(m_hi - mn1);
        float ps0 = 0.f, ps1 = 0.f;
#pragma unroll
        for (int nt = 0; nt < 8; nt++) {
            float p0 = (sacc[nt][0] > -1e29f) ? __expf(sacc[nt][0] - mn0) : 0.f;
            float p1 = (sacc[nt][1] > -1e29f) ? __expf(sacc[nt][1] - mn0) : 0.f;
            float p2 = (sacc[nt][2] > -1e29f) ? __expf(sacc[nt][2] - mn1) : 0.f;
            float p3 = (sacc[nt][3] > -1e29f) ? __expf(sacc[nt][3] - mn1) : 0.f;
            sacc[nt][0] = p0; sacc[nt][1] = p1; sacc[nt][2] = p2; sacc[nt][3] = p3;
            ps0 += p0 + p1;
            ps1 += p2 + p3;
        }
        ps0 += __shfl_xor_sync(0xffffffffu, ps0, 1);
        ps0 += __shfl_xor_sync(0xffffffffu, ps0, 2);
        ps1 += __shfl_xor_sync(0xffffffffu, ps1, 1);
        ps1 += __shfl_xor_sync(0xffffffffu, ps1, 2);
        l_lo = l_lo * al0 + ps0; m_lo = mn0;
        l_hi = l_hi * al1 + ps1; m_hi = mn1;
#pragma unroll
        for (int nt = 0; nt < 16; nt++) {
            oacc[nt][0] *= al0; oacc[nt][1] *= al0;
            oacc[nt][2] *= al1; oacc[nt][3] *= al1;
        }

#pragma unroll
        for (int kv = 0; kv < 4; kv++) {
            unsigned pa_h[4], pa_l[4];
            {
                float p00 = sacc[2 * kv][0], p01 = sacc[2 * kv][1];
                float p10 = sacc[2 * kv][2], p11 = sacc[2 * kv][3];
                float p20 = sacc[2 * kv + 1][0], p21 = sacc[2 * kv + 1][1];
                float p30 = sacc[2 * kv + 1][2], p31 = sacc[2 * kv + 1][3];
                __nv_bfloat162 h0, h1, h2, h3, l0v, l1v, l2v, l3v;
                __nv_bfloat16 hh, ll;
                split2(p00, hh, ll); h0.x = hh; l0v.x = ll;
                split2(p01, hh, ll); h0.y = hh; l0v.y = ll;
                split2(p10, hh, ll); h1.x = hh; l1v.x = ll;
                split2(p11, hh, ll); h1.y = hh; l1v.y = ll;
                split2(p20, hh, ll); h2.x = hh; l2v.x = ll;
                split2(p21, hh, ll); h2.y = hh; l2v.y = ll;
                split2(p30, hh, ll); h3.x = hh; l3v.x = ll;
                split2(p31, hh, ll); h3.y = hh; l3v.y = ll;
                pa_h[0] = *(unsigned*)&h0; pa_h[1] = *(unsigned*)&h1;
                pa_h[2] = *(unsigned*)&h2; pa_h[3] = *(unsigned*)&h3;
                pa_l[0] = *(unsigned*)&l0v; pa_l[1] = *(unsigned*)&l1v;
                pa_l[2] = *(unsigned*)&l2v; pa_l[3] = *(unsigned*)&l3v;
            }
#pragma unroll
            for (int half = 0; half < 2; half++) {
                unsigned vbh[4][4], vbl[4][4];
#pragma unroll
                for (int ntp = 0; ntp < 4; ntp++) {
                    LDSM4(vbh[ntp], sb + SV_OFF + boffV + (half * 4 + ntp) * (16 * AV_STB) + kv * 32);
                    LDSM4(vbl[ntp], sb + SVL_OFF + boffV + (half * 4 + ntp) * (16 * AV_STB) + kv * 32);
                }
#pragma unroll
                for (int nt = 0; nt < 8; nt++)
                    MMA_BF16(oacc[half * 8 + nt], pa_h, vbh[nt >> 1][(nt & 1) * 2], vbh[nt >> 1][(nt & 1) * 2 + 1]);
#pragma unroll
                for (int nt = 0; nt < 8; nt++)
                    MMA_BF16(oacc[half * 8 + nt], pa_l, vbh[nt >> 1][(nt & 1) * 2], vbh[nt >> 1][(nt & 1) * 2 + 1]);
#pragma unroll
                for (int nt = 0; nt < 8; nt++)
                    MMA_BF16(oacc[half * 8 + nt], pa_h, vbl[nt >> 1][(nt & 1) * 2], vbl[nt >> 1][(nt & 1) * 2 + 1]);
            }
        }
        __syncthreads();
    }

    float inv0 = 1.f / l_lo, inv1 = 1.f / l_hi;
#pragma unroll
    for (int nt = 0; nt < 16; nt++) {
        int col = h * HD + nt * 8 + tg * 2;
        float v0 = oacc[nt][0] * inv0, v1 = oacc[nt][1] * inv0;
        float v2 = oacc[nt][2] * inv1, v3 = oacc[nt][3] * inv1;
        __nv_bfloat162 hp, lp;
        __nv_bfloat16 hh, ll;
        split2(v0, hh, ll); hp.x = hh; lp.x = ll;
        split2(v1, hh, ll); hp.y = hh; lp.y = ll;
        *(__nv_bfloat162*)&g_ath[(long)qg_lo * NQD + col] = hp;
        *(__nv_bfloat162*)&g_atl[(long)qg_lo * NQD + col] = lp;
        split2(v2, hh, ll); hp.x = hh; lp.x = ll;
        split2(v3, hh, ll); hp.y = hh; lp.y = ll;
        *(__nv_bfloat162*)&g_ath[(long)qg_hi * NQD + col] = hp;
        *(__nv_bfloat162*)&g_atl[(long)qg_hi * NQD + col] = lp;
    }
}

// ============================================================================
extern "C" void kernel_launch(void* const* d_in, const int* in_sizes, int n_in,
                              void* d_out, int out_size)
{
    const float* x   = (const float*)d_in[0];
    const float* fc  = (const float*)d_in[1];
    const float* fs  = (const float*)d_in[2];
    // d_in[3]: mask — unused (causal + sliding window computed analytically)
    const float* w_q = (const float*)d_in[4];
    const float* w_k = (const float*)d_in[5];
    const float* w_v = (const float*)d_in[6];
    const float* w_o = (const float*)d_in[7];
    float* out = (float*)d_out;

    float *gv;
    cudaGetSymbolAddress((void**)&gv, g_v);
    __nv_bfloat16 *xh, *xl, *ath, *atl, *qh, *ql, *kh, *kl, *vth, *vtl;
    __nv_bfloat16 *wqh, *wql, *wkh, *wkl, *wvh, *wvl, *woh, *wol;
    cudaGetSymbolAddress((void**)&xh, g_xh);   cudaGetSymbolAddress((void**)&xl, g_xl);
    cudaGetSymbolAddress((void**)&ath, g_ath); cudaGetSymbolAddress((void**)&atl, g_atl);
    cudaGetSymbolAddress((void**)&qh, g_qh);   cudaGetSymbolAddress((void**)&ql, g_ql);
    cudaGetSymbolAddress((void**)&kh, g_kh);   cudaGetSymbolAddress((void**)&kl, g_kl);
    cudaGetSymbolAddress((void**)&vth, g_vth); cudaGetSymbolAddress((void**)&vtl, g_vtl);
    cudaGetSymbolAddress((void**)&wqh, g_wqh); cudaGetSymbolAddress((void**)&wql, g_wql);
    cudaGetSymbolAddress((void**)&wkh, g_wkh); cudaGetSymbolAddress((void**)&wkl, g_wkl);
    cudaGetSymbolAddress((void**)&wvh, g_wvh); cudaGetSymbolAddress((void**)&wvl, g_wvl);
    cudaGetSymbolAddress((void**)&woh, g_woh); cudaGetSymbolAddress((void**)&wol, g_wol);

    cudaFuncSetAttribute(gemm_mma<0>, cudaFuncAttributeMaxDynamicSharedMemorySize, GSMEM);
    cudaFuncSetAttribute(gemm_mma<1>, cudaFuncAttributeMaxDynamicSharedMemorySize, GSMEM);
    cudaFuncSetAttribute(attn_mma, cudaFuncAttributeMaxDynamicSharedMemorySize, ASMEM);

    // one-time operand prep
    cvt_hl<<<(S_LEN * D_MODEL / 4 + 255) / 256, 256>>>(x, xh, xl, S_LEN * D_MODEL);
    transpose_hl<<<dim3(NQD / 32, D_MODEL / 32), dim3(32, 8)>>>(w_q, wqh, wql, D_MODEL, NQD);
    transpose_hl<<<dim3(NKVD / 32, D_MODEL / 32), dim3(32, 8)>>>(w_k, wkh, wkl, D_MODEL, NKVD);
    transpose_hl<<<dim3(NKVD / 32, D_MODEL / 32), dim3(32, 8)>>>(w_v, wvh, wvl, D_MODEL, NKVD);
    transpose_hl<<<dim3(D_MODEL / 32, NQD / 32), dim3(32, 8)>>>(w_o, woh, wol, NQD, D_MODEL);

    // Q/K projections with fused RoPE + split; V projection to fp32
    gemm_mma<1><<<dim3(NQD / 128, S_LEN / 128), 256, GSMEM>>>(
        xh, xl, wqh, wql, nullptr, qh, ql, fc, fs, S_LEN, NQD, D_MODEL);
    gemm_mma<1><<<dim3(NKVD / 128, S_LEN / 128), 256, GSMEM>>>(
        xh, xl, wkh, wkl, nullptr, kh, kl, fc, fs, S_LEN, NKVD, D_MODEL);
    gemm_mma<0><<<dim3(NKVD / 128, S_LEN / 128), 256, GSMEM>>>(
        xh, xl, wvh, wvl, gv, nullptr, nullptr, nullptr, nullptr, S_LEN, NKVD, D_MODEL);

    vtrans_hl<<<dim3(S_LEN / 32, HD / 32, NKV), dim3(32, 8)>>>(gv, vth, vtl);

    // attention (writes g_ath/g_atl)
    attn_mma<<<dim3(S_LEN / 64, NQ), 128, ASMEM>>>();

    // output projection
    gemm_mma<0><<<dim3(D_MODEL / 128, S_LEN / 128), 256, GSMEM>>>(
        ath, atl, woh, wol, out, nullptr, nullptr, nullptr, nullptr, S_LEN, D_MODEL, NQD);
}

// round 10
// speedup vs baseline: 5.0093x; 1.0273x over previous
#include <cuda_runtime.h>
#include <cuda_bf16.h>
#include <cstdint>

#define S_LEN   2048
#define D_MODEL 4096
#define NQ      32
#define NKV     8
#define HD      128
#define WINDOW  1024
#define NQD     (NQ*HD)    // 4096
#define NKVD    (NKV*HD)   // 1024
#define NCAT    (NQD + 2*NKVD)  // 6144 fused QKV output width

// ---- bf16 hi/lo operands ----
__device__ __nv_bfloat16 g_xh[S_LEN * D_MODEL],  g_xl[S_LEN * D_MODEL];
__device__ __nv_bfloat16 g_ath[S_LEN * NQD],     g_atl[S_LEN * NQD];   // attn out
__device__ __nv_bfloat16 g_qh[S_LEN * NQD],      g_ql[S_LEN * NQD];
__device__ __nv_bfloat16 g_kh[S_LEN * NKVD],     g_kl[S_LEN * NKVD];
__device__ __nv_bfloat16 g_vth[NKVD * S_LEN],    g_vtl[NKVD * S_LEN];  // [kvh*hd][seq]
__device__ __nv_bfloat16 g_wch[NCAT * D_MODEL],  g_wcl[NCAT * D_MODEL]; // [wq;wk;wv] [N][K]
__device__ __nv_bfloat16 g_woh[D_MODEL * NQD],   g_wol[D_MODEL * NQD];

// ============================================================================
// helpers
// ============================================================================
__device__ __forceinline__ unsigned smem_u32(const void* p) {
    unsigned a;
    asm("{ .reg .u64 t; cvta.to.shared.u64 t, %1; cvt.u32.u64 %0, t; }" : "=r"(a) : "l"(p));
    return a;
}
__device__ __forceinline__ void cp_async16(unsigned s, const void* g) {
    asm volatile("cp.async.cg.shared.global [%0], [%1], 16;" :: "r"(s), "l"(g) : "memory");
}
__device__ __forceinline__ void split2(float v, __nv_bfloat16& h, __nv_bfloat16& l) {
    h = __float2bfloat16_rn(v);
    l = __float2bfloat16_rn(v - __bfloat162float(h));
}

#define MMA_BF16(acc, a, b0v, b1v)                                            \
    asm volatile(                                                             \
        "mma.sync.aligned.m16n8k16.row.col.f32.bf16.bf16.f32 "                \
        "{%0,%1,%2,%3},{%4,%5,%6,%7},{%8,%9},{%0,%1,%2,%3};"                  \
        : "+f"(acc[0]), "+f"(acc[1]), "+f"(acc[2]), "+f"(acc[3])              \
        : "r"(a[0]), "r"(a[1]), "r"(a[2]), "r"(a[3]), "r"(b0v), "r"(b1v))

#define LDSM4(r, addr)                                                        \
    asm volatile("ldmatrix.sync.aligned.m8n8.x4.shared.b16 {%0,%1,%2,%3}, [%4];" \
        : "=r"((r)[0]), "=r"((r)[1]), "=r"((r)[2]), "=r"((r)[3]) : "r"(addr))

// ============================================================================
// one-time converts
// ============================================================================
__global__ void cvt_hl(const float* __restrict__ in, __nv_bfloat16* __restrict__ ho,
                       __nv_bfloat16* __restrict__ lo, int n) {
    int i = (blockIdx.x * blockDim.x + threadIdx.x) * 4;
    if (i >= n) return;
    float4 v = *(const float4*)&in[i];
    __align__(8) __nv_bfloat16 h[4], l[4];
    split2(v.x, h[0], l[0]);
    split2(v.y, h[1], l[1]);
    split2(v.z, h[2], l[2]);
    split2(v.w, h[3], l[3]);
    *(uint2*)&ho[i] = *(uint2*)h;
    *(uint2*)&lo[i] = *(uint2*)l;
}

// weights: w[K][N] fp32 -> th/tl[N][K] bf16 (transpose + split)
__global__ void transpose_hl(const float* __restrict__ w, __nv_bfloat16* __restrict__ th,
                             __nv_bfloat16* __restrict__ tl, int K, int N) {
    __shared__ float t[32][33];
    int n0 = blockIdx.x * 32, k0 = blockIdx.y * 32;
    int tx = threadIdx.x, ty = threadIdx.y;   // 32 x 8
#pragma unroll
    for (int i = 0; i < 32; i += 8)
        t[ty + i][tx] = w[(k0 + ty + i) * N + n0 + tx];
    __syncthreads();
#pragma unroll
    for (int i = 0; i < 32; i += 8) {
        float v = t[tx][ty + i];
        __nv_bfloat16 h, l;
        split2(v, h, l);
        th[(n0 + ty + i) * K + k0 + tx] = h;
        tl[(n0 + ty + i) * K + k0 + tx] = l;
    }
}

// ============================================================================
// mma.sync GEMM: C = A[M,K] @ Bt[N,K]^T. 128x128 tile, K-slab 32, 256 thr,
// 2 CTAs/SM. MODE 0: fp32 C out.
// MODE 2: fused QKV epilogue by n-segment:
//   n<4096        -> Q: RoPE + hi/lo split -> g_qh/g_ql
//   4096<=n<5120  -> K: RoPE + hi/lo split -> g_kh/g_kl
//   n>=5120       -> V: transpose + split  -> g_vth/g_vtl [hd][seq]
// ============================================================================
#define ABYTES 10240
#define STAGEB (4 * ABYTES)
#define GSMEM  (2 * STAGEB)

template<int MODE>
__global__ __launch_bounds__(256, 2) void gemm_mma(
    const __nv_bfloat16* __restrict__ Ah, const __nv_bfloat16* __restrict__ Al,
    const __nv_bfloat16* __restrict__ Bh, const __nv_bfloat16* __restrict__ Bl,
    float* __restrict__ C,
    const float* __restrict__ cosb, const float* __restrict__ sinb,
    int M, int N, int K)
{
    extern __shared__ char smem[];
    const int tid = threadIdx.x, lane = tid & 31, w = tid >> 5;
    const int g = lane >> 2, tg = lane & 3;
    const int t8 = lane >> 3, r8 = lane & 7;
    const int wm = (w & 1) * 64, wn = (w >> 1) * 32;
    const int m0 = blockIdx.y * 128, n0 = blockIdx.x * 128;
    const unsigned sbase = smem_u32(smem);

    auto load_slab = [&](int st, int kt) {
        unsigned s0 = sbase + st * STAGEB;
#pragma unroll
        for (int i = 0; i < 2; i++) {
            int idx = tid + i * 256;
            int row = idx >> 2, c = idx & 3;
            unsigned so = (unsigned)(row * 80 + c * 16);
            long ea = (long)(m0 + row) * K + kt + c * 8;
            long eb = (long)(n0 + row) * K + kt + c * 8;
            cp_async16(s0 + so, Ah + ea);
            cp_async16(s0 + ABYTES + so, Al + ea);
            cp_async16(s0 + 2 * ABYTES + so, Bh + eb);
            cp_async16(s0 + 3 * ABYTES + so, Bl + eb);
        }
        asm volatile("cp.async.commit_group;" ::: "memory");
    };

    float acc[4][4][4];
#pragma unroll
    for (int mt = 0; mt < 4; mt++)
#pragma unroll
        for (int nt = 0; nt < 4; nt++)
#pragma unroll
            for (int i = 0; i < 4; i++) acc[mt][nt][i] = 0.f;

    const unsigned aoff = (unsigned)((wm + (t8 & 1) * 8 + r8) * 80 + (t8 >> 1) * 16);
    const unsigned boff = (unsigned)((wn + (t8 >> 1) * 8 + r8) * 80 + (t8 & 1) * 16);

    const int T = K >> 5;
    load_slab(0, 0);
    load_slab(1, 32);

    for (int it = 0; it < T; it++) {
        asm volatile("cp.async.wait_group 1;" ::: "memory");
        __syncthreads();
        unsigned sb = sbase + (it & 1) * STAGEB;
        unsigned sAh = sb, sAl = sb + ABYTES, sBh = sb + 2 * ABYTES, sBl = sb + 3 * ABYTES;

#pragma unroll
        for (int ks = 0; ks < 2; ks++) {
            unsigned b_h[2][4], b_l[2][4], a_h[4][4];
#pragma unroll
            for (int ntp = 0; ntp < 2; ntp++) {
                LDSM4(b_h[ntp], sBh + boff + ntp * 1280 + ks * 32);
                LDSM4(b_l[ntp], sBl + boff + ntp * 1280 + ks * 32);
            }
#pragma unroll
            for (int mt = 0; mt < 4; mt++)
                LDSM4(a_h[mt], sAh + aoff + mt * 1280 + ks * 32);
#pragma unroll
            for (int mt = 0; mt < 4; mt++)
#pragma unroll
                for (int nt = 0; nt < 4; nt++)
                    MMA_BF16(acc[mt][nt], a_h[mt], b_h[nt >> 1][(nt & 1) * 2], b_h[nt >> 1][(nt & 1) * 2 + 1]);
#pragma unroll
            for (int mt = 0; mt < 4; mt++)
#pragma unroll
                for (int nt = 0; nt < 4; nt++)
                    MMA_BF16(acc[mt][nt], a_h[mt], b_l[nt >> 1][(nt & 1) * 2], b_l[nt >> 1][(nt & 1) * 2 + 1]);
#pragma unroll
            for (int mt = 0; mt < 4; mt++) {
                unsigned a_l[4];
                LDSM4(a_l, sAl + aoff + mt * 1280 + ks * 32);
#pragma unroll
                for (int nt = 0; nt < 4; nt++)
                    MMA_BF16(acc[mt][nt], a_l, b_h[nt >> 1][(nt & 1) * 2], b_h[nt >> 1][(nt & 1) * 2 + 1]);
            }
        }
        __syncthreads();
        if (it + 2 < T) load_slab(it & 1, (it + 2) * 32);
    }

    // ---- epilogue ----
#pragma unroll
    for (int mt = 0; mt < 4; mt++)
#pragma unroll
        for (int nt = 0; nt < 4; nt++) {
            int row = m0 + wm + mt * 16 + g;
            int col = n0 + wn + nt * 8 + tg * 2;
            if (MODE == 0) {
                float2 v0 = {acc[mt][nt][0], acc[mt][nt][1]};
                float2 v1 = {acc[mt][nt][2], acc[mt][nt][3]};
                *(float2*)&C[(long)row * N + col] = v0;
                *(float2*)&C[(long)(row + 8) * N + col] = v1;
            } else {
                if (n0 < NQD + NKVD) {
                    // Q or K segment: fused RoPE + hi/lo split
                    const bool isQ = (n0 < NQD);
                    const int cseg = isQ ? col : col - NQD;
                    const int strd = isQ ? NQD : NKVD;
                    __nv_bfloat16* Hh = isQ ? g_qh : g_kh;
                    __nv_bfloat16* Ll = isQ ? g_ql : g_kl;
                    const int pi = (cseg & 127) >> 1;
#pragma unroll
                    for (int half = 0; half < 2; half++) {
                        int rr = row + half * 8;
                        float cs = cosb[rr * 64 + pi], sn = sinb[rr * 64 + pi];
                        float e = acc[mt][nt][half * 2], o = acc[mt][nt][half * 2 + 1];
                        float re = e * cs - o * sn;
                        float ro = e * sn + o * cs;
                        __nv_bfloat162 hp, lp;
                        __nv_bfloat16 hh, ll;
                        split2(re, hh, ll); hp.x = hh; lp.x = ll;
                        split2(ro, hh, ll); hp.y = hh; lp.y = ll;
                        *(__nv_bfloat162*)&Hh[(long)rr * strd + cseg] = hp;
                        *(__nv_bfloat162*)&Ll[(long)rr * strd + cseg] = lp;
                    }
                } else {
                    // V segment: transpose + split -> [hd][seq]
                    const int cv = col - (NQD + NKVD);
#pragma unroll
                    for (int half = 0; half < 2; half++) {
                        int rr = row + half * 8;
#pragma unroll
                        for (int dc = 0; dc < 2; dc++) {
                            float v = acc[mt][nt][half * 2 + dc];
                            __nv_bfloat16 hh, ll;
                            split2(v, hh, ll);
                            long o = (long)(cv + dc) * S_LEN + rr;
                            g_vth[o] = hh;
                            g_vtl[o] = ll;
                        }
                    }
                }
            }
        }
}

// ============================================================================
// mma.sync flash attention: BQ=BK=64, 128 thr (4 warps, warp = 16 q-rows).
// ============================================================================
#define AQ_STB 272
#define AV_STB 144
#define SQ_OFF 0
#define SQL_OFF (64 * AQ_STB)
#define SK_OFF  (2 * 64 * AQ_STB)
#define SKL_OFF (3 * 64 * AQ_STB)
#define SV_OFF  (4 * 64 * AQ_STB)
#define SVL_OFF (SV_OFF + 128 * AV_STB)
#define ASMEM   (SVL_OFF + 128 * AV_STB)

__global__ __launch_bounds__(128) void attn_mma()
{
    extern __shared__ char smem[];
    const unsigned sb = smem_u32(smem);
    const int tid = threadIdx.x, lane = tid & 31, w = tid >> 5;
    const int g = lane >> 2, tg = lane & 3;
    const int t8 = lane >> 3, r8 = lane & 7;
    const int q0 = blockIdx.x * 64, h = blockIdx.y, kvh = h >> 2;

#pragma unroll
    for (int i = 0; i < 8; i++) {
        int idx = tid + i * 128;
        int row = idx >> 4, c = idx & 15;
        long gq = (long)(q0 + row) * NQD + h * HD + c * 8;
        unsigned so = (unsigned)(row * AQ_STB + c * 16);
        *(uint4*)(smem + SQ_OFF + so) = *(const uint4*)&g_qh[gq];
        *(uint4*)(smem + SQL_OFF + so) = *(const uint4*)&g_ql[gq];
    }

    const unsigned aoffQ = (unsigned)((w * 16 + (t8 & 1) * 8 + r8) * AQ_STB + (t8 >> 1) * 16);
    const unsigned boffK = (unsigned)(((t8 >> 1) * 8 + r8) * AQ_STB + (t8 & 1) * 16);
    const unsigned boffV = (unsigned)(((t8 >> 1) * 8 + r8) * AV_STB + (t8 & 1) * 16);

    float oacc[16][4];
#pragma unroll
    for (int nt = 0; nt < 16; nt++)
#pragma unroll
        for (int i = 0; i < 4; i++) oacc[nt][i] = 0.f;
    float m_lo = -1e30f, m_hi = -1e30f, l_lo = 0.f, l_hi = 0.f;

    const int qg_lo = q0 + w * 16 + g;
    const int qg_hi = qg_lo + 8;
    int lo = q0 - (WINDOW - 1);
    const int kt_lo = lo > 0 ? (lo >> 6) : 0;
    const int kt_hi = blockIdx.x;
    const float scale = 0.08838834764831845f;

    __syncthreads();

    for (int kt = kt_lo; kt <= kt_hi; kt++) {
        const int k0 = kt * 64;
#pragma unroll
        for (int i = 0; i < 8; i++) {
            int idx = tid + i * 128;
            int row = idx >> 4, c = idx & 15;
            long gk = (long)(k0 + row) * NKVD + kvh * HD + c * 8;
            unsigned so = (unsigned)(row * AQ_STB + c * 16);
            *(uint4*)(smem + SK_OFF + so) = *(const uint4*)&g_kh[gk];
            *(uint4*)(smem + SKL_OFF + so) = *(const uint4*)&g_kl[gk];
            int vrow = idx >> 3, vc = idx & 7;
            long gv = (long)(kvh * HD + vrow) * S_LEN + k0 + vc * 8;
            unsigned vo = (unsigned)(vrow * AV_STB + vc * 16);
            *(uint4*)(smem + SV_OFF + vo) = *(const uint4*)&g_vth[gv];
            *(uint4*)(smem + SVL_OFF + vo) = *(const uint4*)&g_vtl[gv];
        }
        __syncthreads();

        float sacc[8][4];
#pragma unroll
        for (int nt = 0; nt < 8; nt++)
#pragma unroll
            for (int i = 0; i < 4; i++) sacc[nt][i] = 0.f;

#pragma unroll
        for (int ks = 0; ks < 8; ks++) {
            unsigned qa[4], qla[4], kb[4][4], kbl[4][4];
            LDSM4(qa, sb + SQ_OFF + aoffQ + ks * 32);
            LDSM4(qla, sb + SQL_OFF + aoffQ + ks * 32);
#pragma unroll
            for (int ntp = 0; ntp < 4; ntp++) {
                LDSM4(kb[ntp], sb + SK_OFF + boffK + ntp * (16 * AQ_STB) + ks * 32);
                LDSM4(kbl[ntp], sb + SKL_OFF + boffK + ntp * (16 * AQ_STB) + ks * 32);
            }
#pragma unroll
            for (int nt = 0; nt < 8; nt++)
                MMA_BF16(sacc[nt], qa, kb[nt >> 1][(nt & 1) * 2], kb[nt >> 1][(nt & 1) * 2 + 1]);
#pragma unroll
            for (int nt = 0; nt < 8; nt++)
                MMA_BF16(sacc[nt], qla, kb[nt >> 1][(nt & 1) * 2], kb[nt >> 1][(nt & 1) * 2 + 1]);
#pragma unroll
            for (int nt = 0; nt < 8; nt++)
                MMA_BF16(sacc[nt], qa, kbl[nt >> 1][(nt & 1) * 2], kbl[nt >> 1][(nt & 1) * 2 + 1]);
        }

#pragma unroll
        for (int nt = 0; nt < 8; nt++) {
            int kg0 = k0 + nt * 8 + tg * 2, kg1 = kg0 + 1;
            int d00 = qg_lo - kg0, d01 = qg_lo - kg1;
            int d10 = qg_hi - kg0, d11 = qg_hi - kg1;
            sacc[nt][0] = (d00 >= 0 && d00 < WINDOW) ? sacc[nt][0] * scale : -1e30f;
            sacc[nt][1] = (d01 >= 0 && d01 < WINDOW) ? sacc[nt][1] * scale : -1e30f;
            sacc[nt][2] = (d10 >= 0 && d10 < WINDOW) ? sacc[nt][2] * scale : -1e30f;
            sacc[nt][3] = (d11 >= 0 && d11 < WINDOW) ? sacc[nt][3] * scale : -1e30f;
        }

        float mx0 = -1e30f, mx1 = -1e30f;
#pragma unroll
        for (int nt = 0; nt < 8; nt++) {
            mx0 = fmaxf(mx0, fmaxf(sacc[nt][0], sacc[nt][1]));
            mx1 = fmaxf(mx1, fmaxf(sacc[nt][2], sacc[nt][3]));
        }
        mx0 = fmaxf(mx0, __shfl_xor_sync(0xffffffffu, mx0, 1));
        mx0 = fmaxf(mx0, __shfl_xor_sync(0xffffffffu, mx0, 2));
        mx1 = fmaxf(mx1, __shfl_xor_sync(0xffffffffu, mx1, 1));
        mx1 = fmaxf(mx1, __shfl_xor_sync(0xffffffffu, mx1, 2));
        float mn0 = fmaxf(m_lo, mx0), mn1 = fmaxf(m_hi, mx1);
        float al0 = __expf(m_lo - mn0), al1 = __expf(m_hi - mn1);
        float ps0 = 0.f, ps1 = 0.f;
#pragma unroll
        for (int nt = 0; nt < 8; nt++) {
            float p0 = (sacc[nt][0] > -1e29f) ? __expf(sacc[nt][0] - mn0) : 0.f;
            float p1 = (sacc[nt][1] > -1e29f) ? __expf(sacc[nt][1] - mn0) : 0.f;
            float p2 = (sacc[nt][2] > -1e29f) ? __expf(sacc[nt][2] - mn1) : 0.f;
            float p3 = (sacc[nt][3] > -1e29f) ? __expf(sacc[nt][3] - mn1) : 0.f;
            sacc[nt][0] = p0; sacc[nt][1] = p1; sacc[nt][2] = p2; sacc[nt][3] = p3;
            ps0 += p0 + p1;
            ps1 += p2 + p3;
        }
        ps0 += __shfl_xor_sync(0xffffffffu, ps0, 1);
        ps0 += __shfl_xor_sync(0xffffffffu, ps0, 2);
        ps1 += __shfl_xor_sync(0xffffffffu, ps1, 1);
        ps1 += __shfl_xor_sync(0xffffffffu, ps1, 2);
        l_lo = l_lo * al0 + ps0; m_lo = mn0;
        l_hi = l_hi * al1 + ps1; m_hi = mn1;
#pragma unroll
        for (int nt = 0; nt < 16; nt++) {
            oacc[nt][0] *= al0; oacc[nt][1] *= al0;
            oacc[nt][2] *= al1; oacc[nt][3] *= al1;
        }

#pragma unroll
        for (int kv = 0; kv < 4; kv++) {
            unsigned pa_h[4], pa_l[4];
            {
                float p00 = sacc[2 * kv][0], p01 = sacc[2 * kv][1];
                float p10 = sacc[2 * kv][2], p11 = sacc[2 * kv][3];
                float p20 = sacc[2 * kv + 1][0], p21 = sacc[2 * kv + 1][1];
                float p30 = sacc[2 * kv + 1][2], p31 = sacc[2 * kv + 1][3];
                __nv_bfloat162 h0, h1, h2, h3, l0v, l1v, l2v, l3v;
                __nv_bfloat16 hh, ll;
                split2(p00, hh, ll); h0.x = hh; l0v.x = ll;
                split2(p01, hh, ll); h0.y = hh; l0v.y = ll;
                split2(p10, hh, ll); h1.x = hh; l1v.x = ll;
                split2(p11, hh, ll); h1.y = hh; l1v.y = ll;
                split2(p20, hh, ll); h2.x = hh; l2v.x = ll;
                split2(p21, hh, ll); h2.y = hh; l2v.y = ll;
                split2(p30, hh, ll); h3.x = hh; l3v.x = ll;
                split2(p31, hh, ll); h3.y = hh; l3v.y = ll;
                pa_h[0] = *(unsigned*)&h0; pa_h[1] = *(unsigned*)&h1;
                pa_h[2] = *(unsigned*)&h2; pa_h[3] = *(unsigned*)&h3;
                pa_l[0] = *(unsigned*)&l0v; pa_l[1] = *(unsigned*)&l1v;
                pa_l[2] = *(unsigned*)&l2v; pa_l[3] = *(unsigned*)&l3v;
            }
#pragma unroll
            for (int half = 0; half < 2; half++) {
                unsigned vbh[4][4], vbl[4][4];
#pragma unroll
                for (int ntp = 0; ntp < 4; ntp++) {
                    LDSM4(vbh[ntp], sb + SV_OFF + boffV + (half * 4 + ntp) * (16 * AV_STB) + kv * 32);
                    LDSM4(vbl[ntp], sb + SVL_OFF + boffV + (half * 4 + ntp) * (16 * AV_STB) + kv * 32);
                }
#pragma unroll
                for (int nt = 0; nt < 8; nt++)
                    MMA_BF16(oacc[half * 8 + nt], pa_h, vbh[nt >> 1][(nt & 1) * 2], vbh[nt >> 1][(nt & 1) * 2 + 1]);
#pragma unroll
                for (int nt = 0; nt < 8; nt++)
                    MMA_BF16(oacc[half * 8 + nt], pa_l, vbh[nt >> 1][(nt & 1) * 2], vbh[nt >> 1][(nt & 1) * 2 + 1]);
#pragma unroll
                for (int nt = 0; nt < 8; nt++)
                    MMA_BF16(oacc[half * 8 + nt], pa_h, vbl[nt >> 1][(nt & 1) * 2], vbl[nt >> 1][(nt & 1) * 2 + 1]);
            }
        }
        __syncthreads();
    }

    float inv0 = 1.f / l_lo, inv1 = 1.f / l_hi;
#pragma unroll
    for (int nt = 0; nt < 16; nt++) {
        int col = h * HD + nt * 8 + tg * 2;
        float v0 = oacc[nt][0] * inv0, v1 = oacc[nt][1] * inv0;
        float v2 = oacc[nt][2] * inv1, v3 = oacc[nt][3] * inv1;
        __nv_bfloat162 hp, lp;
        __nv_bfloat16 hh, ll;
        split2(v0, hh, ll); hp.x = hh; lp.x = ll;
        split2(v1, hh, ll); hp.y = hh; lp.y = ll;
        *(__nv_bfloat162*)&g_ath[(long)qg_lo * NQD + col] = hp;
        *(__nv_bfloat162*)&g_atl[(long)qg_lo * NQD + col] = lp;
        split2(v2, hh, ll); hp.x = hh; lp.x = ll;
        split2(v3, hh, ll); hp.y = hh; lp.y = ll;
        *(__nv_bfloat162*)&g_ath[(long)qg_hi * NQD + col] = hp;
        *(__nv_bfloat162*)&g_atl[(long)qg_hi * NQD + col] = lp;
    }
}

// ============================================================================
extern "C" void kernel_launch(void* const* d_in, const int* in_sizes, int n_in,
                              void* d_out, int out_size)
{
    const float* x   = (const float*)d_in[0];
    const float* fc  = (const float*)d_in[1];
    const float* fs  = (const float*)d_in[2];
    // d_in[3]: mask — unused (causal + sliding window computed analytically)
    const float* w_q = (const float*)d_in[4];
    const float* w_k = (const float*)d_in[5];
    const float* w_v = (const float*)d_in[6];
    const float* w_o = (const float*)d_in[7];
    float* out = (float*)d_out;

    __nv_bfloat16 *xh, *xl, *ath, *atl, *wch, *wcl, *woh, *wol;
    cudaGetSymbolAddress((void**)&xh, g_xh);   cudaGetSymbolAddress((void**)&xl, g_xl);
    cudaGetSymbolAddress((void**)&ath, g_ath); cudaGetSymbolAddress((void**)&atl, g_atl);
    cudaGetSymbolAddress((void**)&wch, g_wch); cudaGetSymbolAddress((void**)&wcl, g_wcl);
    cudaGetSymbolAddress((void**)&woh, g_woh); cudaGetSymbolAddress((void**)&wol, g_wol);

    cudaFuncSetAttribute(gemm_mma<0>, cudaFuncAttributeMaxDynamicSharedMemorySize, GSMEM);
    cudaFuncSetAttribute(gemm_mma<2>, cudaFuncAttributeMaxDynamicSharedMemorySize, GSMEM);
    cudaFuncSetAttribute(attn_mma, cudaFuncAttributeMaxDynamicSharedMemorySize, ASMEM);

    // one-time operand prep (wq/wk/wv transposed into one concatenated buffer)
    cvt_hl<<<(S_LEN * D_MODEL / 4 + 255) / 256, 256>>>(x, xh, xl, S_LEN * D_MODEL);
    transpose_hl<<<dim3(NQD / 32, D_MODEL / 32), dim3(32, 8)>>>(
        w_q, wch, wcl, D_MODEL, NQD);
    transpose_hl<<<dim3(NKVD / 32, D_MODEL / 32), dim3(32, 8)>>>(
        w_k, wch + (long)NQD * D_MODEL, wcl + (long)NQD * D_MODEL, D_MODEL, NKVD);
    transpose_hl<<<dim3(NKVD / 32, D_MODEL / 32), dim3(32, 8)>>>(
        w_v, wch + (long)(NQD + NKVD) * D_MODEL, wcl + (long)(NQD + NKVD) * D_MODEL, D_MODEL, NKVD);
    transpose_hl<<<dim3(D_MODEL / 32, NQD / 32), dim3(32, 8)>>>(w_o, woh, wol, NQD, D_MODEL);

    // fused QKV projection: one launch, per-segment epilogue (rope / rope / v-transpose)
    gemm_mma<2><<<dim3(NCAT / 128, S_LEN / 128), 256, GSMEM>>>(
        xh, xl, wch, wcl, nullptr, fc, fs, S_LEN, NCAT, D_MODEL);

    // attention (reads g_qh/ql, g_kh/kl, g_vth/vtl; writes g_ath/g_atl)
    attn_mma<<<dim3(S_LEN / 64, NQ), 128, ASMEM>>>();

    // output projection
    gemm_mma<0><<<dim3(D_MODEL / 128, S_LEN / 128), 256, GSMEM>>>(
        ath, atl, woh, wol, out, nullptr, nullptr, S_LEN, D_MODEL, NQD);
}

// round 13
// speedup vs baseline: 5.6591x; 1.1297x over previous
#include <cuda_runtime.h>
#include <cuda_bf16.h>
#include <cuda_fp16.h>
#include <cstdint>

#define S_LEN   2048
#define D_MODEL 4096
#define NQ      32
#define NKV     8
#define HD      128
#define WINDOW  1024
#define NQD     (NQ*HD)    // 4096
#define NKVD    (NKV*HD)   // 1024
#define NCAT    (NQD + 2*NKVD)  // 6144 fused QKV output width

// ---- operands ----
__device__ __nv_bfloat16 g_xh[S_LEN * D_MODEL],  g_xl[S_LEN * D_MODEL];
__device__ __half        g_ath[S_LEN * NQD],     g_atl[S_LEN * NQD];   // attn out fp16 hi/lo
__device__ __nv_bfloat16 g_qh[S_LEN * NQD],      g_ql[S_LEN * NQD];
__device__ __nv_bfloat16 g_kh[S_LEN * NKVD],     g_kl[S_LEN * NKVD];
__device__ __half        g_vt[NKVD * S_LEN];                           // V fp16 [kvh*hd][seq]
__device__ __nv_bfloat16 g_wch[NCAT * D_MODEL],  g_wcl[NCAT * D_MODEL]; // [wq;wk;wv] [N][K]
__device__ __half        g_woh[D_MODEL * NQD];                         // w_o fp16 single [N][K]

// ============================================================================
// helpers
// ============================================================================
__device__ __forceinline__ unsigned smem_u32(const void* p) {
    unsigned a;
    asm("{ .reg .u64 t; cvta.to.shared.u64 t, %1; cvt.u32.u64 %0, t; }" : "=r"(a) : "l"(p));
    return a;
}
__device__ __forceinline__ void cp_async16(unsigned s, const void* g) {
    asm volatile("cp.async.cg.shared.global [%0], [%1], 16;" :: "r"(s), "l"(g) : "memory");
}
__device__ __forceinline__ void split2(float v, __nv_bfloat16& h, __nv_bfloat16& l) {
    h = __float2bfloat16_rn(v);
    l = __float2bfloat16_rn(v - __bfloat162float(h));
}
__device__ __forceinline__ void split2h(float v, __half& h, __half& l) {
    h = __float2half_rn(v);
    l = __float2half_rn(v - __half2float(h));
}

#define MMA_BF16(acc, a, b0v, b1v)                                            \
    asm volatile(                                                             \
        "mma.sync.aligned.m16n8k16.row.col.f32.bf16.bf16.f32 "                \
        "{%0,%1,%2,%3},{%4,%5,%6,%7},{%8,%9},{%0,%1,%2,%3};"                  \
        : "+f"(acc[0]), "+f"(acc[1]), "+f"(acc[2]), "+f"(acc[3])              \
        : "r"(a[0]), "r"(a[1]), "r"(a[2]), "r"(a[3]), "r"(b0v), "r"(b1v))

#define MMA_F16(acc, a, b0v, b1v)                                             \
    asm volatile(                                                             \
        "mma.sync.aligned.m16n8k16.row.col.f32.f16.f16.f32 "                  \
        "{%0,%1,%2,%3},{%4,%5,%6,%7},{%8,%9},{%0,%1,%2,%3};"                  \
        : "+f"(acc[0]), "+f"(acc[1]), "+f"(acc[2]), "+f"(acc[3])              \
        : "r"(a[0]), "r"(a[1]), "r"(a[2]), "r"(a[3]), "r"(b0v), "r"(b1v))

#define LDSM4(r, addr)                                                        \
    asm volatile("ldmatrix.sync.aligned.m8n8.x4.shared.b16 {%0,%1,%2,%3}, [%4];" \
        : "=r"((r)[0]), "=r"((r)[1]), "=r"((r)[2]), "=r"((r)[3]) : "r"(addr))

// ============================================================================
// one-time converts
// ============================================================================
__global__ void cvt_hl(const float* __restrict__ in, __nv_bfloat16* __restrict__ ho,
                       __nv_bfloat16* __restrict__ lo, int n) {
    int i = (blockIdx.x * blockDim.x + threadIdx.x) * 4;
    if (i >= n) return;
    float4 v = *(const float4*)&in[i];
    __align__(8) __nv_bfloat16 h[4], l[4];
    split2(v.x, h[0], l[0]);
    split2(v.y, h[1], l[1]);
    split2(v.z, h[2], l[2]);
    split2(v.w, h[3], l[3]);
    *(uint2*)&ho[i] = *(uint2*)h;
    *(uint2*)&lo[i] = *(uint2*)l;
}

// weights: w[K][N] fp32 -> th/tl[N][K] bf16 (transpose + split)
__global__ void transpose_hl(const float* __restrict__ w, __nv_bfloat16* __restrict__ th,
                             __nv_bfloat16* __restrict__ tl, int K, int N) {
    __shared__ float t[32][33];
    int n0 = blockIdx.x * 32, k0 = blockIdx.y * 32;
    int tx = threadIdx.x, ty = threadIdx.y;   // 32 x 8
#pragma unroll
    for (int i = 0; i < 32; i += 8)
        t[ty + i][tx] = w[(k0 + ty + i) * N + n0 + tx];
    __syncthreads();
#pragma unroll
    for (int i = 0; i < 32; i += 8) {
        float v = t[tx][ty + i];
        __nv_bfloat16 h, l;
        split2(v, h, l);
        th[(n0 + ty + i) * K + k0 + tx] = h;
        tl[(n0 + ty + i) * K + k0 + tx] = l;
    }
}

// w_o: w[K][N] fp32 -> th[N][K] fp16 single (transpose)
__global__ void transpose_h(const float* __restrict__ w, __half* __restrict__ th,
                            int K, int N) {
    __shared__ float t[32][33];
    int n0 = blockIdx.x * 32, k0 = blockIdx.y * 32;
    int tx = threadIdx.x, ty = threadIdx.y;
#pragma unroll
    for (int i = 0; i < 32; i += 8)
        t[ty + i][tx] = w[(k0 + ty + i) * N + n0 + tx];
    __syncthreads();
#pragma unroll
    for (int i = 0; i < 32; i += 8)
        th[(n0 + ty + i) * K + k0 + tx] = __float2half_rn(t[tx][ty + i]);
}

// ============================================================================
// QKV GEMM (bf16, 3-pass): C = A[M,K] @ Bt[N,K]^T. 128x128 tile, K-slab 32,
// 256 thr, 2 CTAs/SM. Fused epilogue by n-segment:
//   n<4096        -> Q: RoPE + hi/lo bf16 split -> g_qh/g_ql
//   4096<=n<5120  -> K: RoPE + hi/lo bf16 split -> g_kh/g_kl
//   n>=5120       -> V: transpose + fp16        -> g_vt [hd][seq]
// ============================================================================
#define ABYTES 10240
#define STAGEB (4 * ABYTES)
#define GSMEM  (2 * STAGEB)

__global__ __launch_bounds__(256, 2) void gemm_qkv(
    const __nv_bfloat16* __restrict__ Ah, const __nv_bfloat16* __restrict__ Al,
    const __nv_bfloat16* __restrict__ Bh, const __nv_bfloat16* __restrict__ Bl,
    const float* __restrict__ cosb, const float* __restrict__ sinb,
    int M, int N, int K)
{
    extern __shared__ char smem[];
    const int tid = threadIdx.x, lane = tid & 31, w = tid >> 5;
    const int g = lane >> 2, tg = lane & 3;
    const int t8 = lane >> 3, r8 = lane & 7;
    const int wm = (w & 1) * 64, wn = (w >> 1) * 32;
    const int m0 = blockIdx.y * 128, n0 = blockIdx.x * 128;
    const unsigned sbase = smem_u32(smem);

    auto load_slab = [&](int st, int kt) {
        unsigned s0 = sbase + st * STAGEB;
#pragma unroll
        for (int i = 0; i < 2; i++) {
            int idx = tid + i * 256;
            int row = idx >> 2, c = idx & 3;
            unsigned so = (unsigned)(row * 80 + c * 16);
            long ea = (long)(m0 + row) * K + kt + c * 8;
            long eb = (long)(n0 + row) * K + kt + c * 8;
            cp_async16(s0 + so, Ah + ea);
            cp_async16(s0 + ABYTES + so, Al + ea);
            cp_async16(s0 + 2 * ABYTES + so, Bh + eb);
            cp_async16(s0 + 3 * ABYTES + so, Bl + eb);
        }
        asm volatile("cp.async.commit_group;" ::: "memory");
    };

    float acc[4][4][4];
#pragma unroll
    for (int mt = 0; mt < 4; mt++)
#pragma unroll
        for (int nt = 0; nt < 4; nt++)
#pragma unroll
            for (int i = 0; i < 4; i++) acc[mt][nt][i] = 0.f;

    const unsigned aoff = (unsigned)((wm + (t8 & 1) * 8 + r8) * 80 + (t8 >> 1) * 16);
    const unsigned boff = (unsigned)((wn + (t8 >> 1) * 8 + r8) * 80 + (t8 & 1) * 16);

    const int T = K >> 5;
    load_slab(0, 0);
    load_slab(1, 32);

    for (int it = 0; it < T; it++) {
        asm volatile("cp.async.wait_group 1;" ::: "memory");
        __syncthreads();
        unsigned sb = sbase + (it & 1) * STAGEB;
        unsigned sAh = sb, sAl = sb + ABYTES, sBh = sb + 2 * ABYTES, sBl = sb + 3 * ABYTES;

#pragma unroll
        for (int ks = 0; ks < 2; ks++) {
            unsigned b_h[2][4], b_l[2][4], a_h[4][4];
#pragma unroll
            for (int ntp = 0; ntp < 2; ntp++) {
                LDSM4(b_h[ntp], sBh + boff + ntp * 1280 + ks * 32);
                LDSM4(b_l[ntp], sBl + boff + ntp * 1280 + ks * 32);
            }
#pragma unroll
            for (int mt = 0; mt < 4; mt++)
                LDSM4(a_h[mt], sAh + aoff + mt * 1280 + ks * 32);
#pragma unroll
            for (int mt = 0; mt < 4; mt++)
#pragma unroll
                for (int nt = 0; nt < 4; nt++)
                    MMA_BF16(acc[mt][nt], a_h[mt], b_h[nt >> 1][(nt & 1) * 2], b_h[nt >> 1][(nt & 1) * 2 + 1]);
#pragma unroll
            for (int mt = 0; mt < 4; mt++)
#pragma unroll
                for (int nt = 0; nt < 4; nt++)
                    MMA_BF16(acc[mt][nt], a_h[mt], b_l[nt >> 1][(nt & 1) * 2], b_l[nt >> 1][(nt & 1) * 2 + 1]);
#pragma unroll
            for (int mt = 0; mt < 4; mt++) {
                unsigned a_l[4];
                LDSM4(a_l, sAl + aoff + mt * 1280 + ks * 32);
#pragma unroll
                for (int nt = 0; nt < 4; nt++)
                    MMA_BF16(acc[mt][nt], a_l, b_h[nt >> 1][(nt & 1) * 2], b_h[nt >> 1][(nt & 1) * 2 + 1]);
            }
        }
        __syncthreads();
        if (it + 2 < T) load_slab(it & 1, (it + 2) * 32);
    }

    // ---- fused epilogue ----
#pragma unroll
    for (int mt = 0; mt < 4; mt++)
#pragma unroll
        for (int nt = 0; nt < 4; nt++) {
            int row = m0 + wm + mt * 16 + g;
            int col = n0 + wn + nt * 8 + tg * 2;
            if (n0 < NQD + NKVD) {
                // Q or K segment: fused RoPE + bf16 hi/lo split
                const bool isQ = (n0 < NQD);
                const int cseg = isQ ? col : col - NQD;
                const int strd = isQ ? NQD : NKVD;
                __nv_bfloat16* Hh = isQ ? g_qh : g_kh;
                __nv_bfloat16* Ll = isQ ? g_ql : g_kl;
                const int pi = (cseg & 127) >> 1;
#pragma unroll
                for (int half = 0; half < 2; half++) {
                    int rr = row + half * 8;
                    float cs = cosb[rr * 64 + pi], sn = sinb[rr * 64 + pi];
                    float e = acc[mt][nt][half * 2], o = acc[mt][nt][half * 2 + 1];
                    float re = e * cs - o * sn;
                    float ro = e * sn + o * cs;
                    __nv_bfloat162 hp, lp;
                    __nv_bfloat16 hh, ll;
                    split2(re, hh, ll); hp.x = hh; lp.x = ll;
                    split2(ro, hh, ll); hp.y = hh; lp.y = ll;
                    *(__nv_bfloat162*)&Hh[(long)rr * strd + cseg] = hp;
                    *(__nv_bfloat162*)&Ll[(long)rr * strd + cseg] = lp;
                }
            } else {
                // V segment: transpose + single fp16 -> [hd][seq]
                const int cv = col - (NQD + NKVD);
#pragma unroll
                for (int half = 0; half < 2; half++) {
                    int rr = row + half * 8;
#pragma unroll
                    for (int dc = 0; dc < 2; dc++) {
                        float v = acc[mt][nt][half * 2 + dc];
                        g_vt[(long)(cv + dc) * S_LEN + rr] = __float2half_rn(v);
                    }
                }
            }
        }
}

// ============================================================================
// O-projection GEMM (fp16, 2-pass: Ah*Bh + Al*Bh; B single fp16).
// 3 smem arrays per stage -> less traffic. fp32 out.
// ============================================================================
#define OSTAGE (3 * ABYTES)
#define OSMEM  (2 * OSTAGE)

__global__ __launch_bounds__(256, 2) void gemm_o(
    const __half* __restrict__ Ah, const __half* __restrict__ Al,
    const __half* __restrict__ Bh,
    float* __restrict__ C, int M, int N, int K)
{
    extern __shared__ char smem[];
    const int tid = threadIdx.x, lane = tid & 31, w = tid >> 5;
    const int g = lane >> 2, tg = lane & 3;
    const int t8 = lane >> 3, r8 = lane & 7;
    const int wm = (w & 1) * 64, wn = (w >> 1) * 32;
    const int m0 = blockIdx.y * 128, n0 = blockIdx.x * 128;
    const unsigned sbase = smem_u32(smem);

    auto load_slab = [&](int st, int kt) {
        unsigned s0 = sbase + st * OSTAGE;
#pragma unroll
        for (int i = 0; i < 2; i++) {
            int idx = tid + i * 256;
            int row = idx >> 2, c = idx & 3;
            unsigned so = (unsigned)(row * 80 + c * 16);
            long ea = (long)(m0 + row) * K + kt + c * 8;
            long eb = (long)(n0 + row) * K + kt + c * 8;
            cp_async16(s0 + so, Ah + ea);
            cp_async16(s0 + ABYTES + so, Al + ea);
            cp_async16(s0 + 2 * ABYTES + so, Bh + eb);
        }
        asm volatile("cp.async.commit_group;" ::: "memory");
    };

    float acc[4][4][4];
#pragma unroll
    for (int mt = 0; mt < 4; mt++)
#pragma unroll
        for (int nt = 0; nt < 4; nt++)
#pragma unroll
            for (int i = 0; i < 4; i++) acc[mt][nt][i] = 0.f;

    const unsigned aoff = (unsigned)((wm + (t8 & 1) * 8 + r8) * 80 + (t8 >> 1) * 16);
    const unsigned boff = (unsigned)((wn + (t8 >> 1) * 8 + r8) * 80 + (t8 & 1) * 16);

    const int T = K >> 5;
    load_slab(0, 0);
    load_slab(1, 32);

    for (int it = 0; it < T; it++) {
        asm volatile("cp.async.wait_group 1;" ::: "memory");
        __syncthreads();
        unsigned sb = sbase + (it & 1) * OSTAGE;
        unsigned sAh = sb, sAl = sb + ABYTES, sBh = sb + 2 * ABYTES;

#pragma unroll
        for (int ks = 0; ks < 2; ks++) {
            unsigned b_h[2][4], a_h[4][4];
#pragma unroll
            for (int ntp = 0; ntp < 2; ntp++)
                LDSM4(b_h[ntp], sBh + boff + ntp * 1280 + ks * 32);
#pragma unroll
            for (int mt = 0; mt < 4; mt++)
                LDSM4(a_h[mt], sAh + aoff + mt * 1280 + ks * 32);
            // pass 1: Ah * Bh
#pragma unroll
            for (int mt = 0; mt < 4; mt++)
#pragma unroll
                for (int nt = 0; nt < 4; nt++)
                    MMA_F16(acc[mt][nt], a_h[mt], b_h[nt >> 1][(nt & 1) * 2], b_h[nt >> 1][(nt & 1) * 2 + 1]);
            // pass 2: Al * Bh (reload per-mt)
#pragma unroll
            for (int mt = 0; mt < 4; mt++) {
                unsigned a_l[4];
                LDSM4(a_l, sAl + aoff + mt * 1280 + ks * 32);
#pragma unroll
                for (int nt = 0; nt < 4; nt++)
                    MMA_F16(acc[mt][nt], a_l, b_h[nt >> 1][(nt & 1) * 2], b_h[nt >> 1][(nt & 1) * 2 + 1]);
            }
        }
        __syncthreads();
        if (it + 2 < T) load_slab(it & 1, (it + 2) * 32);
    }

#pragma unroll
    for (int mt = 0; mt < 4; mt++)
#pragma unroll
        for (int nt = 0; nt < 4; nt++) {
            int row = m0 + wm + mt * 16 + g;
            int col = n0 + wn + nt * 8 + tg * 2;
            float2 v0 = {acc[mt][nt][0], acc[mt][nt][1]};
            float2 v1 = {acc[mt][nt][2], acc[mt][nt][3]};
            *(float2*)&C[(long)row * N + col] = v0;
            *(float2*)&C[(long)(row + 8) * N + col] = v1;
        }
}

// ============================================================================
// flash attention: QK bf16 3-pass; PV fp16 2-pass (P split, V single fp16).
// BQ=BK=64, 128 thr (4 warps). Heavy-first scheduling (reversed qt).
// ============================================================================
#define AQ_STB 272
#define AV_STB 144
#define SQ_OFF 0
#define SQL_OFF (64 * AQ_STB)
#define SK_OFF  (2 * 64 * AQ_STB)
#define SKL_OFF (3 * 64 * AQ_STB)
#define SV_OFF  (4 * 64 * AQ_STB)
#define ASMEM   (SV_OFF + 128 * AV_STB)   // 88064

__global__ __launch_bounds__(128) void attn_mma()
{
    extern __shared__ char smem[];
    const unsigned sb = smem_u32(smem);
    const int tid = threadIdx.x, lane = tid & 31, w = tid >> 5;
    const int g = lane >> 2, tg = lane & 3;
    const int t8 = lane >> 3, r8 = lane & 7;
    const int qt = (int)gridDim.x - 1 - (int)blockIdx.x;   // heavy tiles first
    const int q0 = qt * 64, h = blockIdx.y, kvh = h >> 2;

#pragma unroll
    for (int i = 0; i < 8; i++) {
        int idx = tid + i * 128;
        int row = idx >> 4, c = idx & 15;
        long gq = (long)(q0 + row) * NQD + h * HD + c * 8;
        unsigned so = (unsigned)(row * AQ_STB + c * 16);
        *(uint4*)(smem + SQ_OFF + so) = *(const uint4*)&g_qh[gq];
        *(uint4*)(smem + SQL_OFF + so) = *(const uint4*)&g_ql[gq];
    }

    const unsigned aoffQ = (unsigned)((w * 16 + (t8 & 1) * 8 + r8) * AQ_STB + (t8 >> 1) * 16);
    const unsigned boffK = (unsigned)(((t8 >> 1) * 8 + r8) * AQ_STB + (t8 & 1) * 16);
    const unsigned boffV = (unsigned)(((t8 >> 1) * 8 + r8) * AV_STB + (t8 & 1) * 16);

    float oacc[16][4];
#pragma unroll
    for (int nt = 0; nt < 16; nt++)
#pragma unroll
        for (int i = 0; i < 4; i++) oacc[nt][i] = 0.f;
    float m_lo = -1e30f, m_hi = -1e30f, l_lo = 0.f, l_hi = 0.f;

    const int qg_lo = q0 + w * 16 + g;
    const int qg_hi = qg_lo + 8;
    int lo = q0 - (WINDOW - 1);
    const int kt_lo = lo > 0 ? (lo >> 6) : 0;
    const int kt_hi = qt;
    const float scale = 0.08838834764831845f;

    __syncthreads();

    for (int kt = kt_lo; kt <= kt_hi; kt++) {
        const int k0 = kt * 64;
        // load K (64x128 bf16 hi/lo) and V (128x64 fp16)
#pragma unroll
        for (int i = 0; i < 8; i++) {
            int idx = tid + i * 128;
            int row = idx >> 4, c = idx & 15;
            long gk = (long)(k0 + row) * NKVD + kvh * HD + c * 8;
            unsigned so = (unsigned)(row * AQ_STB + c * 16);
            *(uint4*)(smem + SK_OFF + so) = *(const uint4*)&g_kh[gk];
            *(uint4*)(smem + SKL_OFF + so) = *(const uint4*)&g_kl[gk];
            int vrow = idx >> 3, vc = idx & 7;
            long gv = (long)(kvh * HD + vrow) * S_LEN + k0 + vc * 8;
            unsigned vo = (unsigned)(vrow * AV_STB + vc * 16);
            *(uint4*)(smem + SV_OFF + vo) = *(const uint4*)&g_vt[gv];
        }
        __syncthreads();

        float sacc[8][4];
#pragma unroll
        for (int nt = 0; nt < 8; nt++)
#pragma unroll
            for (int i = 0; i < 4; i++) sacc[nt][i] = 0.f;

#pragma unroll
        for (int ks = 0; ks < 8; ks++) {
            unsigned qa[4], qla[4], kb[4][4], kbl[4][4];
            LDSM4(qa, sb + SQ_OFF + aoffQ + ks * 32);
            LDSM4(qla, sb + SQL_OFF + aoffQ + ks * 32);
#pragma unroll
            for (int ntp = 0; ntp < 4; ntp++) {
                LDSM4(kb[ntp], sb + SK_OFF + boffK + ntp * (16 * AQ_STB) + ks * 32);
                LDSM4(kbl[ntp], sb + SKL_OFF + boffK + ntp * (16 * AQ_STB) + ks * 32);
            }
#pragma unroll
            for (int nt = 0; nt < 8; nt++)
                MMA_BF16(sacc[nt], qa, kb[nt >> 1][(nt & 1) * 2], kb[nt >> 1][(nt & 1) * 2 + 1]);
#pragma unroll
            for (int nt = 0; nt < 8; nt++)
                MMA_BF16(sacc[nt], qla, kb[nt >> 1][(nt & 1) * 2], kb[nt >> 1][(nt & 1) * 2 + 1]);
#pragma unroll
            for (int nt = 0; nt < 8; nt++)
                MMA_BF16(sacc[nt], qa, kbl[nt >> 1][(nt & 1) * 2], kbl[nt >> 1][(nt & 1) * 2 + 1]);
        }

#pragma unroll
        for (int nt = 0; nt < 8; nt++) {
            int kg0 = k0 + nt * 8 + tg * 2, kg1 = kg0 + 1;
            int d00 = qg_lo - kg0, d01 = qg_lo - kg1;
            int d10 = qg_hi - kg0, d11 = qg_hi - kg1;
            sacc[nt][0] = (d00 >= 0 && d00 < WINDOW) ? sacc[nt][0] * scale : -1e30f;
            sacc[nt][1] = (d01 >= 0 && d01 < WINDOW) ? sacc[nt][1] * scale : -1e30f;
            sacc[nt][2] = (d10 >= 0 && d10 < WINDOW) ? sacc[nt][2] * scale : -1e30f;
            sacc[nt][3] = (d11 >= 0 && d11 < WINDOW) ? sacc[nt][3] * scale : -1e30f;
        }

        float mx0 = -1e30f, mx1 = -1e30f;
#pragma unroll
        for (int nt = 0; nt < 8; nt++) {
            mx0 = fmaxf(mx0, fmaxf(sacc[nt][0], sacc[nt][1]));
            mx1 = fmaxf(mx1, fmaxf(sacc[nt][2], sacc[nt][3]));
        }
        mx0 = fmaxf(mx0, __shfl_xor_sync(0xffffffffu, mx0, 1));
        mx0 = fmaxf(mx0, __shfl_xor_sync(0xffffffffu, mx0, 2));
        mx1 = fmaxf(mx1, __shfl_xor_sync(0xffffffffu, mx1, 1));
        mx1 = fmaxf(mx1, __shfl_xor_sync(0xffffffffu, mx1, 2));
        float mn0 = fmaxf(m_lo, mx0), mn1 = fmaxf(m_hi, mx1);
        float al0 = __expf(m_lo - mn0), al1 = __expf(m_hi - mn1);
        float ps0 = 0.f, ps1 = 0.f;
#pragma unroll
        for (int nt = 0; nt < 8; nt++) {
            float p0 = (sacc[nt][0] > -1e29f) ? __expf(sacc[nt][0] - mn0) : 0.f;
            float p1 = (sacc[nt][1] > -1e29f) ? __expf(sacc[nt][1] - mn0) : 0.f;
            float p2 = (sacc[nt][2] > -1e29f) ? __expf(sacc[nt][2] - mn1) : 0.f;
            float p3 = (sacc[nt][3] > -1e29f) ? __expf(sacc[nt][3] - mn1) : 0.f;
            sacc[nt][0] = p0; sacc[nt][1] = p1; sacc[nt][2] = p2; sacc[nt][3] = p3;
            ps0 += p0 + p1;
            ps1 += p2 + p3;
        }
        ps0 += __shfl_xor_sync(0xffffffffu, ps0, 1);
        ps0 += __shfl_xor_sync(0xffffffffu, ps0, 2);
        ps1 += __shfl_xor_sync(0xffffffffu, ps1, 1);
        ps1 += __shfl_xor_sync(0xffffffffu, ps1, 2);
        l_lo = l_lo * al0 + ps0; m_lo = mn0;
        l_hi = l_hi * al1 + ps1; m_hi = mn1;
#pragma unroll
        for (int nt = 0; nt < 16; nt++) {
            oacc[nt][0] *= al0; oacc[nt][1] *= al0;
            oacc[nt][2] *= al1; oacc[nt][3] *= al1;
        }

        // ---- O += P V : P split fp16 hi/lo, V single fp16 (2 passes) ----
#pragma unroll
        for (int kv = 0; kv < 4; kv++) {
            unsigned pa_h[4], pa_l[4];
            {
                __half2 h0, h1, h2, h3, l0v, l1v, l2v, l3v;
                __half hh, ll;
                split2h(sacc[2 * kv][0], hh, ll);     h0.x = hh; l0v.x = ll;
                split2h(sacc[2 * kv][1], hh, ll);     h0.y = hh; l0v.y = ll;
                split2h(sacc[2 * kv][2], hh, ll);     h1.x = hh; l1v.x = ll;
                split2h(sacc[2 * kv][3], hh, ll);     h1.y = hh; l1v.y = ll;
                split2h(sacc[2 * kv + 1][0], hh, ll); h2.x = hh; l2v.x = ll;
                split2h(sacc[2 * kv + 1][1], hh, ll); h2.y = hh; l2v.y = ll;
                split2h(sacc[2 * kv + 1][2], hh, ll); h3.x = hh; l3v.x = ll;
                split2h(sacc[2 * kv + 1][3], hh, ll); h3.y = hh; l3v.y = ll;
                pa_h[0] = *(unsigned*)&h0; pa_h[1] = *(unsigned*)&h1;
                pa_h[2] = *(unsigned*)&h2; pa_h[3] = *(unsigned*)&h3;
                pa_l[0] = *(unsigned*)&l0v; pa_l[1] = *(unsigned*)&l1v;
                pa_l[2] = *(unsigned*)&l2v; pa_l[3] = *(unsigned*)&l3v;
            }
#pragma unroll
            for (int half = 0; half < 2; half++) {
                unsigned vbh[4][4];
#pragma unroll
                for (int ntp = 0; ntp < 4; ntp++)
                    LDSM4(vbh[ntp], sb + SV_OFF + boffV + (half * 4 + ntp) * (16 * AV_STB) + kv * 32);
#pragma unroll
                for (int nt = 0; nt < 8; nt++)
                    MMA_F16(oacc[half * 8 + nt], pa_h, vbh[nt >> 1][(nt & 1) * 2], vbh[nt >> 1][(nt & 1) * 2 + 1]);
#pragma unroll
                for (int nt = 0; nt < 8; nt++)
                    MMA_F16(oacc[half * 8 + nt], pa_l, vbh[nt >> 1][(nt & 1) * 2], vbh[nt >> 1][(nt & 1) * 2 + 1]);
            }
        }
        __syncthreads();
    }

    // ---- epilogue: normalize + fp16 hi/lo out ----
    float inv0 = 1.f / l_lo, inv1 = 1.f / l_hi;
#pragma unroll
    for (int nt = 0; nt < 16; nt++) {
        int col = h * HD + nt * 8 + tg * 2;
        float v0 = oacc[nt][0] * inv0, v1 = oacc[nt][1] * inv0;
        float v2 = oacc[nt][2] * inv1, v3 = oacc[nt][3] * inv1;
        __half2 hp, lp;
        __half hh, ll;
        split2h(v0, hh, ll); hp.x = hh; lp.x = ll;
        split2h(v1, hh, ll); hp.y = hh; lp.y = ll;
        *(__half2*)&g_ath[(long)qg_lo * NQD + col] = hp;
        *(__half2*)&g_atl[(long)qg_lo * NQD + col] = lp;
        split2h(v2, hh, ll); hp.x = hh; lp.x = ll;
        split2h(v3, hh, ll); hp.y = hh; lp.y = ll;
        *(__half2*)&g_ath[(long)qg_hi * NQD + col] = hp;
        *(__half2*)&g_atl[(long)qg_hi * NQD + col] = lp;
    }
}

// ============================================================================
extern "C" void kernel_launch(void* const* d_in, const int* in_sizes, int n_in,
                              void* d_out, int out_size)
{
    const float* x   = (const float*)d_in[0];
    const float* fc  = (const float*)d_in[1];
    const float* fs  = (const float*)d_in[2];
    // d_in[3]: mask — unused (causal + sliding window computed analytically)
    const float* w_q = (const float*)d_in[4];
    const float* w_k = (const float*)d_in[5];
    const float* w_v = (const float*)d_in[6];
    const float* w_o = (const float*)d_in[7];
    float* out = (float*)d_out;

    __nv_bfloat16 *xh, *xl, *wch, *wcl;
    __half *ath, *atl, *woh;
    cudaGetSymbolAddress((void**)&xh, g_xh);   cudaGetSymbolAddress((void**)&xl, g_xl);
    cudaGetSymbolAddress((void**)&ath, g_ath); cudaGetSymbolAddress((void**)&atl, g_atl);
    cudaGetSymbolAddress((void**)&wch, g_wch); cudaGetSymbolAddress((void**)&wcl, g_wcl);
    cudaGetSymbolAddress((void**)&woh, g_woh);

    cudaFuncSetAttribute(gemm_qkv, cudaFuncAttributeMaxDynamicSharedMemorySize, GSMEM);
    cudaFuncSetAttribute(gemm_o, cudaFuncAttributeMaxDynamicSharedMemorySize, OSMEM);
    cudaFuncSetAttribute(attn_mma, cudaFuncAttributeMaxDynamicSharedMemorySize, ASMEM);

    // one-time operand prep
    cvt_hl<<<(S_LEN * D_MODEL / 4 + 255) / 256, 256>>>(x, xh, xl, S_LEN * D_MODEL);
    transpose_hl<<<dim3(NQD / 32, D_MODEL / 32), dim3(32, 8)>>>(
        w_q, wch, wcl, D_MODEL, NQD);
    transpose_hl<<<dim3(NKVD / 32, D_MODEL / 32), dim3(32, 8)>>>(
        w_k, wch + (long)NQD * D_MODEL, wcl + (long)NQD * D_MODEL, D_MODEL, NKVD);
    transpose_hl<<<dim3(NKVD / 32, D_MODEL / 32), dim3(32, 8)>>>(
        w_v, wch + (long)(NQD + NKVD) * D_MODEL, wcl + (long)(NQD + NKVD) * D_MODEL, D_MODEL, NKVD);
    transpose_h<<<dim3(D_MODEL / 32, NQD / 32), dim3(32, 8)>>>(w_o, woh, NQD, D_MODEL);

    // fused QKV projection (bf16 3-pass; fused rope / rope / v-transpose epilogue)
    gemm_qkv<<<dim3(NCAT / 128, S_LEN / 128), 256, GSMEM>>>(
        xh, xl, wch, wcl, fc, fs, S_LEN, NCAT, D_MODEL);

    // attention (QK bf16 3-pass, PV fp16 2-pass) -> fp16 hi/lo attn-out
    attn_mma<<<dim3(S_LEN / 64, NQ), 128, ASMEM>>>();

    // output projection (fp16 2-pass)
    gemm_o<<<dim3(D_MODEL / 128, S_LEN / 128), 256, OSMEM>>>(
        ath, atl, woh, out, S_LEN, D_MODEL, NQD);
}

// round 14
// speedup vs baseline: 6.4751x; 1.1442x over previous
#include <cuda_runtime.h>
#include <cuda_bf16.h>
#include <cuda_fp16.h>
#include <cstdint>

#define S_LEN   2048
#define D_MODEL 4096
#define NQ      32
#define NKV     8
#define HD      128
#define WINDOW  1024
#define NQD     (NQ*HD)    // 4096
#define NKVD    (NKV*HD)   // 1024
#define NCAT    (NQD + 2*NKVD)  // 6144 fused QKV output width

// ---- operands ----
__device__ __nv_bfloat16 g_xh[S_LEN * D_MODEL],  g_xl[S_LEN * D_MODEL];
__device__ __half        g_at[S_LEN * NQD];                            // attn out fp16 single
__device__ __nv_bfloat16 g_qh[S_LEN * NQD],      g_ql[S_LEN * NQD];
__device__ __nv_bfloat16 g_kh[S_LEN * NKVD],     g_kl[S_LEN * NKVD];
__device__ __half        g_vt[NKVD * S_LEN];                           // V fp16 [kvh*hd][seq]
__device__ __nv_bfloat16 g_wch[NCAT * D_MODEL],  g_wcl[NCAT * D_MODEL]; // [wq;wk;wv] [N][K]
__device__ __half        g_woh[D_MODEL * NQD];                         // w_o fp16 single [N][K]

// ============================================================================
// helpers
// ============================================================================
__device__ __forceinline__ unsigned smem_u32(const void* p) {
    unsigned a;
    asm("{ .reg .u64 t; cvta.to.shared.u64 t, %1; cvt.u32.u64 %0, t; }" : "=r"(a) : "l"(p));
    return a;
}
__device__ __forceinline__ void cp_async16(unsigned s, const void* g) {
    asm volatile("cp.async.cg.shared.global [%0], [%1], 16;" :: "r"(s), "l"(g) : "memory");
}
__device__ __forceinline__ void split2(float v, __nv_bfloat16& h, __nv_bfloat16& l) {
    h = __float2bfloat16_rn(v);
    l = __float2bfloat16_rn(v - __bfloat162float(h));
}

#define MMA_BF16(acc, a, b0v, b1v)                                            \
    asm volatile(                                                             \
        "mma.sync.aligned.m16n8k16.row.col.f32.bf16.bf16.f32 "                \
        "{%0,%1,%2,%3},{%4,%5,%6,%7},{%8,%9},{%0,%1,%2,%3};"                  \
        : "+f"(acc[0]), "+f"(acc[1]), "+f"(acc[2]), "+f"(acc[3])              \
        : "r"(a[0]), "r"(a[1]), "r"(a[2]), "r"(a[3]), "r"(b0v), "r"(b1v))

#define MMA_F16(acc, a, b0v, b1v)                                             \
    asm volatile(                                                             \
        "mma.sync.aligned.m16n8k16.row.col.f32.f16.f16.f32 "                  \
        "{%0,%1,%2,%3},{%4,%5,%6,%7},{%8,%9},{%0,%1,%2,%3};"                  \
        : "+f"(acc[0]), "+f"(acc[1]), "+f"(acc[2]), "+f"(acc[3])              \
        : "r"(a[0]), "r"(a[1]), "r"(a[2]), "r"(a[3]), "r"(b0v), "r"(b1v))

#define LDSM4(r, addr)                                                        \
    asm volatile("ldmatrix.sync.aligned.m8n8.x4.shared.b16 {%0,%1,%2,%3}, [%4];" \
        : "=r"((r)[0]), "=r"((r)[1]), "=r"((r)[2]), "=r"((r)[3]) : "r"(addr))

// ============================================================================
// one-time converts
// ============================================================================
__global__ void cvt_hl(const float* __restrict__ in, __nv_bfloat16* __restrict__ ho,
                       __nv_bfloat16* __restrict__ lo, int n) {
    int i = (blockIdx.x * blockDim.x + threadIdx.x) * 4;
    if (i >= n) return;
    float4 v = *(const float4*)&in[i];
    __align__(8) __nv_bfloat16 h[4], l[4];
    split2(v.x, h[0], l[0]);
    split2(v.y, h[1], l[1]);
    split2(v.z, h[2], l[2]);
    split2(v.w, h[3], l[3]);
    *(uint2*)&ho[i] = *(uint2*)h;
    *(uint2*)&lo[i] = *(uint2*)l;
}

// weights: w[K][N] fp32 -> th/tl[N][K] bf16 (transpose + split)
__global__ void transpose_hl(const float* __restrict__ w, __nv_bfloat16* __restrict__ th,
                             __nv_bfloat16* __restrict__ tl, int K, int N) {
    __shared__ float t[32][33];
    int n0 = blockIdx.x * 32, k0 = blockIdx.y * 32;
    int tx = threadIdx.x, ty = threadIdx.y;   // 32 x 8
#pragma unroll
    for (int i = 0; i < 32; i += 8)
        t[ty + i][tx] = w[(k0 + ty + i) * N + n0 + tx];
    __syncthreads();
#pragma unroll
    for (int i = 0; i < 32; i += 8) {
        float v = t[tx][ty + i];
        __nv_bfloat16 h, l;
        split2(v, h, l);
        th[(n0 + ty + i) * K + k0 + tx] = h;
        tl[(n0 + ty + i) * K + k0 + tx] = l;
    }
}

// w_o: w[K][N] fp32 -> th[N][K] fp16 single (transpose)
__global__ void transpose_h(const float* __restrict__ w, __half* __restrict__ th,
                            int K, int N) {
    __shared__ float t[32][33];
    int n0 = blockIdx.x * 32, k0 = blockIdx.y * 32;
    int tx = threadIdx.x, ty = threadIdx.y;
#pragma unroll
    for (int i = 0; i < 32; i += 8)
        t[ty + i][tx] = w[(k0 + ty + i) * N + n0 + tx];
    __syncthreads();
#pragma unroll
    for (int i = 0; i < 32; i += 8)
        th[(n0 + ty + i) * K + k0 + tx] = __float2half_rn(t[tx][ty + i]);
}

// ============================================================================
// QKV GEMM (bf16, 3-pass): C = A[M,K] @ Bt[N,K]^T. 128x128 tile, K-slab 32,
// 256 thr, 2 CTAs/SM. L2-rasterized block order (8 n-blocks per group).
// Fused epilogue by n-segment: Q rope / K rope / V transpose->fp16.
// ============================================================================
#define ABYTES 10240
#define STAGEB (4 * ABYTES)
#define GSMEM  (2 * STAGEB)

__global__ __launch_bounds__(256, 2) void gemm_qkv(
    const __nv_bfloat16* __restrict__ Ah, const __nv_bfloat16* __restrict__ Al,
    const __nv_bfloat16* __restrict__ Bh, const __nv_bfloat16* __restrict__ Bl,
    const float* __restrict__ cosb, const float* __restrict__ sinb,
    int M, int N, int K)
{
    extern __shared__ char smem[];
    const int tid = threadIdx.x, lane = tid & 31, w = tid >> 5;
    const int g = lane >> 2, tg = lane & 3;
    const int t8 = lane >> 3, r8 = lane & 7;
    const int wm = (w & 1) * 64, wn = (w >> 1) * 32;
    // L2 rasterization: groups of 8 n-blocks x all m-blocks
    const int bid = blockIdx.y * gridDim.x + blockIdx.x;
    const int gsz = 8 * gridDim.y;
    const int grp = bid / gsz, rem = bid % gsz;
    const int m0 = (rem >> 3) * 128, n0 = (grp * 8 + (rem & 7)) * 128;
    const unsigned sbase = smem_u32(smem);

    auto load_slab = [&](int st, int kt) {
        unsigned s0 = sbase + st * STAGEB;
#pragma unroll
        for (int i = 0; i < 2; i++) {
            int idx = tid + i * 256;
            int row = idx >> 2, c = idx & 3;
            unsigned so = (unsigned)(row * 80 + c * 16);
            long ea = (long)(m0 + row) * K + kt + c * 8;
            long eb = (long)(n0 + row) * K + kt + c * 8;
            cp_async16(s0 + so, Ah + ea);
            cp_async16(s0 + ABYTES + so, Al + ea);
            cp_async16(s0 + 2 * ABYTES + so, Bh + eb);
            cp_async16(s0 + 3 * ABYTES + so, Bl + eb);
        }
        asm volatile("cp.async.commit_group;" ::: "memory");
    };

    float acc[4][4][4];
#pragma unroll
    for (int mt = 0; mt < 4; mt++)
#pragma unroll
        for (int nt = 0; nt < 4; nt++)
#pragma unroll
            for (int i = 0; i < 4; i++) acc[mt][nt][i] = 0.f;

    const unsigned aoff = (unsigned)((wm + (t8 & 1) * 8 + r8) * 80 + (t8 >> 1) * 16);
    const unsigned boff = (unsigned)((wn + (t8 >> 1) * 8 + r8) * 80 + (t8 & 1) * 16);

    const int T = K >> 5;
    load_slab(0, 0);
    load_slab(1, 32);

    for (int it = 0; it < T; it++) {
        asm volatile("cp.async.wait_group 1;" ::: "memory");
        __syncthreads();
        unsigned sb = sbase + (it & 1) * STAGEB;
        unsigned sAh = sb, sAl = sb + ABYTES, sBh = sb + 2 * ABYTES, sBl = sb + 3 * ABYTES;

#pragma unroll
        for (int ks = 0; ks < 2; ks++) {
            unsigned b_h[2][4], b_l[2][4], a_h[4][4];
#pragma unroll
            for (int ntp = 0; ntp < 2; ntp++) {
                LDSM4(b_h[ntp], sBh + boff + ntp * 1280 + ks * 32);
                LDSM4(b_l[ntp], sBl + boff + ntp * 1280 + ks * 32);
            }
#pragma unroll
            for (int mt = 0; mt < 4; mt++)
                LDSM4(a_h[mt], sAh + aoff + mt * 1280 + ks * 32);
#pragma unroll
            for (int mt = 0; mt < 4; mt++)
#pragma unroll
                for (int nt = 0; nt < 4; nt++)
                    MMA_BF16(acc[mt][nt], a_h[mt], b_h[nt >> 1][(nt & 1) * 2], b_h[nt >> 1][(nt & 1) * 2 + 1]);
#pragma unroll
            for (int mt = 0; mt < 4; mt++)
#pragma unroll
                for (int nt = 0; nt < 4; nt++)
                    MMA_BF16(acc[mt][nt], a_h[mt], b_l[nt >> 1][(nt & 1) * 2], b_l[nt >> 1][(nt & 1) * 2 + 1]);
#pragma unroll
            for (int mt = 0; mt < 4; mt++) {
                unsigned a_l[4];
                LDSM4(a_l, sAl + aoff + mt * 1280 + ks * 32);
#pragma unroll
                for (int nt = 0; nt < 4; nt++)
                    MMA_BF16(acc[mt][nt], a_l, b_h[nt >> 1][(nt & 1) * 2], b_h[nt >> 1][(nt & 1) * 2 + 1]);
            }
        }
        __syncthreads();
        if (it + 2 < T) load_slab(it & 1, (it + 2) * 32);
    }

    // ---- fused epilogue ----
#pragma unroll
    for (int mt = 0; mt < 4; mt++)
#pragma unroll
        for (int nt = 0; nt < 4; nt++) {
            int row = m0 + wm + mt * 16 + g;
            int col = n0 + wn + nt * 8 + tg * 2;
            if (n0 < NQD + NKVD) {
                // Q or K segment: fused RoPE + bf16 hi/lo split
                const bool isQ = (n0 < NQD);
                const int cseg = isQ ? col : col - NQD;
                const int strd = isQ ? NQD : NKVD;
                __nv_bfloat16* Hh = isQ ? g_qh : g_kh;
                __nv_bfloat16* Ll = isQ ? g_ql : g_kl;
                const int pi = (cseg & 127) >> 1;
#pragma unroll
                for (int half = 0; half < 2; half++) {
                    int rr = row + half * 8;
                    float cs = cosb[rr * 64 + pi], sn = sinb[rr * 64 + pi];
                    float e = acc[mt][nt][half * 2], o = acc[mt][nt][half * 2 + 1];
                    float re = e * cs - o * sn;
                    float ro = e * sn + o * cs;
                    __nv_bfloat162 hp, lp;
                    __nv_bfloat16 hh, ll;
                    split2(re, hh, ll); hp.x = hh; lp.x = ll;
                    split2(ro, hh, ll); hp.y = hh; lp.y = ll;
                    *(__nv_bfloat162*)&Hh[(long)rr * strd + cseg] = hp;
                    *(__nv_bfloat162*)&Ll[(long)rr * strd + cseg] = lp;
                }
            } else {
                // V segment: transpose + single fp16 -> [hd][seq]
                const int cv = col - (NQD + NKVD);
#pragma unroll
                for (int half = 0; half < 2; half++) {
                    int rr = row + half * 8;
#pragma unroll
                    for (int dc = 0; dc < 2; dc++) {
                        float v = acc[mt][nt][half * 2 + dc];
                        g_vt[(long)(cv + dc) * S_LEN + rr] = __float2half_rn(v);
                    }
                }
            }
        }
}

// ============================================================================
// O-projection GEMM (fp16, SINGLE pass: A single fp16, B single fp16).
// 2 smem arrays per stage. fp32 out.
// ============================================================================
#define OSTAGE (2 * ABYTES)
#define OSMEM  (2 * OSTAGE)

__global__ __launch_bounds__(256, 2) void gemm_o(
    const __half* __restrict__ Ah, const __half* __restrict__ Bh,
    float* __restrict__ C, int M, int N, int K)
{
    extern __shared__ char smem[];
    const int tid = threadIdx.x, lane = tid & 31, w = tid >> 5;
    const int g = lane >> 2, tg = lane & 3;
    const int t8 = lane >> 3, r8 = lane & 7;
    const int wm = (w & 1) * 64, wn = (w >> 1) * 32;
    const int m0 = blockIdx.y * 128, n0 = blockIdx.x * 128;
    const unsigned sbase = smem_u32(smem);

    auto load_slab = [&](int st, int kt) {
        unsigned s0 = sbase + st * OSTAGE;
#pragma unroll
        for (int i = 0; i < 2; i++) {
            int idx = tid + i * 256;
            int row = idx >> 2, c = idx & 3;
            unsigned so = (unsigned)(row * 80 + c * 16);
            long ea = (long)(m0 + row) * K + kt + c * 8;
            long eb = (long)(n0 + row) * K + kt + c * 8;
            cp_async16(s0 + so, Ah + ea);
            cp_async16(s0 + ABYTES + so, Bh + eb);
        }
        asm volatile("cp.async.commit_group;" ::: "memory");
    };

    float acc[4][4][4];
#pragma unroll
    for (int mt = 0; mt < 4; mt++)
#pragma unroll
        for (int nt = 0; nt < 4; nt++)
#pragma unroll
            for (int i = 0; i < 4; i++) acc[mt][nt][i] = 0.f;

    const unsigned aoff = (unsigned)((wm + (t8 & 1) * 8 + r8) * 80 + (t8 >> 1) * 16);
    const unsigned boff = (unsigned)((wn + (t8 >> 1) * 8 + r8) * 80 + (t8 & 1) * 16);

    const int T = K >> 5;
    load_slab(0, 0);
    load_slab(1, 32);

    for (int it = 0; it < T; it++) {
        asm volatile("cp.async.wait_group 1;" ::: "memory");
        __syncthreads();
        unsigned sb = sbase + (it & 1) * OSTAGE;
        unsigned sAh = sb, sBh = sb + ABYTES;

#pragma unroll
        for (int ks = 0; ks < 2; ks++) {
            unsigned b_h[2][4], a_h[4][4];
#pragma unroll
            for (int ntp = 0; ntp < 2; ntp++)
                LDSM4(b_h[ntp], sBh + boff + ntp * 1280 + ks * 32);
#pragma unroll
            for (int mt = 0; mt < 4; mt++)
                LDSM4(a_h[mt], sAh + aoff + mt * 1280 + ks * 32);
#pragma unroll
            for (int mt = 0; mt < 4; mt++)
#pragma unroll
                for (int nt = 0; nt < 4; nt++)
                    MMA_F16(acc[mt][nt], a_h[mt], b_h[nt >> 1][(nt & 1) * 2], b_h[nt >> 1][(nt & 1) * 2 + 1]);
        }
        __syncthreads();
        if (it + 2 < T) load_slab(it & 1, (it + 2) * 32);
    }

#pragma unroll
    for (int mt = 0; mt < 4; mt++)
#pragma unroll
        for (int nt = 0; nt < 4; nt++) {
            int row = m0 + wm + mt * 16 + g;
            int col = n0 + wn + nt * 8 + tg * 2;
            float2 v0 = {acc[mt][nt][0], acc[mt][nt][1]};
            float2 v1 = {acc[mt][nt][2], acc[mt][nt][3]};
            *(float2*)&C[(long)row * N + col] = v0;
            *(float2*)&C[(long)(row + 8) * N + col] = v1;
        }
}

// ============================================================================
// flash attention: QK bf16 3-pass; PV fp16 SINGLE pass (P single, V single).
// BQ=BK=64, 128 thr (4 warps). Heavy-first scheduling (reversed qt).
// ============================================================================
#define AQ_STB 272
#define AV_STB 144
#define SQ_OFF 0
#define SQL_OFF (64 * AQ_STB)
#define SK_OFF  (2 * 64 * AQ_STB)
#define SKL_OFF (3 * 64 * AQ_STB)
#define SV_OFF  (4 * 64 * AQ_STB)
#define ASMEM   (SV_OFF + 128 * AV_STB)   // 88064

__global__ __launch_bounds__(128) void attn_mma()
{
    extern __shared__ char smem[];
    const unsigned sb = smem_u32(smem);
    const int tid = threadIdx.x, lane = tid & 31, w = tid >> 5;
    const int g = lane >> 2, tg = lane & 3;
    const int t8 = lane >> 3, r8 = lane & 7;
    const int qt = (int)gridDim.x - 1 - (int)blockIdx.x;   // heavy tiles first
    const int q0 = qt * 64, h = blockIdx.y, kvh = h >> 2;

#pragma unroll
    for (int i = 0; i < 8; i++) {
        int idx = tid + i * 128;
        int row = idx >> 4, c = idx & 15;
        long gq = (long)(q0 + row) * NQD + h * HD + c * 8;
        unsigned so = (unsigned)(row * AQ_STB + c * 16);
        *(uint4*)(smem + SQ_OFF + so) = *(const uint4*)&g_qh[gq];
        *(uint4*)(smem + SQL_OFF + so) = *(const uint4*)&g_ql[gq];
    }

    const unsigned aoffQ = (unsigned)((w * 16 + (t8 & 1) * 8 + r8) * AQ_STB + (t8 >> 1) * 16);
    const unsigned boffK = (unsigned)(((t8 >> 1) * 8 + r8) * AQ_STB + (t8 & 1) * 16);
    const unsigned boffV = (unsigned)(((t8 >> 1) * 8 + r8) * AV_STB + (t8 & 1) * 16);

    float oacc[16][4];
#pragma unroll
    for (int nt = 0; nt < 16; nt++)
#pragma unroll
        for (int i = 0; i < 4; i++) oacc[nt][i] = 0.f;
    float m_lo = -1e30f, m_hi = -1e30f, l_lo = 0.f, l_hi = 0.f;

    const int qg_lo = q0 + w * 16 + g;
    const int qg_hi = qg_lo + 8;
    int lo = q0 - (WINDOW - 1);
    const int kt_lo = lo > 0 ? (lo >> 6) : 0;
    const int kt_hi = qt;
    const float scale = 0.08838834764831845f;

    __syncthreads();

    for (int kt = kt_lo; kt <= kt_hi; kt++) {
        const int k0 = kt * 64;
        // load K (64x128 bf16 hi/lo) and V (128x64 fp16)
#pragma unroll
        for (int i = 0; i < 8; i++) {
            int idx = tid + i * 128;
            int row = idx >> 4, c = idx & 15;
            long gk = (long)(k0 + row) * NKVD + kvh * HD + c * 8;
            unsigned so = (unsigned)(row * AQ_STB + c * 16);
            *(uint4*)(smem + SK_OFF + so) = *(const uint4*)&g_kh[gk];
            *(uint4*)(smem + SKL_OFF + so) = *(const uint4*)&g_kl[gk];
            int vrow = idx >> 3, vc = idx & 7;
            long gv = (long)(kvh * HD + vrow) * S_LEN + k0 + vc * 8;
            unsigned vo = (unsigned)(vrow * AV_STB + vc * 16);
            *(uint4*)(smem + SV_OFF + vo) = *(const uint4*)&g_vt[gv];
        }
        __syncthreads();

        float sacc[8][4];
#pragma unroll
        for (int nt = 0; nt < 8; nt++)
#pragma unroll
            for (int i = 0; i < 4; i++) sacc[nt][i] = 0.f;

#pragma unroll
        for (int ks = 0; ks < 8; ks++) {
            unsigned qa[4], qla[4], kb[4][4], kbl[4][4];
            LDSM4(qa, sb + SQ_OFF + aoffQ + ks * 32);
            LDSM4(qla, sb + SQL_OFF + aoffQ + ks * 32);
#pragma unroll
            for (int ntp = 0; ntp < 4; ntp++) {
                LDSM4(kb[ntp], sb + SK_OFF + boffK + ntp * (16 * AQ_STB) + ks * 32);
                LDSM4(kbl[ntp], sb + SKL_OFF + boffK + ntp * (16 * AQ_STB) + ks * 32);
            }
#pragma unroll
            for (int nt = 0; nt < 8; nt++)
                MMA_BF16(sacc[nt], qa, kb[nt >> 1][(nt & 1) * 2], kb[nt >> 1][(nt & 1) * 2 + 1]);
#pragma unroll
            for (int nt = 0; nt < 8; nt++)
                MMA_BF16(sacc[nt], qla, kb[nt >> 1][(nt & 1) * 2], kb[nt >> 1][(nt & 1) * 2 + 1]);
#pragma unroll
            for (int nt = 0; nt < 8; nt++)
                MMA_BF16(sacc[nt], qa, kbl[nt >> 1][(nt & 1) * 2], kbl[nt >> 1][(nt & 1) * 2 + 1]);
        }

#pragma unroll
        for (int nt = 0; nt < 8; nt++) {
            int kg0 = k0 + nt * 8 + tg * 2, kg1 = kg0 + 1;
            int d00 = qg_lo - kg0, d01 = qg_lo - kg1;
            int d10 = qg_hi - kg0, d11 = qg_hi - kg1;
            sacc[nt][0] = (d00 >= 0 && d00 < WINDOW) ? sacc[nt][0] * scale : -1e30f;
            sacc[nt][1] = (d01 >= 0 && d01 < WINDOW) ? sacc[nt][1] * scale : -1e30f;
            sacc[nt][2] = (d10 >= 0 && d10 < WINDOW) ? sacc[nt][2] * scale : -1e30f;
            sacc[nt][3] = (d11 >= 0 && d11 < WINDOW) ? sacc[nt][3] * scale : -1e30f;
        }

        float mx0 = -1e30f, mx1 = -1e30f;
#pragma unroll
        for (int nt = 0; nt < 8; nt++) {
            mx0 = fmaxf(mx0, fmaxf(sacc[nt][0], sacc[nt][1]));
            mx1 = fmaxf(mx1, fmaxf(sacc[nt][2], sacc[nt][3]));
        }
        mx0 = fmaxf(mx0, __shfl_xor_sync(0xffffffffu, mx0, 1));
        mx0 = fmaxf(mx0, __shfl_xor_sync(0xffffffffu, mx0, 2));
        mx1 = fmaxf(mx1, __shfl_xor_sync(0xffffffffu, mx1, 1));
        mx1 = fmaxf(mx1, __shfl_xor_sync(0xffffffffu, mx1, 2));
        float mn0 = fmaxf(m_lo, mx0), mn1 = fmaxf(m_hi, mx1);
        float al0 = __expf(m_lo - mn0), al1 = __expf(m_hi - mn1);
        float ps0 = 0.f, ps1 = 0.f;
#pragma unroll
        for (int nt = 0; nt < 8; nt++) {
            float p0 = (sacc[nt][0] > -1e29f) ? __expf(sacc[nt][0] - mn0) : 0.f;
            float p1 = (sacc[nt][1] > -1e29f) ? __expf(sacc[nt][1] - mn0) : 0.f;
            float p2 = (sacc[nt][2] > -1e29f) ? __expf(sacc[nt][2] - mn1) : 0.f;
            float p3 = (sacc[nt][3] > -1e29f) ? __expf(sacc[nt][3] - mn1) : 0.f;
            sacc[nt][0] = p0; sacc[nt][1] = p1; sacc[nt][2] = p2; sacc[nt][3] = p3;
            ps0 += p0 + p1;
            ps1 += p2 + p3;
        }
        ps0 += __shfl_xor_sync(0xffffffffu, ps0, 1);
        ps0 += __shfl_xor_sync(0xffffffffu, ps0, 2);
        ps1 += __shfl_xor_sync(0xffffffffu, ps1, 1);
        ps1 += __shfl_xor_sync(0xffffffffu, ps1, 2);
        l_lo = l_lo * al0 + ps0; m_lo = mn0;
        l_hi = l_hi * al1 + ps1; m_hi = mn1;
#pragma unroll
        for (int nt = 0; nt < 16; nt++) {
            oacc[nt][0] *= al0; oacc[nt][1] *= al0;
            oacc[nt][2] *= al1; oacc[nt][3] *= al1;
        }

        // ---- O += P V : P single fp16, V single fp16 (1 pass) ----
#pragma unroll
        for (int kv = 0; kv < 4; kv++) {
            unsigned pa[4];
            {
                __half2 h0, h1, h2, h3;
                h0.x = __float2half_rn(sacc[2 * kv][0]);
                h0.y = __float2half_rn(sacc[2 * kv][1]);
                h1.x = __float2half_rn(sacc[2 * kv][2]);
                h1.y = __float2half_rn(sacc[2 * kv][3]);
                h2.x = __float2half_rn(sacc[2 * kv + 1][0]);
                h2.y = __float2half_rn(sacc[2 * kv + 1][1]);
                h3.x = __float2half_rn(sacc[2 * kv + 1][2]);
                h3.y = __float2half_rn(sacc[2 * kv + 1][3]);
                pa[0] = *(unsigned*)&h0; pa[1] = *(unsigned*)&h1;
                pa[2] = *(unsigned*)&h2; pa[3] = *(unsigned*)&h3;
            }
#pragma unroll
            for (int half = 0; half < 2; half++) {
                unsigned vbh[4][4];
#pragma unroll
                for (int ntp = 0; ntp < 4; ntp++)
                    LDSM4(vbh[ntp], sb + SV_OFF + boffV + (half * 4 + ntp) * (16 * AV_STB) + kv * 32);
#pragma unroll
                for (int nt = 0; nt < 8; nt++)
                    MMA_F16(oacc[half * 8 + nt], pa, vbh[nt >> 1][(nt & 1) * 2], vbh[nt >> 1][(nt & 1) * 2 + 1]);
            }
        }
        __syncthreads();
    }

    // ---- epilogue: normalize + single fp16 out ----
    float inv0 = 1.f / l_lo, inv1 = 1.f / l_hi;
#pragma unroll
    for (int nt = 0; nt < 16; nt++) {
        int col = h * HD + nt * 8 + tg * 2;
        __half2 hp;
        hp.x = __float2half_rn(oacc[nt][0] * inv0);
        hp.y = __float2half_rn(oacc[nt][1] * inv0);
        *(__half2*)&g_at[(long)qg_lo * NQD + col] = hp;
        hp.x = __float2half_rn(oacc[nt][2] * inv1);
        hp.y = __float2half_rn(oacc[nt][3] * inv1);
        *(__half2*)&g_at[(long)qg_hi * NQD + col] = hp;
    }
}

// ============================================================================
extern "C" void kernel_launch(void* const* d_in, const int* in_sizes, int n_in,
                              void* d_out, int out_size)
{
    const float* x   = (const float*)d_in[0];
    const float* fc  = (const float*)d_in[1];
    const float* fs  = (const float*)d_in[2];
    // d_in[3]: mask — unused (causal + sliding window computed analytically)
    const float* w_q = (const float*)d_in[4];
    const float* w_k = (const float*)d_in[5];
    const float* w_v = (const float*)d_in[6];
    const float* w_o = (const float*)d_in[7];
    float* out = (float*)d_out;

    __nv_bfloat16 *xh, *xl, *wch, *wcl;
    __half *at, *woh;
    cudaGetSymbolAddress((void**)&xh, g_xh);   cudaGetSymbolAddress((void**)&xl, g_xl);
    cudaGetSymbolAddress((void**)&at, g_at);
    cudaGetSymbolAddress((void**)&wch, g_wch); cudaGetSymbolAddress((void**)&wcl, g_wcl);
    cudaGetSymbolAddress((void**)&woh, g_woh);

    cudaFuncSetAttribute(gemm_qkv, cudaFuncAttributeMaxDynamicSharedMemorySize, GSMEM);
    cudaFuncSetAttribute(gemm_o, cudaFuncAttributeMaxDynamicSharedMemorySize, OSMEM);
    cudaFuncSetAttribute(attn_mma, cudaFuncAttributeMaxDynamicSharedMemorySize, ASMEM);

    // one-time operand prep
    cvt_hl<<<(S_LEN * D_MODEL / 4 + 255) / 256, 256>>>(x, xh, xl, S_LEN * D_MODEL);
    transpose_hl<<<dim3(NQD / 32, D_MODEL / 32), dim3(32, 8)>>>(
        w_q, wch, wcl, D_MODEL, NQD);
    transpose_hl<<<dim3(NKVD / 32, D_MODEL / 32), dim3(32, 8)>>>(
        w_k, wch + (long)NQD * D_MODEL, wcl + (long)NQD * D_MODEL, D_MODEL, NKVD);
    transpose_hl<<<dim3(NKVD / 32, D_MODEL / 32), dim3(32, 8)>>>(
        w_v, wch + (long)(NQD + NKVD) * D_MODEL, wcl + (long)(NQD + NKVD) * D_MODEL, D_MODEL, NKVD);
    transpose_h<<<dim3(D_MODEL / 32, NQD / 32), dim3(32, 8)>>>(w_o, woh, NQD, D_MODEL);

    // fused QKV projection (bf16 3-pass; fused rope / rope / v-transpose epilogue)
    gemm_qkv<<<dim3(NCAT / 128, S_LEN / 128), 256, GSMEM>>>(
        xh, xl, wch, wcl, fc, fs, S_LEN, NCAT, D_MODEL);

    // attention (QK bf16 3-pass, PV fp16 1-pass) -> fp16 single attn-out
    attn_mma<<<dim3(S_LEN / 64, NQ), 128, ASMEM>>>();

    // output projection (fp16 1-pass)
    gemm_o<<<dim3(D_MODEL / 128, S_LEN / 128), 256, OSMEM>>>(
        at, woh, out, S_LEN, D_MODEL, NQD);
}

// round 16
// speedup vs baseline: 6.5394x; 1.0099x over previous
#include <cuda_runtime.h>
#include <cuda_bf16.h>
#include <cuda_fp16.h>
#include <cstdint>

#define S_LEN   2048
#define D_MODEL 4096
#define NQ      32
#define NKV     8
#define HD      128
#define WINDOW  1024
#define NQD     (NQ*HD)    // 4096
#define NKVD    (NKV*HD)   // 1024
#define NCAT    (NQD + 2*NKVD)  // 6144 fused QKV output width

// ---- operands ----
__device__ __nv_bfloat16 g_xh[S_LEN * D_MODEL],  g_xl[S_LEN * D_MODEL];
__device__ __half        g_at[S_LEN * NQD];                            // attn out fp16 single
__device__ __nv_bfloat16 g_qh[S_LEN * NQD],      g_ql[S_LEN * NQD];
__device__ __nv_bfloat16 g_kh[S_LEN * NKVD],     g_kl[S_LEN * NKVD];
__device__ __half        g_vt[NKVD * S_LEN];                           // V fp16 [kvh*hd][seq]
__device__ __nv_bfloat16 g_wch[NCAT * D_MODEL],  g_wcl[NCAT * D_MODEL]; // [wq;wk;wv] [N][K]
__device__ __half        g_woh[D_MODEL * NQD];                         // w_o fp16 single [N][K]

// ============================================================================
// helpers
// ============================================================================
__device__ __forceinline__ unsigned smem_u32(const void* p) {
    unsigned a;
    asm("{ .reg .u64 t; cvta.to.shared.u64 t, %1; cvt.u32.u64 %0, t; }" : "=r"(a) : "l"(p));
    return a;
}
__device__ __forceinline__ void cp_async16(unsigned s, const void* g) {
    asm volatile("cp.async.cg.shared.global [%0], [%1], 16;" :: "r"(s), "l"(g) : "memory");
}
__device__ __forceinline__ void split2(float v, __nv_bfloat16& h, __nv_bfloat16& l) {
    h = __float2bfloat16_rn(v);
    l = __float2bfloat16_rn(v - __bfloat162float(h));
}

#define MMA_BF16(acc, a, b0v, b1v)                                            \
    asm volatile(                                                             \
        "mma.sync.aligned.m16n8k16.row.col.f32.bf16.bf16.f32 "                \
        "{%0,%1,%2,%3},{%4,%5,%6,%7},{%8,%9},{%0,%1,%2,%3};"                  \
        : "+f"(acc[0]), "+f"(acc[1]), "+f"(acc[2]), "+f"(acc[3])              \
        : "r"(a[0]), "r"(a[1]), "r"(a[2]), "r"(a[3]), "r"(b0v), "r"(b1v))

#define MMA_F16(acc, a, b0v, b1v)                                             \
    asm volatile(                                                             \
        "mma.sync.aligned.m16n8k16.row.col.f32.f16.f16.f32 "                  \
        "{%0,%1,%2,%3},{%4,%5,%6,%7},{%8,%9},{%0,%1,%2,%3};"                  \
        : "+f"(acc[0]), "+f"(acc[1]), "+f"(acc[2]), "+f"(acc[3])              \
        : "r"(a[0]), "r"(a[1]), "r"(a[2]), "r"(a[3]), "r"(b0v), "r"(b1v))

#define LDSM4(r, addr)                                                        \
    asm volatile("ldmatrix.sync.aligned.m8n8.x4.shared.b16 {%0,%1,%2,%3}, [%4];" \
        : "=r"((r)[0]), "=r"((r)[1]), "=r"((r)[2]), "=r"((r)[3]) : "r"(addr))

// ============================================================================
// one-time converts
// ============================================================================
__global__ void cvt_hl(const float* __restrict__ in, __nv_bfloat16* __restrict__ ho,
                       __nv_bfloat16* __restrict__ lo, int n) {
    int i = (blockIdx.x * blockDim.x + threadIdx.x) * 4;
    if (i >= n) return;
    float4 v = *(const float4*)&in[i];
    __align__(8) __nv_bfloat16 h[4], l[4];
    split2(v.x, h[0], l[0]);
    split2(v.y, h[1], l[1]);
    split2(v.z, h[2], l[2]);
    split2(v.w, h[3], l[3]);
    *(uint2*)&ho[i] = *(uint2*)h;
    *(uint2*)&lo[i] = *(uint2*)l;
}

// weights: w[K][N] fp32 -> th/tl[N][K] bf16 (transpose + split)
__global__ void transpose_hl(const float* __restrict__ w, __nv_bfloat16* __restrict__ th,
                             __nv_bfloat16* __restrict__ tl, int K, int N) {
    __shared__ float t[32][33];
    int n0 = blockIdx.x * 32, k0 = blockIdx.y * 32;
    int tx = threadIdx.x, ty = threadIdx.y;   // 32 x 8
#pragma unroll
    for (int i = 0; i < 32; i += 8)
        t[ty + i][tx] = w[(k0 + ty + i) * N + n0 + tx];
    __syncthreads();
#pragma unroll
    for (int i = 0; i < 32; i += 8) {
        float v = t[tx][ty + i];
        __nv_bfloat16 h, l;
        split2(v, h, l);
        th[(n0 + ty + i) * K + k0 + tx] = h;
        tl[(n0 + ty + i) * K + k0 + tx] = l;
    }
}

// w_o: w[K][N] fp32 -> th[N][K] fp16 single (transpose)
__global__ void transpose_h(const float* __restrict__ w, __half* __restrict__ th,
                            int K, int N) {
    __shared__ float t[32][33];
    int n0 = blockIdx.x * 32, k0 = blockIdx.y * 32;
    int tx = threadIdx.x, ty = threadIdx.y;
#pragma unroll
    for (int i = 0; i < 32; i += 8)
        t[ty + i][tx] = w[(k0 + ty + i) * N + n0 + tx];
    __syncthreads();
#pragma unroll
    for (int i = 0; i < 32; i += 8)
        th[(n0 + ty + i) * K + k0 + tx] = __float2half_rn(t[tx][ty + i]);
}

// ============================================================================
// QKV GEMM (bf16, 3-pass). 128x128 tile, K-slab 32, 256 thr, 2 CTAs/SM.
// L2-rasterized block order. Fused epilogue: Q rope / K rope / V->fp16 transp.
// ============================================================================
#define ABYTES 10240
#define STAGEB (4 * ABYTES)
#define GSMEM  (2 * STAGEB)

__global__ __launch_bounds__(256, 2) void gemm_qkv(
    const __nv_bfloat16* __restrict__ Ah, const __nv_bfloat16* __restrict__ Al,
    const __nv_bfloat16* __restrict__ Bh, const __nv_bfloat16* __restrict__ Bl,
    const float* __restrict__ cosb, const float* __restrict__ sinb,
    int M, int N, int K)
{
    extern __shared__ char smem[];
    const int tid = threadIdx.x, lane = tid & 31, w = tid >> 5;
    const int g = lane >> 2, tg = lane & 3;
    const int t8 = lane >> 3, r8 = lane & 7;
    const int wm = (w & 1) * 64, wn = (w >> 1) * 32;
    const int bid = blockIdx.y * gridDim.x + blockIdx.x;
    const int gsz = 8 * gridDim.y;
    const int grp = bid / gsz, rem = bid % gsz;
    const int m0 = (rem >> 3) * 128, n0 = (grp * 8 + (rem & 7)) * 128;
    const unsigned sbase = smem_u32(smem);

    auto load_slab = [&](int st, int kt) {
        unsigned s0 = sbase + st * STAGEB;
#pragma unroll
        for (int i = 0; i < 2; i++) {
            int idx = tid + i * 256;
            int row = idx >> 2, c = idx & 3;
            unsigned so = (unsigned)(row * 80 + c * 16);
            long ea = (long)(m0 + row) * K + kt + c * 8;
            long eb = (long)(n0 + row) * K + kt + c * 8;
            cp_async16(s0 + so, Ah + ea);
            cp_async16(s0 + ABYTES + so, Al + ea);
            cp_async16(s0 + 2 * ABYTES + so, Bh + eb);
            cp_async16(s0 + 3 * ABYTES + so, Bl + eb);
        }
        asm volatile("cp.async.commit_group;" ::: "memory");
    };

    float acc[4][4][4];
#pragma unroll
    for (int mt = 0; mt < 4; mt++)
#pragma unroll
        for (int nt = 0; nt < 4; nt++)
#pragma unroll
            for (int i = 0; i < 4; i++) acc[mt][nt][i] = 0.f;

    const unsigned aoff = (unsigned)((wm + (t8 & 1) * 8 + r8) * 80 + (t8 >> 1) * 16);
    const unsigned boff = (unsigned)((wn + (t8 >> 1) * 8 + r8) * 80 + (t8 & 1) * 16);

    const int T = K >> 5;
    load_slab(0, 0);
    load_slab(1, 32);

    for (int it = 0; it < T; it++) {
        asm volatile("cp.async.wait_group 1;" ::: "memory");
        __syncthreads();
        unsigned sb = sbase + (it & 1) * STAGEB;
        unsigned sAh = sb, sAl = sb + ABYTES, sBh = sb + 2 * ABYTES, sBl = sb + 3 * ABYTES;

#pragma unroll
        for (int ks = 0; ks < 2; ks++) {
            unsigned b_h[2][4], b_l[2][4], a_h[4][4];
#pragma unroll
            for (int ntp = 0; ntp < 2; ntp++) {
                LDSM4(b_h[ntp], sBh + boff + ntp * 1280 + ks * 32);
                LDSM4(b_l[ntp], sBl + boff + ntp * 1280 + ks * 32);
            }
#pragma unroll
            for (int mt = 0; mt < 4; mt++)
                LDSM4(a_h[mt], sAh + aoff + mt * 1280 + ks * 32);
#pragma unroll
            for (int mt = 0; mt < 4; mt++)
#pragma unroll
                for (int nt = 0; nt < 4; nt++)
                    MMA_BF16(acc[mt][nt], a_h[mt], b_h[nt >> 1][(nt & 1) * 2], b_h[nt >> 1][(nt & 1) * 2 + 1]);
#pragma unroll
            for (int mt = 0; mt < 4; mt++)
#pragma unroll
                for (int nt = 0; nt < 4; nt++)
                    MMA_BF16(acc[mt][nt], a_h[mt], b_l[nt >> 1][(nt & 1) * 2], b_l[nt >> 1][(nt & 1) * 2 + 1]);
#pragma unroll
            for (int mt = 0; mt < 4; mt++) {
                unsigned a_l[4];
                LDSM4(a_l, sAl + aoff + mt * 1280 + ks * 32);
#pragma unroll
                for (int nt = 0; nt < 4; nt++)
                    MMA_BF16(acc[mt][nt], a_l, b_h[nt >> 1][(nt & 1) * 2], b_h[nt >> 1][(nt & 1) * 2 + 1]);
            }
        }
        __syncthreads();
        if (it + 2 < T) load_slab(it & 1, (it + 2) * 32);
    }

    // ---- fused epilogue ----
#pragma unroll
    for (int mt = 0; mt < 4; mt++)
#pragma unroll
        for (int nt = 0; nt < 4; nt++) {
            int row = m0 + wm + mt * 16 + g;
            int col = n0 + wn + nt * 8 + tg * 2;
            if (n0 < NQD + NKVD) {
                const bool isQ = (n0 < NQD);
                const int cseg = isQ ? col : col - NQD;
                const int strd = isQ ? NQD : NKVD;
                __nv_bfloat16* Hh = isQ ? g_qh : g_kh;
                __nv_bfloat16* Ll = isQ ? g_ql : g_kl;
                const int pi = (cseg & 127) >> 1;
#pragma unroll
                for (int half = 0; half < 2; half++) {
                    int rr = row + half * 8;
                    float cs = cosb[rr * 64 + pi], sn = sinb[rr * 64 + pi];
                    float e = acc[mt][nt][half * 2], o = acc[mt][nt][half * 2 + 1];
                    float re = e * cs - o * sn;
                    float ro = e * sn + o * cs;
                    __nv_bfloat162 hp, lp;
                    __nv_bfloat16 hh, ll;
                    split2(re, hh, ll); hp.x = hh; lp.x = ll;
                    split2(ro, hh, ll); hp.y = hh; lp.y = ll;
                    *(__nv_bfloat162*)&Hh[(long)rr * strd + cseg] = hp;
                    *(__nv_bfloat162*)&Ll[(long)rr * strd + cseg] = lp;
                }
            } else {
                const int cv = col - (NQD + NKVD);
#pragma unroll
                for (int half = 0; half < 2; half++) {
                    int rr = row + half * 8;
#pragma unroll
                    for (int dc = 0; dc < 2; dc++) {
                        float v = acc[mt][nt][half * 2 + dc];
                        g_vt[(long)(cv + dc) * S_LEN + rr] = __float2half_rn(v);
                    }
                }
            }
        }
}

// ============================================================================
// O-projection GEMM (fp16, single pass), 3-stage cp.async pipeline.
// ============================================================================
#define OSTAGE (2 * ABYTES)
#define OSMEM  (3 * OSTAGE)

__global__ __launch_bounds__(256, 2) void gemm_o(
    const __half* __restrict__ Ah, const __half* __restrict__ Bh,
    float* __restrict__ C, int M, int N, int K)
{
    extern __shared__ char smem[];
    const int tid = threadIdx.x, lane = tid & 31, w = tid >> 5;
    const int g = lane >> 2, tg = lane & 3;
    const int t8 = lane >> 3, r8 = lane & 7;
    const int wm = (w & 1) * 64, wn = (w >> 1) * 32;
    const int m0 = blockIdx.y * 128, n0 = blockIdx.x * 128;
    const unsigned sbase = smem_u32(smem);

    auto load_slab = [&](int st, int kt) {
        unsigned s0 = sbase + st * OSTAGE;
#pragma unroll
        for (int i = 0; i < 2; i++) {
            int idx = tid + i * 256;
            int row = idx >> 2, c = idx & 3;
            unsigned so = (unsigned)(row * 80 + c * 16);
            long ea = (long)(m0 + row) * K + kt + c * 8;
            long eb = (long)(n0 + row) * K + kt + c * 8;
            cp_async16(s0 + so, Ah + ea);
            cp_async16(s0 + ABYTES + so, Bh + eb);
        }
        asm volatile("cp.async.commit_group;" ::: "memory");
    };

    float acc[4][4][4];
#pragma unroll
    for (int mt = 0; mt < 4; mt++)
#pragma unroll
        for (int nt = 0; nt < 4; nt++)
#pragma unroll
            for (int i = 0; i < 4; i++) acc[mt][nt][i] = 0.f;

    const unsigned aoff = (unsigned)((wm + (t8 & 1) * 8 + r8) * 80 + (t8 >> 1) * 16);
    const unsigned boff = (unsigned)((wn + (t8 >> 1) * 8 + r8) * 80 + (t8 & 1) * 16);

    const int T = K >> 5;
    load_slab(0, 0);
    load_slab(1, 32);
    load_slab(2, 64);

    int st = 0;
    for (int it = 0; it < T; it++) {
        asm volatile("cp.async.wait_group 2;" ::: "memory");
        __syncthreads();
        unsigned sb = sbase + st * OSTAGE;
        unsigned sAh = sb, sBh = sb + ABYTES;

#pragma unroll
        for (int ks = 0; ks < 2; ks++) {
            unsigned b_h[2][4], a_h[4][4];
#pragma unroll
            for (int ntp = 0; ntp < 2; ntp++)
                LDSM4(b_h[ntp], sBh + boff + ntp * 1280 + ks * 32);
#pragma unroll
            for (int mt = 0; mt < 4; mt++)
                LDSM4(a_h[mt], sAh + aoff + mt * 1280 + ks * 32);
#pragma unroll
            for (int mt = 0; mt < 4; mt++)
#pragma unroll
                for (int nt = 0; nt < 4; nt++)
                    MMA_F16(acc[mt][nt], a_h[mt], b_h[nt >> 1][(nt & 1) * 2], b_h[nt >> 1][(nt & 1) * 2 + 1]);
        }
        __syncthreads();
        if (it + 3 < T) load_slab(st, (it + 3) * 32);
        else asm volatile("cp.async.commit_group;" ::: "memory");
        st = (st == 2) ? 0 : st + 1;
    }

#pragma unroll
    for (int mt = 0; mt < 4; mt++)
#pragma unroll
        for (int nt = 0; nt < 4; nt++) {
            int row = m0 + wm + mt * 16 + g;
            int col = n0 + wn + nt * 8 + tg * 2;
            float2 v0 = {acc[mt][nt][0], acc[mt][nt][1]};
            float2 v1 = {acc[mt][nt][2], acc[mt][nt][3]};
            *(float2*)&C[(long)row * N + col] = v0;
            *(float2*)&C[(long)(row + 8) * N + col] = v1;
        }
}

// ============================================================================
// flash attention: QK bf16 3-pass; PV fp16 1-pass.
// Q fragments hoisted to registers; K/V double-buffered via cp.async.
// BQ=BK=64, 128 thr (4 warps). Heavy-first scheduling.
// smem: 2 KV stages, each [Kh 64x272 | Kl 64x272 | V 128x144] = 53248 B.
// ============================================================================
#define AQ_STB 272
#define AV_STB 144
#define KVKH   0
#define KVKL   17408
#define KVV    34816
#define KVSTG  53248
#define ASMEM  (2 * KVSTG)   // 106496

__global__ __launch_bounds__(128) void attn_mma()
{
    extern __shared__ char smem[];
    const unsigned sb = smem_u32(smem);
    const int tid = threadIdx.x, lane = tid & 31, w = tid >> 5;
    const int g = lane >> 2, tg = lane & 3;
    const int t8 = lane >> 3, r8 = lane & 7;
    const int qt = (int)gridDim.x - 1 - (int)blockIdx.x;   // heavy tiles first
    const int q0 = qt * 64, h = blockIdx.y, kvh = h >> 2;

    const unsigned aoffQ = (unsigned)((w * 16 + (t8 & 1) * 8 + r8) * AQ_STB + (t8 >> 1) * 16);
    const unsigned boffK = (unsigned)(((t8 >> 1) * 8 + r8) * AQ_STB + (t8 & 1) * 16);
    const unsigned boffV = (unsigned)(((t8 >> 1) * 8 + r8) * AV_STB + (t8 & 1) * 16);

    // ---- stage Q into smem (stage-0 area), pull fragments to registers ----
#pragma unroll
    for (int i = 0; i < 8; i++) {
        int idx = tid + i * 128;
        int row = idx >> 4, c = idx & 15;
        long gq = (long)(q0 + row) * NQD + h * HD + c * 8;
        unsigned so = (unsigned)(row * AQ_STB + c * 16);
        *(uint4*)(smem + so) = *(const uint4*)&g_qh[gq];
        *(uint4*)(smem + KVKL + so) = *(const uint4*)&g_ql[gq];
    }
    __syncthreads();
    unsigned qa[8][4], qla[8][4];
#pragma unroll
    for (int ks = 0; ks < 8; ks++) {
        LDSM4(qa[ks], sb + aoffQ + ks * 32);
        LDSM4(qla[ks], sb + KVKL + aoffQ + ks * 32);
    }
    __syncthreads();

    float oacc[16][4];
#pragma unroll
    for (int nt = 0; nt < 16; nt++)
#pragma unroll
        for (int i = 0; i < 4; i++) oacc[nt][i] = 0.f;
    float m_lo = -1e30f, m_hi = -1e30f, l_lo = 0.f, l_hi = 0.f;

    const int qg_lo = q0 + w * 16 + g;
    const int qg_hi = qg_lo + 8;
    int lo = q0 - (WINDOW - 1);
    const int kt_lo = lo > 0 ? (lo >> 6) : 0;
    const int kt_hi = qt;
    const float scale = 0.08838834764831845f;

    // ---- K/V tile loader (cp.async) ----
    auto load_kv = [&](int st, int kt) {
        unsigned s0 = sb + st * KVSTG;
        const int k0 = kt * 64;
#pragma unroll
        for (int i = 0; i < 8; i++) {
            int idx = tid + i * 128;
            int row = idx >> 4, c = idx & 15;
            long gk = (long)(k0 + row) * NKVD + kvh * HD + c * 8;
            unsigned so = (unsigned)(row * AQ_STB + c * 16);
            cp_async16(s0 + KVKH + so, &g_kh[gk]);
            cp_async16(s0 + KVKL + so, &g_kl[gk]);
            int vrow = idx >> 3, vc = idx & 7;
            long gv = (long)(kvh * HD + vrow) * S_LEN + k0 + vc * 8;
            cp_async16(s0 + KVV + (unsigned)(vrow * AV_STB + vc * 16), &g_vt[gv]);
        }
        asm volatile("cp.async.commit_group;" ::: "memory");
    };

    load_kv(0, kt_lo);
    if (kt_lo + 1 <= kt_hi) load_kv(1, kt_lo + 1);
    else asm volatile("cp.async.commit_group;" ::: "memory");

    for (int kt = kt_lo; kt <= kt_hi; kt++) {
        const int j = kt - kt_lo;
        const int k0 = kt * 64;
        asm volatile("cp.async.wait_group 1;" ::: "memory");
        __syncthreads();
        const unsigned s0 = sb + (j & 1) * KVSTG;

        float sacc[8][4];
#pragma unroll
        for (int nt = 0; nt < 8; nt++)
#pragma unroll
            for (int i = 0; i < 4; i++) sacc[nt][i] = 0.f;

#pragma unroll
        for (int ks = 0; ks < 8; ks++) {
            unsigned kb[4][4], kbl[4][4];
#pragma unroll
            for (int ntp = 0; ntp < 4; ntp++) {
                LDSM4(kb[ntp], s0 + KVKH + boffK + ntp * (16 * AQ_STB) + ks * 32);
                LDSM4(kbl[ntp], s0 + KVKL + boffK + ntp * (16 * AQ_STB) + ks * 32);
            }
#pragma unroll
            for (int nt = 0; nt < 8; nt++)
                MMA_BF16(sacc[nt], qa[ks], kb[nt >> 1][(nt & 1) * 2], kb[nt >> 1][(nt & 1) * 2 + 1]);
#pragma unroll
            for (int nt = 0; nt < 8; nt++)
                MMA_BF16(sacc[nt], qla[ks], kb[nt >> 1][(nt & 1) * 2], kb[nt >> 1][(nt & 1) * 2 + 1]);
#pragma unroll
            for (int nt = 0; nt < 8; nt++)
                MMA_BF16(sacc[nt], qa[ks], kbl[nt >> 1][(nt & 1) * 2], kbl[nt >> 1][(nt & 1) * 2 + 1]);
        }

#pragma unroll
        for (int nt = 0; nt < 8; nt++) {
            int kg0 = k0 + nt * 8 + tg * 2, kg1 = kg0 + 1;
            int d00 = qg_lo - kg0, d01 = qg_lo - kg1;
            int d10 = qg_hi - kg0, d11 = qg_hi - kg1;
            sacc[nt][0] = (d00 >= 0 && d00 < WINDOW) ? sacc[nt][0] * scale : -1e30f;
            sacc[nt][1] = (d01 >= 0 && d01 < WINDOW) ? sacc[nt][1] * scale : -1e30f;
            sacc[nt][2] = (d10 >= 0 && d10 < WINDOW) ? sacc[nt][2] * scale : -1e30f;
            sacc[nt][3] = (d11 >= 0 && d11 < WINDOW) ? sacc[nt][3] * scale : -1e30f;
        }

        float mx0 = -1e30f, mx1 = -1e30f;
#pragma unroll
        for (int nt = 0; nt < 8; nt++) {
            mx0 = fmaxf(mx0, fmaxf(sacc[nt][0], sacc[nt][1]));
            mx1 = fmaxf(mx1, fmaxf(sacc[nt][2], sacc[nt][3]));
        }
        mx0 = fmaxf(mx0, __shfl_xor_sync(0xffffffffu, mx0, 1));
        mx0 = fmaxf(mx0, __shfl_xor_sync(0xffffffffu, mx0, 2));
        mx1 = fmaxf(mx1, __shfl_xor_sync(0xffffffffu, mx1, 1));
        mx1 = fmaxf(mx1, __shfl_xor_sync(0xffffffffu, mx1, 2));
        float mn0 = fmaxf(m_lo, mx0), mn1 = fmaxf(m_hi, mx1);
        float al0 = __expf(m_lo - mn0), al1 = __expf(m_hi - mn1);
        float ps0 = 0.f, ps1 = 0.f;
#pragma unroll
        for (int nt = 0; nt < 8; nt++) {
            float p0 = (sacc[nt][0] > -1e29f) ? __expf(sacc[nt][0] - mn0) : 0.f;
            float p1 = (sacc[nt][1] > -1e29f) ? __expf(sacc[nt][1] - mn0) : 0.f;
            float p2 = (sacc[nt][2] > -1e29f) ? __expf(sacc[nt][2] - mn1) : 0.f;
            float p3 = (sacc[nt][3] > -1e29f) ? __expf(sacc[nt][3] - mn1) : 0.f;
            sacc[nt][0] = p0; sacc[nt][1] = p1; sacc[nt][2] = p2; sacc[nt][3] = p3;
            ps0 += p0 + p1;
            ps1 += p2 + p3;
        }
        ps0 += __shfl_xor_sync(0xffffffffu, ps0, 1);
        ps0 += __shfl_xor_sync(0xffffffffu, ps0, 2);
        ps1 += __shfl_xor_sync(0xffffffffu, ps1, 1);
        ps1 += __shfl_xor_sync(0xffffffffu, ps1, 2);
        l_lo = l_lo * al0 + ps0; m_lo = mn0;
        l_hi = l_hi * al1 + ps1; m_hi = mn1;
#pragma unroll
        for (int nt = 0; nt < 16; nt++) {
            oacc[nt][0] *= al0; oacc[nt][1] *= al0;
            oacc[nt][2] *= al1; oacc[nt][3] *= al1;
        }

        // ---- O += P V (P single fp16, V single fp16) ----
#pragma unroll
        for (int kv = 0; kv < 4; kv++) {
            unsigned pa[4];
            {
                __half2 h0, h1, h2, h3;
                h0.x = __float2half_rn(sacc[2 * kv][0]);
                h0.y = __float2half_rn(sacc[2 * kv][1]);
                h1.x = __float2half_rn(sacc[2 * kv][2]);
                h1.y = __float2half_rn(sacc[2 * kv][3]);
                h2.x = __float2half_rn(sacc[2 * kv + 1][0]);
                h2.y = __float2half_rn(sacc[2 * kv + 1][1]);
                h3.x = __float2half_rn(sacc[2 * kv + 1][2]);
                h3.y = __float2half_rn(sacc[2 * kv + 1][3]);
                pa[0] = *(unsigned*)&h0; pa[1] = *(unsigned*)&h1;
                pa[2] = *(unsigned*)&h2; pa[3] = *(unsigned*)&h3;
            }
#pragma unroll
            for (int half = 0; half < 2; half++) {
                unsigned vbh[4][4];
#pragma unroll
                for (int ntp = 0; ntp < 4; ntp++)
                    LDSM4(vbh[ntp], s0 + KVV + boffV + (half * 4 + ntp) * (16 * AV_STB) + kv * 32);
#pragma unroll
                for (int nt = 0; nt < 8; nt++)
                    MMA_F16(oacc[half * 8 + nt], pa, vbh[nt >> 1][(nt & 1) * 2], vbh[nt >> 1][(nt & 1) * 2 + 1]);
            }
        }
        __syncthreads();
        if (kt + 2 <= kt_hi) load_kv(j & 1, kt + 2);
        else asm volatile("cp.async.commit_group;" ::: "memory");
    }

    // ---- epilogue: normalize + single fp16 out ----
    float inv0 = 1.f / l_lo, inv1 = 1.f / l_hi;
#pragma unroll
    for (int nt = 0; nt < 16; nt++) {
        int col = h * HD + nt * 8 + tg * 2;
        __half2 hp;
        hp.x = __float2half_rn(oacc[nt][0] * inv0);
        hp.y = __float2half_rn(oacc[nt][1] * inv0);
        *(__half2*)&g_at[(long)qg_lo * NQD + col] = hp;
        hp.x = __float2half_rn(oacc[nt][2] * inv1);
        hp.y = __float2half_rn(oacc[nt][3] * inv1);
        *(__half2*)&g_at[(long)qg_hi * NQD + col] = hp;
    }
}

// ============================================================================
extern "C" void kernel_launch(void* const* d_in, const int* in_sizes, int n_in,
                              void* d_out, int out_size)
{
    const float* x   = (const float*)d_in[0];
    const float* fc  = (const float*)d_in[1];
    const float* fs  = (const float*)d_in[2];
    // d_in[3]: mask — unused (causal + sliding window computed analytically)
    const float* w_q = (const float*)d_in[4];
    const float* w_k = (const float*)d_in[5];
    const float* w_v = (const float*)d_in[6];
    const float* w_o = (const float*)d_in[7];
    float* out = (float*)d_out;

    __nv_bfloat16 *xh, *xl, *wch, *wcl;
    __half *at, *woh;
    cudaGetSymbolAddress((void**)&xh, g_xh);   cudaGetSymbolAddress((void**)&xl, g_xl);
    cudaGetSymbolAddress((void**)&at, g_at);
    cudaGetSymbolAddress((void**)&wch, g_wch); cudaGetSymbolAddress((void**)&wcl, g_wcl);
    cudaGetSymbolAddress((void**)&woh, g_woh);

    cudaFuncSetAttribute(gemm_qkv, cudaFuncAttributeMaxDynamicSharedMemorySize, GSMEM);
    cudaFuncSetAttribute(gemm_o, cudaFuncAttributeMaxDynamicSharedMemorySize, OSMEM);
    cudaFuncSetAttribute(attn_mma, cudaFuncAttributeMaxDynamicSharedMemorySize, ASMEM);

    // one-time operand prep
    cvt_hl<<<(S_LEN * D_MODEL / 4 + 255) / 256, 256>>>(x, xh, xl, S_LEN * D_MODEL);
    transpose_hl<<<dim3(NQD / 32, D_MODEL / 32), dim3(32, 8)>>>(
        w_q, wch, wcl, D_MODEL, NQD);
    transpose_hl<<<dim3(NKVD / 32, D_MODEL / 32), dim3(32, 8)>>>(
        w_k, wch + (long)NQD * D_MODEL, wcl + (long)NQD * D_MODEL, D_MODEL, NKVD);
    transpose_hl<<<dim3(NKVD / 32, D_MODEL / 32), dim3(32, 8)>>>(
        w_v, wch + (long)(NQD + NKVD) * D_MODEL, wcl + (long)(NQD + NKVD) * D_MODEL, D_MODEL, NKVD);
    transpose_h<<<dim3(D_MODEL / 32, NQD / 32), dim3(32, 8)>>>(w_o, woh, NQD, D_MODEL);

    // fused QKV projection (bf16 3-pass; fused rope / rope / v-transpose epilogue)
    gemm_qkv<<<dim3(NCAT / 128, S_LEN / 128), 256, GSMEM>>>(
        xh, xl, wch, wcl, fc, fs, S_LEN, NCAT, D_MODEL);

    // attention (QK bf16 3-pass, PV fp16 1-pass; Q in regs, K/V cp.async pipelined)
    attn_mma<<<dim3(S_LEN / 64, NQ), 128, ASMEM>>>();

    // output projection (fp16 1-pass, 3-stage pipeline)
    gemm_o<<<dim3(D_MODEL / 128, S_LEN / 128), 256, OSMEM>>>(
        at, woh, out, S_LEN, D_MODEL, NQD);
}

// round 17
// speedup vs baseline: 8.0227x; 1.2268x over previous
#include <cuda_runtime.h>
#include <cuda_bf16.h>
#include <cuda_fp16.h>
#include <cstdint>

#define S_LEN   2048
#define D_MODEL 4096
#define NQ      32
#define NKV     8
#define HD      128
#define WINDOW  1024
#define NQD     (NQ*HD)    // 4096
#define NKVD    (NKV*HD)   // 1024
#define NCAT    (NQD + 2*NKVD)  // 6144 fused QKV output width

// ---- operands ----
__device__ __half        g_xh[S_LEN * D_MODEL],  g_xl[S_LEN * D_MODEL]; // x fp16 hi/lo
__device__ __half        g_at[S_LEN * NQD];                             // attn out fp16
__device__ __nv_bfloat16 g_qh[S_LEN * NQD],      g_ql[S_LEN * NQD];     // Q bf16 hi/lo
__device__ __nv_bfloat16 g_kh[S_LEN * NKVD],     g_kl[S_LEN * NKVD];    // K bf16 hi/lo
__device__ __half        g_vt[NKVD * S_LEN];                            // V fp16 [hd][seq]
__device__ __half        g_wc[NCAT * D_MODEL];                          // [wq;wk;wv] fp16 [N][K]
__device__ __half        g_woh[D_MODEL * NQD];                          // w_o fp16 [N][K]

// ============================================================================
// helpers
// ============================================================================
__device__ __forceinline__ unsigned smem_u32(const void* p) {
    unsigned a;
    asm("{ .reg .u64 t; cvta.to.shared.u64 t, %1; cvt.u32.u64 %0, t; }" : "=r"(a) : "l"(p));
    return a;
}
__device__ __forceinline__ void cp_async16(unsigned s, const void* g) {
    asm volatile("cp.async.cg.shared.global [%0], [%1], 16;" :: "r"(s), "l"(g) : "memory");
}
__device__ __forceinline__ void split2(float v, __nv_bfloat16& h, __nv_bfloat16& l) {
    h = __float2bfloat16_rn(v);
    l = __float2bfloat16_rn(v - __bfloat162float(h));
}
__device__ __forceinline__ void split2h(float v, __half& h, __half& l) {
    h = __float2half_rn(v);
    l = __float2half_rn(v - __half2float(h));
}

#define MMA_BF16(acc, a, b0v, b1v)                                            \
    asm volatile(                                                             \
        "mma.sync.aligned.m16n8k16.row.col.f32.bf16.bf16.f32 "                \
        "{%0,%1,%2,%3},{%4,%5,%6,%7},{%8,%9},{%0,%1,%2,%3};"                  \
        : "+f"(acc[0]), "+f"(acc[1]), "+f"(acc[2]), "+f"(acc[3])              \
        : "r"(a[0]), "r"(a[1]), "r"(a[2]), "r"(a[3]), "r"(b0v), "r"(b1v))

#define MMA_F16(acc, a, b0v, b1v)                                             \
    asm volatile(                                                             \
        "mma.sync.aligned.m16n8k16.row.col.f32.f16.f16.f32 "                  \
        "{%0,%1,%2,%3},{%4,%5,%6,%7},{%8,%9},{%0,%1,%2,%3};"                  \
        : "+f"(acc[0]), "+f"(acc[1]), "+f"(acc[2]), "+f"(acc[3])              \
        : "r"(a[0]), "r"(a[1]), "r"(a[2]), "r"(a[3]), "r"(b0v), "r"(b1v))

#define LDSM4(r, addr)                                                        \
    asm volatile("ldmatrix.sync.aligned.m8n8.x4.shared.b16 {%0,%1,%2,%3}, [%4];" \
        : "=r"((r)[0]), "=r"((r)[1]), "=r"((r)[2]), "=r"((r)[3]) : "r"(addr))

// ============================================================================
// one-time converts
// ============================================================================
__global__ void cvt_hl16(const float* __restrict__ in, __half* __restrict__ ho,
                         __half* __restrict__ lo, int n) {
    int i = (blockIdx.x * blockDim.x + threadIdx.x) * 4;
    if (i >= n) return;
    float4 v = *(const float4*)&in[i];
    __align__(8) __half h[4], l[4];
    split2h(v.x, h[0], l[0]);
    split2h(v.y, h[1], l[1]);
    split2h(v.z, h[2], l[2]);
    split2h(v.w, h[3], l[3]);
    *(uint2*)&ho[i] = *(uint2*)h;
    *(uint2*)&lo[i] = *(uint2*)l;
}

// weights: w[K][N] fp32 -> th[N][K] fp16 single (transpose)
__global__ void transpose_h(const float* __restrict__ w, __half* __restrict__ th,
                            int K, int N) {
    __shared__ float t[32][33];
    int n0 = blockIdx.x * 32, k0 = blockIdx.y * 32;
    int tx = threadIdx.x, ty = threadIdx.y;   // 32 x 8
#pragma unroll
    for (int i = 0; i < 32; i += 8)
        t[ty + i][tx] = w[(k0 + ty + i) * N + n0 + tx];
    __syncthreads();
#pragma unroll
    for (int i = 0; i < 32; i += 8)
        th[(n0 + ty + i) * K + k0 + tx] = __float2half_rn(t[tx][ty + i]);
}

// ============================================================================
// QKV GEMM (fp16 2-pass: xh*w + xl*w, w single fp16). 128x128 tile, K-slab 32,
// 256 thr, 2 CTAs/SM, 3-stage cp.async pipeline. L2-rasterized block order.
// Fused epilogue by n-segment: Q rope / K rope / V->fp16 transpose.
// ============================================================================
#define ABYTES 10240
#define QSTAGE (3 * ABYTES)
#define GSMEM  (3 * QSTAGE)    // 92160

__global__ __launch_bounds__(256, 2) void gemm_qkv(
    const __half* __restrict__ Ah, const __half* __restrict__ Al,
    const __half* __restrict__ Bh,
    const float* __restrict__ cosb, const float* __restrict__ sinb,
    int M, int N, int K)
{
    extern __shared__ char smem[];
    const int tid = threadIdx.x, lane = tid & 31, w = tid >> 5;
    const int g = lane >> 2, tg = lane & 3;
    const int t8 = lane >> 3, r8 = lane & 7;
    const int wm = (w & 1) * 64, wn = (w >> 1) * 32;
    const int bid = blockIdx.y * gridDim.x + blockIdx.x;
    const int gsz = 8 * gridDim.y;
    const int grp = bid / gsz, rem = bid % gsz;
    const int m0 = (rem >> 3) * 128, n0 = (grp * 8 + (rem & 7)) * 128;
    const unsigned sbase = smem_u32(smem);

    auto load_slab = [&](int st, int kt) {
        unsigned s0 = sbase + st * QSTAGE;
#pragma unroll
        for (int i = 0; i < 2; i++) {
            int idx = tid + i * 256;
            int row = idx >> 2, c = idx & 3;
            unsigned so = (unsigned)(row * 80 + c * 16);
            long ea = (long)(m0 + row) * K + kt + c * 8;
            long eb = (long)(n0 + row) * K + kt + c * 8;
            cp_async16(s0 + so, Ah + ea);
            cp_async16(s0 + ABYTES + so, Al + ea);
            cp_async16(s0 + 2 * ABYTES + so, Bh + eb);
        }
        asm volatile("cp.async.commit_group;" ::: "memory");
    };

    float acc[4][4][4];
#pragma unroll
    for (int mt = 0; mt < 4; mt++)
#pragma unroll
        for (int nt = 0; nt < 4; nt++)
#pragma unroll
            for (int i = 0; i < 4; i++) acc[mt][nt][i] = 0.f;

    const unsigned aoff = (unsigned)((wm + (t8 & 1) * 8 + r8) * 80 + (t8 >> 1) * 16);
    const unsigned boff = (unsigned)((wn + (t8 >> 1) * 8 + r8) * 80 + (t8 & 1) * 16);

    const int T = K >> 5;
    load_slab(0, 0);
    load_slab(1, 32);
    load_slab(2, 64);

    int st = 0;
    for (int it = 0; it < T; it++) {
        asm volatile("cp.async.wait_group 2;" ::: "memory");
        __syncthreads();
        unsigned sb = sbase + st * QSTAGE;
        unsigned sAh = sb, sAl = sb + ABYTES, sBh = sb + 2 * ABYTES;

#pragma unroll
        for (int ks = 0; ks < 2; ks++) {
            unsigned b_h[2][4], a_h[4][4];
#pragma unroll
            for (int ntp = 0; ntp < 2; ntp++)
                LDSM4(b_h[ntp], sBh + boff + ntp * 1280 + ks * 32);
#pragma unroll
            for (int mt = 0; mt < 4; mt++)
                LDSM4(a_h[mt], sAh + aoff + mt * 1280 + ks * 32);
            // pass 1: xh * w
#pragma unroll
            for (int mt = 0; mt < 4; mt++)
#pragma unroll
                for (int nt = 0; nt < 4; nt++)
                    MMA_F16(acc[mt][nt], a_h[mt], b_h[nt >> 1][(nt & 1) * 2], b_h[nt >> 1][(nt & 1) * 2 + 1]);
            // pass 2: xl * w (reload per-mt for reg diet)
#pragma unroll
            for (int mt = 0; mt < 4; mt++) {
                unsigned a_l[4];
                LDSM4(a_l, sAl + aoff + mt * 1280 + ks * 32);
#pragma unroll
                for (int nt = 0; nt < 4; nt++)
                    MMA_F16(acc[mt][nt], a_l, b_h[nt >> 1][(nt & 1) * 2], b_h[nt >> 1][(nt & 1) * 2 + 1]);
            }
        }
        __syncthreads();
        if (it + 3 < T) load_slab(st, (it + 3) * 32);
        else asm volatile("cp.async.commit_group;" ::: "memory");
        st = (st == 2) ? 0 : st + 1;
    }

    // ---- fused epilogue ----
#pragma unroll
    for (int mt = 0; mt < 4; mt++)
#pragma unroll
        for (int nt = 0; nt < 4; nt++) {
            int row = m0 + wm + mt * 16 + g;
            int col = n0 + wn + nt * 8 + tg * 2;
            if (n0 < NQD + NKVD) {
                // Q or K segment: fused RoPE + bf16 hi/lo split
                const bool isQ = (n0 < NQD);
                const int cseg = isQ ? col : col - NQD;
                const int strd = isQ ? NQD : NKVD;
                __nv_bfloat16* Hh = isQ ? g_qh : g_kh;
                __nv_bfloat16* Ll = isQ ? g_ql : g_kl;
                const int pi = (cseg & 127) >> 1;
#pragma unroll
                for (int half = 0; half < 2; half++) {
                    int rr = row + half * 8;
                    float cs = cosb[rr * 64 + pi], sn = sinb[rr * 64 + pi];
                    float e = acc[mt][nt][half * 2], o = acc[mt][nt][half * 2 + 1];
                    float re = e * cs - o * sn;
                    float ro = e * sn + o * cs;
                    __nv_bfloat162 hp, lp;
                    __nv_bfloat16 hh, ll;
                    split2(re, hh, ll); hp.x = hh; lp.x = ll;
                    split2(ro, hh, ll); hp.y = hh; lp.y = ll;
                    *(__nv_bfloat162*)&Hh[(long)rr * strd + cseg] = hp;
                    *(__nv_bfloat162*)&Ll[(long)rr * strd + cseg] = lp;
                }
            } else {
                // V segment: transpose + single fp16 -> [hd][seq]
                const int cv = col - (NQD + NKVD);
#pragma unroll
                for (int half = 0; half < 2; half++) {
                    int rr = row + half * 8;
#pragma unroll
                    for (int dc = 0; dc < 2; dc++) {
                        float v = acc[mt][nt][half * 2 + dc];
                        g_vt[(long)(cv + dc) * S_LEN + rr] = __float2half_rn(v);
                    }
                }
            }
        }
}

// ============================================================================
// O-projection GEMM (fp16, single pass), 3-stage cp.async pipeline.
// ============================================================================
#define OSTAGE (2 * ABYTES)
#define OSMEM  (3 * OSTAGE)

__global__ __launch_bounds__(256, 2) void gemm_o(
    const __half* __restrict__ Ah, const __half* __restrict__ Bh,
    float* __restrict__ C, int M, int N, int K)
{
    extern __shared__ char smem[];
    const int tid = threadIdx.x, lane = tid & 31, w = tid >> 5;
    const int g = lane >> 2, tg = lane & 3;
    const int t8 = lane >> 3, r8 = lane & 7;
    const int wm = (w & 1) * 64, wn = (w >> 1) * 32;
    const int m0 = blockIdx.y * 128, n0 = blockIdx.x * 128;
    const unsigned sbase = smem_u32(smem);

    auto load_slab = [&](int st, int kt) {
        unsigned s0 = sbase + st * OSTAGE;
#pragma unroll
        for (int i = 0; i < 2; i++) {
            int idx = tid + i * 256;
            int row = idx >> 2, c = idx & 3;
            unsigned so = (unsigned)(row * 80 + c * 16);
            long ea = (long)(m0 + row) * K + kt + c * 8;
            long eb = (long)(n0 + row) * K + kt + c * 8;
            cp_async16(s0 + so, Ah + ea);
            cp_async16(s0 + ABYTES + so, Bh + eb);
        }
        asm volatile("cp.async.commit_group;" ::: "memory");
    };

    float acc[4][4][4];
#pragma unroll
    for (int mt = 0; mt < 4; mt++)
#pragma unroll
        for (int nt = 0; nt < 4; nt++)
#pragma unroll
            for (int i = 0; i < 4; i++) acc[mt][nt][i] = 0.f;

    const unsigned aoff = (unsigned)((wm + (t8 & 1) * 8 + r8) * 80 + (t8 >> 1) * 16);
    const unsigned boff = (unsigned)((wn + (t8 >> 1) * 8 + r8) * 80 + (t8 & 1) * 16);

    const int T = K >> 5;
    load_slab(0, 0);
    load_slab(1, 32);
    load_slab(2, 64);

    int st = 0;
    for (int it = 0; it < T; it++) {
        asm volatile("cp.async.wait_group 2;" ::: "memory");
        __syncthreads();
        unsigned sb = sbase + st * OSTAGE;
        unsigned sAh = sb, sBh = sb + ABYTES;

#pragma unroll
        for (int ks = 0; ks < 2; ks++) {
            unsigned b_h[2][4], a_h[4][4];
#pragma unroll
            for (int ntp = 0; ntp < 2; ntp++)
                LDSM4(b_h[ntp], sBh + boff + ntp * 1280 + ks * 32);
#pragma unroll
            for (int mt = 0; mt < 4; mt++)
                LDSM4(a_h[mt], sAh + aoff + mt * 1280 + ks * 32);
#pragma unroll
            for (int mt = 0; mt < 4; mt++)
#pragma unroll
                for (int nt = 0; nt < 4; nt++)
                    MMA_F16(acc[mt][nt], a_h[mt], b_h[nt >> 1][(nt & 1) * 2], b_h[nt >> 1][(nt & 1) * 2 + 1]);
        }
        __syncthreads();
        if (it + 3 < T) load_slab(st, (it + 3) * 32);
        else asm volatile("cp.async.commit_group;" ::: "memory");
        st = (st == 2) ? 0 : st + 1;
    }

#pragma unroll
    for (int mt = 0; mt < 4; mt++)
#pragma unroll
        for (int nt = 0; nt < 4; nt++) {
            int row = m0 + wm + mt * 16 + g;
            int col = n0 + wn + nt * 8 + tg * 2;
            float2 v0 = {acc[mt][nt][0], acc[mt][nt][1]};
            float2 v1 = {acc[mt][nt][2], acc[mt][nt][3]};
            *(float2*)&C[(long)row * N + col] = v0;
            *(float2*)&C[(long)(row + 8) * N + col] = v1;
        }
}

// ============================================================================
// flash attention: QK bf16 3-pass; PV fp16 1-pass.
// Q fragments in registers; K/V double-buffered via cp.async.
// BQ=BK=64, 128 thr (4 warps). Heavy-first scheduling.
// ============================================================================
#define AQ_STB 272
#define AV_STB 144
#define KVKH   0
#define KVKL   17408
#define KVV    34816
#define KVSTG  53248
#define ASMEM  (2 * KVSTG)   // 106496

__global__ __launch_bounds__(128) void attn_mma()
{
    extern __shared__ char smem[];
    const unsigned sb = smem_u32(smem);
    const int tid = threadIdx.x, lane = tid & 31, w = tid >> 5;
    const int g = lane >> 2, tg = lane & 3;
    const int t8 = lane >> 3, r8 = lane & 7;
    const int qt = (int)gridDim.x - 1 - (int)blockIdx.x;   // heavy tiles first
    const int q0 = qt * 64, h = blockIdx.y, kvh = h >> 2;

    const unsigned aoffQ = (unsigned)((w * 16 + (t8 & 1) * 8 + r8) * AQ_STB + (t8 >> 1) * 16);
    const unsigned boffK = (unsigned)(((t8 >> 1) * 8 + r8) * AQ_STB + (t8 & 1) * 16);
    const unsigned boffV = (unsigned)(((t8 >> 1) * 8 + r8) * AV_STB + (t8 & 1) * 16);

    // ---- stage Q via smem, pull fragments to registers ----
#pragma unroll
    for (int i = 0; i < 8; i++) {
        int idx = tid + i * 128;
        int row = idx >> 4, c = idx & 15;
        long gq = (long)(q0 + row) * NQD + h * HD + c * 8;
        unsigned so = (unsigned)(row * AQ_STB + c * 16);
        *(uint4*)(smem + so) = *(const uint4*)&g_qh[gq];
        *(uint4*)(smem + KVKL + so) = *(const uint4*)&g_ql[gq];
    }
    __syncthreads();
    unsigned qa[8][4], qla[8][4];
#pragma unroll
    for (int ks = 0; ks < 8; ks++) {
        LDSM4(qa[ks], sb + aoffQ + ks * 32);
        LDSM4(qla[ks], sb + KVKL + aoffQ + ks * 32);
    }
    __syncthreads();

    float oacc[16][4];
#pragma unroll
    for (int nt = 0; nt < 16; nt++)
#pragma unroll
        for (int i = 0; i < 4; i++) oacc[nt][i] = 0.f;
    float m_lo = -1e30f, m_hi = -1e30f, l_lo = 0.f, l_hi = 0.f;

    const int qg_lo = q0 + w * 16 + g;
    const int qg_hi = qg_lo + 8;
    int lo = q0 - (WINDOW - 1);
    const int kt_lo = lo > 0 ? (lo >> 6) : 0;
    const int kt_hi = qt;
    const float scale = 0.08838834764831845f;

    auto load_kv = [&](int st, int kt) {
        unsigned s0 = sb + st * KVSTG;
        const int k0 = kt * 64;
#pragma unroll
        for (int i = 0; i < 8; i++) {
            int idx = tid + i * 128;
            int row = idx >> 4, c = idx & 15;
            long gk = (long)(k0 + row) * NKVD + kvh * HD + c * 8;
            unsigned so = (unsigned)(row * AQ_STB + c * 16);
            cp_async16(s0 + KVKH + so, &g_kh[gk]);
            cp_async16(s0 + KVKL + so, &g_kl[gk]);
            int vrow = idx >> 3, vc = idx & 7;
            long gv = (long)(kvh * HD + vrow) * S_LEN + k0 + vc * 8;
            cp_async16(s0 + KVV + (unsigned)(vrow * AV_STB + vc * 16), &g_vt[gv]);
        }
        asm volatile("cp.async.commit_group;" ::: "memory");
    };

    load_kv(0, kt_lo);
    if (kt_lo + 1 <= kt_hi) load_kv(1, kt_lo + 1);
    else asm volatile("cp.async.commit_group;" ::: "memory");

    for (int kt = kt_lo; kt <= kt_hi; kt++) {
        const int j = kt - kt_lo;
        const int k0 = kt * 64;
        asm volatile("cp.async.wait_group 1;" ::: "memory");
        __syncthreads();
        const unsigned s0 = sb + (j & 1) * KVSTG;

        float sacc[8][4];
#pragma unroll
        for (int nt = 0; nt < 8; nt++)
#pragma unroll
            for (int i = 0; i < 4; i++) sacc[nt][i] = 0.f;

#pragma unroll
        for (int ks = 0; ks < 8; ks++) {
            unsigned kb[4][4], kbl[4][4];
#pragma unroll
            for (int ntp = 0; ntp < 4; ntp++) {
                LDSM4(kb[ntp], s0 + KVKH + boffK + ntp * (16 * AQ_STB) + ks * 32);
                LDSM4(kbl[ntp], s0 + KVKL + boffK + ntp * (16 * AQ_STB) + ks * 32);
            }
#pragma unroll
            for (int nt = 0; nt < 8; nt++)
                MMA_BF16(sacc[nt], qa[ks], kb[nt >> 1][(nt & 1) * 2], kb[nt >> 1][(nt & 1) * 2 + 1]);
#pragma unroll
            for (int nt = 0; nt < 8; nt++)
                MMA_BF16(sacc[nt], qla[ks], kb[nt >> 1][(nt & 1) * 2], kb[nt >> 1][(nt & 1) * 2 + 1]);
#pragma unroll
            for (int nt = 0; nt < 8; nt++)
                MMA_BF16(sacc[nt], qa[ks], kbl[nt >> 1][(nt & 1) * 2], kbl[nt >> 1][(nt & 1) * 2 + 1]);
        }

#pragma unroll
        for (int nt = 0; nt < 8; nt++) {
            int kg0 = k0 + nt * 8 + tg * 2, kg1 = kg0 + 1;
            int d00 = qg_lo - kg0, d01 = qg_lo - kg1;
            int d10 = qg_hi - kg0, d11 = qg_hi - kg1;
            sacc[nt][0] = (d00 >= 0 && d00 < WINDOW) ? sacc[nt][0] * scale : -1e30f;
            sacc[nt][1] = (d01 >= 0 && d01 < WINDOW) ? sacc[nt][1] * scale : -1e30f;
            sacc[nt][2] = (d10 >= 0 && d10 < WINDOW) ? sacc[nt][2] * scale : -1e30f;
            sacc[nt][3] = (d11 >= 0 && d11 < WINDOW) ? sacc[nt][3] * scale : -1e30f;
        }

        float mx0 = -1e30f, mx1 = -1e30f;
#pragma unroll
        for (int nt = 0; nt < 8; nt++) {
            mx0 = fmaxf(mx0, fmaxf(sacc[nt][0], sacc[nt][1]));
            mx1 = fmaxf(mx1, fmaxf(sacc[nt][2], sacc[nt][3]));
        }
        mx0 = fmaxf(mx0, __shfl_xor_sync(0xffffffffu, mx0, 1));
        mx0 = fmaxf(mx0, __shfl_xor_sync(0xffffffffu, mx0, 2));
        mx1 = fmaxf(mx1, __shfl_xor_sync(0xffffffffu, mx1, 1));
        mx1 = fmaxf(mx1, __shfl_xor_sync(0xffffffffu, mx1, 2));
        float mn0 = fmaxf(m_lo, mx0), mn1 = fmaxf(m_hi, mx1);
        float al0 = __expf(m_lo - mn0), al1 = __expf(m_hi - mn1);
        float ps0 = 0.f, ps1 = 0.f;
#pragma unroll
        for (int nt = 0; nt < 8; nt++) {
            float p0 = (sacc[nt][0] > -1e29f) ? __expf(sacc[nt][0] - mn0) : 0.f;
            float p1 = (sacc[nt][1] > -1e29f) ? __expf(sacc[nt][1] - mn0) : 0.f;
            float p2 = (sacc[nt][2] > -1e29f) ? __expf(sacc[nt][2] - mn1) : 0.f;
            float p3 = (sacc[nt][3] > -1e29f) ? __expf(sacc[nt][3] - mn1) : 0.f;
            sacc[nt][0] = p0; sacc[nt][1] = p1; sacc[nt][2] = p2; sacc[nt][3] = p3;
            ps0 += p0 + p1;
            ps1 += p2 + p3;
        }
        ps0 += __shfl_xor_sync(0xffffffffu, ps0, 1);
        ps0 += __shfl_xor_sync(0xffffffffu, ps0, 2);
        ps1 += __shfl_xor_sync(0xffffffffu, ps1, 1);
        ps1 += __shfl_xor_sync(0xffffffffu, ps1, 2);
        l_lo = l_lo * al0 + ps0; m_lo = mn0;
        l_hi = l_hi * al1 + ps1; m_hi = mn1;
#pragma unroll
        for (int nt = 0; nt < 16; nt++) {
            oacc[nt][0] *= al0; oacc[nt][1] *= al0;
            oacc[nt][2] *= al1; oacc[nt][3] *= al1;
        }

        // ---- O += P V (P single fp16, V single fp16) ----
#pragma unroll
        for (int kv = 0; kv < 4; kv++) {
            unsigned pa[4];
            {
                __half2 h0, h1, h2, h3;
                h0.x = __float2half_rn(sacc[2 * kv][0]);
                h0.y = __float2half_rn(sacc[2 * kv][1]);
                h1.x = __float2half_rn(sacc[2 * kv][2]);
                h1.y = __float2half_rn(sacc[2 * kv][3]);
                h2.x = __float2half_rn(sacc[2 * kv + 1][0]);
                h2.y = __float2half_rn(sacc[2 * kv + 1][1]);
                h3.x = __float2half_rn(sacc[2 * kv + 1][2]);
                h3.y = __float2half_rn(sacc[2 * kv + 1][3]);
                pa[0] = *(unsigned*)&h0; pa[1] = *(unsigned*)&h1;
                pa[2] = *(unsigned*)&h2; pa[3] = *(unsigned*)&h3;
            }
#pragma unroll
            for (int half = 0; half < 2; half++) {
                unsigned vbh[4][4];
#pragma unroll
                for (int ntp = 0; ntp < 4; ntp++)
                    LDSM4(vbh[ntp], s0 + KVV + boffV + (half * 4 + ntp) * (16 * AV_STB) + kv * 32);
#pragma unroll
                for (int nt = 0; nt < 8; nt++)
                    MMA_F16(oacc[half * 8 + nt], pa, vbh[nt >> 1][(nt & 1) * 2], vbh[nt >> 1][(nt & 1) * 2 + 1]);
            }
        }
        __syncthreads();
        if (kt + 2 <= kt_hi) load_kv(j & 1, kt + 2);
        else asm volatile("cp.async.commit_group;" ::: "memory");
    }

    // ---- epilogue: normalize + single fp16 out ----
    float inv0 = 1.f / l_lo, inv1 = 1.f / l_hi;
#pragma unroll
    for (int nt = 0; nt < 16; nt++) {
        int col = h * HD + nt * 8 + tg * 2;
        __half2 hp;
        hp.x = __float2half_rn(oacc[nt][0] * inv0);
        hp.y = __float2half_rn(oacc[nt][1] * inv0);
        *(__half2*)&g_at[(long)qg_lo * NQD + col] = hp;
        hp.x = __float2half_rn(oacc[nt][2] * inv1);
        hp.y = __float2half_rn(oacc[nt][3] * inv1);
        *(__half2*)&g_at[(long)qg_hi * NQD + col] = hp;
    }
}

// ============================================================================
extern "C" void kernel_launch(void* const* d_in, const int* in_sizes, int n_in,
                              void* d_out, int out_size)
{
    const float* x   = (const float*)d_in[0];
    const float* fc  = (const float*)d_in[1];
    const float* fs  = (const float*)d_in[2];
    // d_in[3]: mask — unused (causal + sliding window computed analytically)
    const float* w_q = (const float*)d_in[4];
    const float* w_k = (const float*)d_in[5];
    const float* w_v = (const float*)d_in[6];
    const float* w_o = (const float*)d_in[7];
    float* out = (float*)d_out;

    __half *xh, *xl, *at, *wc, *woh;
    cudaGetSymbolAddress((void**)&xh, g_xh);   cudaGetSymbolAddress((void**)&xl, g_xl);
    cudaGetSymbolAddress((void**)&at, g_at);
    cudaGetSymbolAddress((void**)&wc, g_wc);   cudaGetSymbolAddress((void**)&woh, g_woh);

    cudaFuncSetAttribute(gemm_qkv, cudaFuncAttributeMaxDynamicSharedMemorySize, GSMEM);
    cudaFuncSetAttribute(gemm_o, cudaFuncAttributeMaxDynamicSharedMemorySize, OSMEM);
    cudaFuncSetAttribute(attn_mma, cudaFuncAttributeMaxDynamicSharedMemorySize, ASMEM);

    // one-time operand prep: x -> fp16 hi/lo; weights -> single fp16 [N][K]
    cvt_hl16<<<(S_LEN * D_MODEL / 4 + 255) / 256, 256>>>(x, xh, xl, S_LEN * D_MODEL);
    transpose_h<<<dim3(NQD / 32, D_MODEL / 32), dim3(32, 8)>>>(w_q, wc, D_MODEL, NQD);
    transpose_h<<<dim3(NKVD / 32, D_MODEL / 32), dim3(32, 8)>>>(
        w_k, wc + (long)NQD * D_MODEL, D_MODEL, NKVD);
    transpose_h<<<dim3(NKVD / 32, D_MODEL / 32), dim3(32, 8)>>>(
        w_v, wc + (long)(NQD + NKVD) * D_MODEL, D_MODEL, NKVD);
    transpose_h<<<dim3(D_MODEL / 32, NQD / 32), dim3(32, 8)>>>(w_o, woh, NQD, D_MODEL);

    // fused QKV projection (fp16 2-pass; fused rope / rope / v-transpose epilogue)
    gemm_qkv<<<dim3(NCAT / 128, S_LEN / 128), 256, GSMEM>>>(
        xh, xl, wc, fc, fs, S_LEN, NCAT, D_MODEL);

    // attention (QK bf16 3-pass, PV fp16 1-pass)
    attn_mma<<<dim3(S_LEN / 64, NQ), 128, ASMEM>>>();

    // output projection (fp16 1-pass, 3-stage pipeline)
    gemm_o<<<dim3(D_MODEL / 128, S_LEN / 128), 256, OSMEM>>>(
        at, woh, out, S_LEN, D_MODEL, NQD);
}